// round 6
// baseline (speedup 1.0000x reference)
#include <cuda_runtime.h>
#include <cuda_bf16.h>
#include <cstdint>

// Problem constants (fixed shapes)
#define BB 2
#define NN 2048
#define CC 1024
#define HH 16
#define HD 64
#define MM (BB * NN)   // 4096 rows

typedef __nv_bfloat16 bf16;

// ---------------------------------------------------------------------------
// Scratch (device globals — no allocations allowed)
// ---------------------------------------------------------------------------
__device__ float g_ao[MM * CC];
__device__ bf16 g_xh[MM * CC], g_xl[MM * CC];
__device__ bf16 g_qkvh[MM * 3 * CC], g_qkvl[MM * 3 * CC];
__device__ bf16 g_wT_h[3 * CC * CC], g_wT_l[3 * CC * CC];   // qk rows 0..2C-1, v rows 2C..3C-1
__device__ bf16 g_wpT_h[CC * CC], g_wpT_l[CC * CC];

// ---------------------------------------------------------------------------
// helpers
// ---------------------------------------------------------------------------
__device__ __forceinline__ uint32_t smem_u32(const void* p) {
    uint32_t a;
    asm("{ .reg .u64 t; cvta.to.shared.u64 t, %1; cvt.u32.u64 %0, t; }"
        : "=r"(a) : "l"(p));
    return a;
}

__device__ __forceinline__ void mma_bf16(float* c, const unsigned* a, const unsigned* b) {
    asm volatile(
        "mma.sync.aligned.m16n8k16.row.col.f32.bf16.bf16.f32 "
        "{%0,%1,%2,%3}, {%4,%5,%6,%7}, {%8,%9}, {%0,%1,%2,%3};"
        : "+f"(c[0]), "+f"(c[1]), "+f"(c[2]), "+f"(c[3])
        : "r"(a[0]), "r"(a[1]), "r"(a[2]), "r"(a[3]), "r"(b[0]), "r"(b[1]));
}

__device__ __forceinline__ void ldm_x4(unsigned* r, uint32_t addr) {
    asm volatile("ldmatrix.sync.aligned.m8n8.x4.shared.b16 {%0,%1,%2,%3}, [%4];"
        : "=r"(r[0]), "=r"(r[1]), "=r"(r[2]), "=r"(r[3]) : "r"(addr));
}
__device__ __forceinline__ void ldm_x4t(unsigned* r, uint32_t addr) {
    asm volatile("ldmatrix.sync.aligned.m8n8.x4.trans.shared.b16 {%0,%1,%2,%3}, [%4];"
        : "=r"(r[0]), "=r"(r[1]), "=r"(r[2]), "=r"(r[3]) : "r"(addr));
}

// cp.async 16B global -> shared
__device__ __forceinline__ void cp16(uint32_t dst, const void* src) {
    asm volatile("cp.async.cg.shared.global [%0], [%1], 16;"
        :: "r"(dst), "l"(__cvta_generic_to_global(src)) : "memory");
}
#define CP_COMMIT() asm volatile("cp.async.commit_group;" ::: "memory")
#define CP_WAIT1()  asm volatile("cp.async.wait_group 1;" ::: "memory")
#define CP_WAIT0()  asm volatile("cp.async.wait_group 0;" ::: "memory")

// pack two f32 -> bf16x2 register (lo = first arg)
__device__ __forceinline__ unsigned pack_bf2(float lo, float hi) {
    unsigned r;
    asm("cvt.rn.bf16x2.f32 %0, %1, %2;" : "=r"(r) : "f"(hi), "f"(lo));
    return r;
}
__device__ __forceinline__ float bf_round(float x) {
    return __bfloat162float(__float2bfloat16(x));
}

// ---------------------------------------------------------------------------
// LayerNorm -> bf16 hi/lo split output
// ---------------------------------------------------------------------------
__global__ void ln_split_kernel(const float* __restrict__ x,
                                const float* __restrict__ g,
                                const float* __restrict__ b,
                                bf16* __restrict__ oh,
                                bf16* __restrict__ ol) {
    int row = blockIdx.x;
    int t = threadIdx.x;
    const float4* xr = reinterpret_cast<const float4*>(x + (size_t)row * CC);
    float4 v = xr[t];
    float s  = v.x + v.y + v.z + v.w;
    float ss = v.x * v.x + v.y * v.y + v.z * v.z + v.w * v.w;

    #pragma unroll
    for (int o = 16; o > 0; o >>= 1) {
        s  += __shfl_down_sync(0xFFFFFFFFu, s,  o);
        ss += __shfl_down_sync(0xFFFFFFFFu, ss, o);
    }
    __shared__ float sh[8][2];
    int w = t >> 5, l = t & 31;
    if (l == 0) { sh[w][0] = s; sh[w][1] = ss; }
    __syncthreads();
    if (w == 0) {
        s  = (l < 8) ? sh[l][0] : 0.0f;
        ss = (l < 8) ? sh[l][1] : 0.0f;
        #pragma unroll
        for (int o = 4; o > 0; o >>= 1) {
            s  += __shfl_down_sync(0xFFFFFFFFu, s,  o);
            ss += __shfl_down_sync(0xFFFFFFFFu, ss, o);
        }
        if (l == 0) { sh[0][0] = s; sh[0][1] = ss; }
    }
    __syncthreads();
    s = sh[0][0]; ss = sh[0][1];

    float mu  = s * (1.0f / CC);
    float var = ss * (1.0f / CC) - mu * mu;
    float inv = rsqrtf(var + 1e-5f);

    const float4 gv = reinterpret_cast<const float4*>(g)[t];
    const float4 bv = reinterpret_cast<const float4*>(b)[t];
    float o0 = (v.x - mu) * inv * gv.x + bv.x;
    float o1 = (v.y - mu) * inv * gv.y + bv.y;
    float o2 = (v.z - mu) * inv * gv.z + bv.z;
    float o3 = (v.w - mu) * inv * gv.w + bv.w;

    unsigned h01 = pack_bf2(o0, o1), h23 = pack_bf2(o2, o3);
    unsigned l01 = pack_bf2(o0 - bf_round(o0), o1 - bf_round(o1));
    unsigned l23 = pack_bf2(o2 - bf_round(o2), o3 - bf_round(o3));
    uint2* hp = reinterpret_cast<uint2*>(oh + (size_t)row * CC + t * 4);
    uint2* lp = reinterpret_cast<uint2*>(ol + (size_t)row * CC + t * 4);
    *hp = make_uint2(h01, h23);
    *lp = make_uint2(l01, l23);
}

// ---------------------------------------------------------------------------
// Transpose + split: w[K][N] fp32 -> wT_hi/lo[N][K] bf16
// ---------------------------------------------------------------------------
__global__ void wsplit_kernel(const float* __restrict__ w,
                              bf16* __restrict__ th,
                              bf16* __restrict__ tl,
                              int K, int N) {
    __shared__ float t[32][33];
    int bx = blockIdx.x, by = blockIdx.y;
    int x = bx * 32 + threadIdx.x;
    #pragma unroll
    for (int j = 0; j < 32; j += 8)
        t[threadIdx.y + j][threadIdx.x] = w[(size_t)(by * 32 + threadIdx.y + j) * N + x];
    __syncthreads();
    int n = bx * 32 + threadIdx.y;
    int k = by * 32 + threadIdx.x;
    #pragma unroll
    for (int j = 0; j < 32; j += 8) {
        float v = t[threadIdx.x][threadIdx.y + j];
        bf16 h = __float2bfloat16(v);
        th[(size_t)(n + j) * K + k] = h;
        tl[(size_t)(n + j) * K + k] = __float2bfloat16(v - __bfloat162float(h));
    }
}

// ---------------------------------------------------------------------------
// mma.sync bf16x3 GEMM, cp.async double-buffered.
// SPLIT=false: fp32 out (+bias). SPLIT=true: bf16 hi/lo out, cols<qcols x0.125.
// CTA 128x128 tile, 8 warps (2x4), warp 64x32, K chunk 16.
// ---------------------------------------------------------------------------
#define KC 16
#define PAD 24

template <bool SPLIT>
__global__ void __launch_bounds__(256)
gemm_mma(const bf16* __restrict__ Ah, const bf16* __restrict__ Al,
         const bf16* __restrict__ Bh, const bf16* __restrict__ Bl,
         const float* __restrict__ bias, float* __restrict__ C,
         bf16* __restrict__ Ch, bf16* __restrict__ Cl,
         int M, int N, int K, int qcols) {
    __shared__ bf16 sAh[2][128 * PAD];
    __shared__ bf16 sAl[2][128 * PAD];
    __shared__ bf16 sBh[2][128 * PAD];
    __shared__ bf16 sBl[2][128 * PAD];

    int tid = threadIdx.x;
    int warp = tid >> 5, lane = tid & 31;
    int wm = warp >> 2, wn = warp & 3;
    int m0 = blockIdx.y * 128, n0 = blockIdx.x * 128;

    int lr = tid >> 1;
    int lk = (tid & 1) * 8;
    const bf16* gAh = Ah + (size_t)(m0 + lr) * K + lk;
    const bf16* gAl = Al + (size_t)(m0 + lr) * K + lk;
    const bf16* gBh = Bh + (size_t)(n0 + lr) * K + lk;
    const bf16* gBl = Bl + (size_t)(n0 + lr) * K + lk;
    int sob = (lr * PAD + lk) * 2;   // smem byte offset

    uint32_t bAh[2] = {smem_u32(&sAh[0][0]), smem_u32(&sAh[1][0])};
    uint32_t bAl[2] = {smem_u32(&sAl[0][0]), smem_u32(&sAl[1][0])};
    uint32_t bBh[2] = {smem_u32(&sBh[0][0]), smem_u32(&sBh[1][0])};
    uint32_t bBl[2] = {smem_u32(&sBl[0][0]), smem_u32(&sBl[1][0])};

    float acc[4][4][4];
    #pragma unroll
    for (int i = 0; i < 4; i++)
        #pragma unroll
        for (int j = 0; j < 4; j++)
            #pragma unroll
            for (int q = 0; q < 4; q++) acc[i][j][q] = 0.0f;

    int a_row = wm * 64 + (lane & 15);
    int a_cb  = ((lane >> 4) & 1) * 16;
    int b_row = wn * 32 + ((lane >> 4) & 1) * 8 + (lane & 7);
    int b_cb  = ((lane >> 3) & 1) * 16;

    // prologue: chunk 0
    cp16(bAh[0] + sob, gAh);
    cp16(bAl[0] + sob, gAl);
    cp16(bBh[0] + sob, gBh);
    cp16(bBl[0] + sob, gBl);
    CP_COMMIT();

    int nch = K / KC;
    #pragma unroll 1
    for (int c = 0; c < nch; c++) {
        int cur = c & 1;
        if (c + 1 < nch) {
            int nxt = cur ^ 1;
            cp16(bAh[nxt] + sob, gAh + (c + 1) * KC);
            cp16(bAl[nxt] + sob, gAl + (c + 1) * KC);
            cp16(bBh[nxt] + sob, gBh + (c + 1) * KC);
            cp16(bBl[nxt] + sob, gBl + (c + 1) * KC);
            CP_COMMIT();
            CP_WAIT1();
        } else {
            CP_WAIT0();
        }
        __syncthreads();

        unsigned fA[4][4], fBh[4][2], fBl[4][2];
        #pragma unroll
        for (int np = 0; np < 2; np++) {
            unsigned r4[4];
            uint32_t off = (uint32_t)(b_row + np * 16) * (PAD * 2) + b_cb;
            ldm_x4(r4, bBh[cur] + off);
            fBh[np * 2 + 0][0] = r4[0]; fBh[np * 2 + 0][1] = r4[1];
            fBh[np * 2 + 1][0] = r4[2]; fBh[np * 2 + 1][1] = r4[3];
            ldm_x4(r4, bBl[cur] + off);
            fBl[np * 2 + 0][0] = r4[0]; fBl[np * 2 + 0][1] = r4[1];
            fBl[np * 2 + 1][0] = r4[2]; fBl[np * 2 + 1][1] = r4[3];
        }
        #pragma unroll
        for (int mt = 0; mt < 4; mt++)
            ldm_x4(fA[mt], bAh[cur] + (uint32_t)(a_row + mt * 16) * (PAD * 2) + a_cb);
        #pragma unroll
        for (int mt = 0; mt < 4; mt++)
            #pragma unroll
            for (int nt = 0; nt < 4; nt++)
                mma_bf16(acc[mt][nt], fA[mt], fBh[nt]);
        #pragma unroll
        for (int mt = 0; mt < 4; mt++)
            #pragma unroll
            for (int nt = 0; nt < 4; nt++)
                mma_bf16(acc[mt][nt], fA[mt], fBl[nt]);
        #pragma unroll
        for (int mt = 0; mt < 4; mt++)
            ldm_x4(fA[mt], bAl[cur] + (uint32_t)(a_row + mt * 16) * (PAD * 2) + a_cb);
        #pragma unroll
        for (int mt = 0; mt < 4; mt++)
            #pragma unroll
            for (int nt = 0; nt < 4; nt++)
                mma_bf16(acc[mt][nt], fA[mt], fBh[nt]);
        __syncthreads();
    }

    // epilogue
    #pragma unroll
    for (int mt = 0; mt < 4; mt++) {
        int row = m0 + wm * 64 + mt * 16 + (lane >> 2);
        #pragma unroll
        for (int nt = 0; nt < 4; nt++) {
            int col = n0 + wn * 32 + nt * 8 + (lane & 3) * 2;
            if (SPLIT) {
                float sc = (col < qcols) ? 0.125f : 1.0f;
                #pragma unroll
                for (int half = 0; half < 2; half++) {
                    int rr = row + half * 8;
                    float v0 = acc[mt][nt][half * 2 + 0] * sc;
                    float v1 = acc[mt][nt][half * 2 + 1] * sc;
                    unsigned hp = pack_bf2(v0, v1);
                    unsigned lp = pack_bf2(v0 - bf_round(v0), v1 - bf_round(v1));
                    *reinterpret_cast<unsigned*>(Ch + (size_t)rr * N + col) = hp;
                    *reinterpret_cast<unsigned*>(Cl + (size_t)rr * N + col) = lp;
                }
            } else {
                float bx = bias[col], by = bias[col + 1];
                float2 r0 = make_float2(acc[mt][nt][0] + bx, acc[mt][nt][1] + by);
                float2 r1 = make_float2(acc[mt][nt][2] + bx, acc[mt][nt][3] + by);
                *reinterpret_cast<float2*>(C + (size_t)row * N + col) = r0;
                *reinterpret_cast<float2*>(C + (size_t)(row + 8) * N + col) = r1;
            }
        }
    }
}

// ---------------------------------------------------------------------------
// Flash attention on tensor cores (bf16x3, FA2-style register softmax),
// cp.async double-buffered K/V. BQ=128 (8 warps x 16 rows), BK=64, hd=64.
// q/k/v live in the fused qkv buffer [M, 3C] at col offsets 0 / C / 2C.
// ---------------------------------------------------------------------------
#define APAD 72
#define KVB (4 * 64 * APAD)      // elems per K/V buffer
#define ASMEM (2 * KVB * 2)      // bytes (73728)

__global__ void __launch_bounds__(256)
attn_mma(const bf16* __restrict__ qkvh, const bf16* __restrict__ qkvl,
         float* __restrict__ out) {
    extern __shared__ bf16 sm[];
    const uint32_t sb = smem_u32(sm);

    int qt = blockIdx.x, h = blockIdx.y, b = blockIdx.z;
    int tid = threadIdx.x, warp = tid >> 5, lane = tid & 31;
    int quad = lane >> 2, tq = lane & 3;
    const int RS = 3 * CC;   // qkv row stride

    // --- stage Q hi/lo (in buf0 region) and build persistent A-frags ---
    for (int i = tid; i < 128 * 8; i += 256) {
        int r = i >> 3, c8 = (i & 7) * 8;
        size_t grow = (size_t)(b * NN + qt * 128 + r) * RS + h * HD + c8;
        *reinterpret_cast<uint4*>(&sm[r * APAD + c8]) =
            *reinterpret_cast<const uint4*>(qkvh + grow);
        *reinterpret_cast<uint4*>(&sm[(128 + r) * APAD + c8]) =
            *reinterpret_cast<const uint4*>(qkvl + grow);
    }
    __syncthreads();
    unsigned fQh[4][4], fQl[4][4];
    {
        int ar = warp * 16 + (lane & 15);
        int cb = ((lane >> 4) & 1) * 16;
        #pragma unroll
        for (int kk = 0; kk < 4; kk++) {
            ldm_x4(fQh[kk], sb + (uint32_t)(ar * APAD) * 2 + kk * 32 + cb);
            ldm_x4(fQl[kk], sb + (uint32_t)((128 + ar) * APAD) * 2 + kk * 32 + cb);
        }
    }
    __syncthreads();

    float O[8][4];
    #pragma unroll
    for (int nt = 0; nt < 8; nt++)
        #pragma unroll
        for (int q = 0; q < 4; q++) O[nt][q] = 0.0f;
    float m0 = -1e30f, m1 = -1e30f, l0 = 0.0f, l1 = 0.0f;

    // K/V cp.async addressing: 2 row-chunks of 16B per tensor per thread
    int kr0 = tid >> 3, kc0 = (tid & 7) * 8;
    int kr1 = kr0 + 32;

    // B-frag ldmatrix lane addressing
    int kb_row = ((lane >> 4) & 1) * 8 + (lane & 7);
    int kb_cb  = ((lane >> 3) & 1) * 16;
    int vb_row = ((lane >> 3) & 1) * 8 + (lane & 7);
    int vb_cb  = ((lane >> 4) & 1) * 16;

    // issue K/V tile `it` into buffer `buf`
    auto kv_issue = [&](int it, int buf) {
        uint32_t base = sb + (uint32_t)buf * (KVB * 2);
        int k0 = it * 64;
        size_t r0 = (size_t)(b * NN + k0 + kr0) * RS + h * HD;
        size_t r1 = (size_t)(b * NN + k0 + kr1) * RS + h * HD;
        cp16(base + (uint32_t)(0 * 64 * APAD + kr0 * APAD + kc0) * 2, qkvh + r0 + CC + kc0);
        cp16(base + (uint32_t)(0 * 64 * APAD + kr1 * APAD + kc0) * 2, qkvh + r1 + CC + kc0);
        cp16(base + (uint32_t)(1 * 64 * APAD + kr0 * APAD + kc0) * 2, qkvl + r0 + CC + kc0);
        cp16(base + (uint32_t)(1 * 64 * APAD + kr1 * APAD + kc0) * 2, qkvl + r1 + CC + kc0);
        cp16(base + (uint32_t)(2 * 64 * APAD + kr0 * APAD + kc0) * 2, qkvh + r0 + 2 * CC + kc0);
        cp16(base + (uint32_t)(2 * 64 * APAD + kr1 * APAD + kc0) * 2, qkvh + r1 + 2 * CC + kc0);
        cp16(base + (uint32_t)(3 * 64 * APAD + kr0 * APAD + kc0) * 2, qkvl + r0 + 2 * CC + kc0);
        cp16(base + (uint32_t)(3 * 64 * APAD + kr1 * APAD + kc0) * 2, qkvl + r1 + 2 * CC + kc0);
        CP_COMMIT();
    };

    kv_issue(0, 0);

    const int NIT = NN / 64;
    #pragma unroll 1
    for (int it = 0; it < NIT; it++) {
        int cur = it & 1;
        if (it + 1 < NIT) {
            kv_issue(it + 1, cur ^ 1);
            CP_WAIT1();
        } else {
            CP_WAIT0();
        }
        __syncthreads();

        uint32_t base = sb + (uint32_t)cur * (KVB * 2);
        uint32_t sKh = base;
        uint32_t sKl = base + 64 * APAD * 2;
        uint32_t sVh = base + 2 * 64 * APAD * 2;
        uint32_t sVl = base + 3 * 64 * APAD * 2;

        // ---- S = Q @ K^T (3 passes) ----
        float S[8][4];
        #pragma unroll
        for (int nt = 0; nt < 8; nt++)
            #pragma unroll
            for (int q = 0; q < 4; q++) S[nt][q] = 0.0f;

        #pragma unroll
        for (int kk = 0; kk < 4; kk++) {
            unsigned fKh[8][2], fKl[8][2];
            #pragma unroll
            for (int np = 0; np < 4; np++) {
                unsigned r4[4];
                uint32_t off = (uint32_t)(kb_row + np * 16) * (APAD * 2) + kb_cb + kk * 32;
                ldm_x4(r4, sKh + off);
                fKh[np * 2 + 0][0] = r4[0]; fKh[np * 2 + 0][1] = r4[1];
                fKh[np * 2 + 1][0] = r4[2]; fKh[np * 2 + 1][1] = r4[3];
                ldm_x4(r4, sKl + off);
                fKl[np * 2 + 0][0] = r4[0]; fKl[np * 2 + 0][1] = r4[1];
                fKl[np * 2 + 1][0] = r4[2]; fKl[np * 2 + 1][1] = r4[3];
            }
            #pragma unroll
            for (int nt = 0; nt < 8; nt++) {
                mma_bf16(S[nt], fQh[kk], fKh[nt]);
                mma_bf16(S[nt], fQh[kk], fKl[nt]);
                mma_bf16(S[nt], fQl[kk], fKh[nt]);
            }
        }

        // ---- online softmax in registers ----
        float mx0 = -1e30f, mx1 = -1e30f;
        #pragma unroll
        for (int nt = 0; nt < 8; nt++) {
            mx0 = fmaxf(mx0, fmaxf(S[nt][0], S[nt][1]));
            mx1 = fmaxf(mx1, fmaxf(S[nt][2], S[nt][3]));
        }
        mx0 = fmaxf(mx0, __shfl_xor_sync(0xFFFFFFFFu, mx0, 1));
        mx0 = fmaxf(mx0, __shfl_xor_sync(0xFFFFFFFFu, mx0, 2));
        mx1 = fmaxf(mx1, __shfl_xor_sync(0xFFFFFFFFu, mx1, 1));
        mx1 = fmaxf(mx1, __shfl_xor_sync(0xFFFFFFFFu, mx1, 2));
        float mn0 = fmaxf(m0, mx0), mn1 = fmaxf(m1, mx1);
        float al0 = __expf(m0 - mn0), al1 = __expf(m1 - mn1);
        m0 = mn0; m1 = mn1;

        float s0 = 0.0f, s1 = 0.0f;
        #pragma unroll
        for (int nt = 0; nt < 8; nt++) {
            S[nt][0] = __expf(S[nt][0] - mn0); s0 += S[nt][0];
            S[nt][1] = __expf(S[nt][1] - mn0); s0 += S[nt][1];
            S[nt][2] = __expf(S[nt][2] - mn1); s1 += S[nt][2];
            S[nt][3] = __expf(S[nt][3] - mn1); s1 += S[nt][3];
        }
        s0 += __shfl_xor_sync(0xFFFFFFFFu, s0, 1);
        s0 += __shfl_xor_sync(0xFFFFFFFFu, s0, 2);
        s1 += __shfl_xor_sync(0xFFFFFFFFu, s1, 1);
        s1 += __shfl_xor_sync(0xFFFFFFFFu, s1, 2);
        l0 = l0 * al0 + s0;
        l1 = l1 * al1 + s1;

        // rescale O
        #pragma unroll
        for (int nt = 0; nt < 8; nt++) {
            O[nt][0] *= al0; O[nt][1] *= al0;
            O[nt][2] *= al1; O[nt][3] *= al1;
        }

        // pack P hi/lo (C-frag -> A-frag identity)
        unsigned Phi[8][2], Plo[8][2];
        #pragma unroll
        for (int nt = 0; nt < 8; nt++) {
            float p0 = S[nt][0], p1 = S[nt][1], p2 = S[nt][2], p3 = S[nt][3];
            Phi[nt][0] = pack_bf2(p0, p1);
            Phi[nt][1] = pack_bf2(p2, p3);
            Plo[nt][0] = pack_bf2(p0 - bf_round(p0), p1 - bf_round(p1));
            Plo[nt][1] = pack_bf2(p2 - bf_round(p2), p3 - bf_round(p3));
        }

        // ---- O += P @ V (3 passes) ----
        #pragma unroll
        for (int kk = 0; kk < 4; kk++) {
            unsigned aPh[4] = {Phi[2 * kk][0], Phi[2 * kk][1],
                               Phi[2 * kk + 1][0], Phi[2 * kk + 1][1]};
            unsigned aPl[4] = {Plo[2 * kk][0], Plo[2 * kk][1],
                               Plo[2 * kk + 1][0], Plo[2 * kk + 1][1]};
            unsigned fVh[8][2], fVl[8][2];
            #pragma unroll
            for (int nt2 = 0; nt2 < 4; nt2++) {
                unsigned r4[4];
                uint32_t off = (uint32_t)(vb_row + kk * 16) * (APAD * 2) + vb_cb + nt2 * 32;
                ldm_x4t(r4, sVh + off);
                fVh[nt2 * 2 + 0][0] = r4[0]; fVh[nt2 * 2 + 0][1] = r4[1];
                fVh[nt2 * 2 + 1][0] = r4[2]; fVh[nt2 * 2 + 1][1] = r4[3];
                ldm_x4t(r4, sVl + off);
                fVl[nt2 * 2 + 0][0] = r4[0]; fVl[nt2 * 2 + 0][1] = r4[1];
                fVl[nt2 * 2 + 1][0] = r4[2]; fVl[nt2 * 2 + 1][1] = r4[3];
            }
            #pragma unroll
            for (int nt = 0; nt < 8; nt++) {
                mma_bf16(O[nt], aPh, fVh[nt]);
                mma_bf16(O[nt], aPh, fVl[nt]);
                mma_bf16(O[nt], aPl, fVh[nt]);
            }
        }
        __syncthreads();
    }

    // ---- finalize & store ----
    float inv0 = 1.0f / l0, inv1 = 1.0f / l1;
    int row0 = b * NN + qt * 128 + warp * 16 + quad;
    #pragma unroll
    for (int nt = 0; nt < 8; nt++) {
        int col = h * HD + nt * 8 + tq * 2;
        *reinterpret_cast<float2*>(out + (size_t)row0 * CC + col) =
            make_float2(O[nt][0] * inv0, O[nt][1] * inv0);
        *reinterpret_cast<float2*>(out + (size_t)(row0 + 8) * CC + col) =
            make_float2(O[nt][2] * inv1, O[nt][3] * inv1);
    }
}

// ---------------------------------------------------------------------------
extern "C" void kernel_launch(void* const* d_in, const int* in_sizes, int n_in,
                              void* d_out, int out_size) {
    const float* x      = (const float*)d_in[0];
    const float* ln1_g  = (const float*)d_in[1];
    const float* ln1_b  = (const float*)d_in[2];
    const float* w_qk   = (const float*)d_in[3];
    const float* w_v    = (const float*)d_in[4];
    const float* ln2_g  = (const float*)d_in[5];
    const float* ln2_b  = (const float*)d_in[6];
    const float* w_proj = (const float*)d_in[7];
    const float* b_proj = (const float*)d_in[8];
    float* out = (float*)d_out;

    float* ao;
    bf16 *xh, *xl, *qkvh, *qkvl, *wh, *wl, *wph, *wpl;
    cudaGetSymbolAddress((void**)&ao,    g_ao);
    cudaGetSymbolAddress((void**)&xh,    g_xh);
    cudaGetSymbolAddress((void**)&xl,    g_xl);
    cudaGetSymbolAddress((void**)&qkvh,  g_qkvh);
    cudaGetSymbolAddress((void**)&qkvl,  g_qkvl);
    cudaGetSymbolAddress((void**)&wh,    g_wT_h);
    cudaGetSymbolAddress((void**)&wl,    g_wT_l);
    cudaGetSymbolAddress((void**)&wph,   g_wpT_h);
    cudaGetSymbolAddress((void**)&wpl,   g_wpT_l);

    cudaFuncSetAttribute(attn_mma, cudaFuncAttributeMaxDynamicSharedMemorySize, ASMEM);

    // weight transpose+split into fused [3C][C] buffer (qk rows 0..2C-1, v rows 2C..)
    wsplit_kernel<<<dim3(2 * CC / 32, CC / 32), dim3(32, 8)>>>(w_qk, wh, wl, CC, 2 * CC);
    wsplit_kernel<<<dim3(CC / 32, CC / 32), dim3(32, 8)>>>(
        w_v, wh + (size_t)2 * CC * CC, wl + (size_t)2 * CC * CC, CC, CC);
    wsplit_kernel<<<dim3(CC / 32, CC / 32), dim3(32, 8)>>>(w_proj, wph, wpl, CC, CC);

    // 1. LN1 -> bf16 hi/lo
    ln_split_kernel<<<MM, 256>>>(x, ln1_g, ln1_b, xh, xl);

    // 2. fused qkv projection -> bf16 hi/lo [M, 3C] (q cols pre-scaled 0.125)
    gemm_mma<true><<<dim3(3 * CC / 128, MM / 128), 256>>>(
        xh, xl, wh, wl, nullptr, nullptr, qkvh, qkvl, MM, 3 * CC, CC, CC);

    // 3. tensor-core flash attention
    attn_mma<<<dim3(NN / 128, HH, BB), 256, ASMEM>>>(qkvh, qkvl, ao);

    // 4. LN2 -> bf16 hi/lo
    ln_split_kernel<<<MM, 256>>>(ao, ln2_g, ln2_b, xh, xl);

    // 5. output projection + bias (fp32 out)
    gemm_mma<false><<<dim3(CC / 128, MM / 128), 256>>>(
        xh, xl, wph, wpl, b_proj, out, nullptr, nullptr, MM, CC, CC, 0);
}

// round 7
// speedup vs baseline: 1.1731x; 1.1731x over previous
#include <cuda_runtime.h>
#include <cuda_bf16.h>
#include <cstdint>

// Problem constants (fixed shapes)
#define BB 2
#define NN 2048
#define CC 1024
#define HH 16
#define HD 64
#define MM (BB * NN)   // 4096 rows

typedef __nv_bfloat16 bf16;

// ---------------------------------------------------------------------------
// Scratch (device globals — no allocations allowed)
// ---------------------------------------------------------------------------
__device__ float g_ao[MM * CC];
__device__ bf16 g_xh[MM * CC], g_xl[MM * CC];
__device__ bf16 g_qkh[MM * 2 * CC], g_qkl[MM * 2 * CC];
__device__ bf16 g_vh[MM * CC], g_vl[MM * CC];
__device__ bf16 g_wqkT_h[2 * CC * CC], g_wqkT_l[2 * CC * CC];
__device__ bf16 g_wvT_h[CC * CC], g_wvT_l[CC * CC];
__device__ bf16 g_wpT_h[CC * CC], g_wpT_l[CC * CC];

// ---------------------------------------------------------------------------
// helpers
// ---------------------------------------------------------------------------
__device__ __forceinline__ uint32_t smem_u32(const void* p) {
    uint32_t a;
    asm("{ .reg .u64 t; cvta.to.shared.u64 t, %1; cvt.u32.u64 %0, t; }"
        : "=r"(a) : "l"(p));
    return a;
}

__device__ __forceinline__ void mma_bf16(float* c, const unsigned* a, const unsigned* b) {
    asm volatile(
        "mma.sync.aligned.m16n8k16.row.col.f32.bf16.bf16.f32 "
        "{%0,%1,%2,%3}, {%4,%5,%6,%7}, {%8,%9}, {%0,%1,%2,%3};"
        : "+f"(c[0]), "+f"(c[1]), "+f"(c[2]), "+f"(c[3])
        : "r"(a[0]), "r"(a[1]), "r"(a[2]), "r"(a[3]), "r"(b[0]), "r"(b[1]));
}

__device__ __forceinline__ void ldm_x4(unsigned* r, uint32_t addr) {
    asm volatile("ldmatrix.sync.aligned.m8n8.x4.shared.b16 {%0,%1,%2,%3}, [%4];"
        : "=r"(r[0]), "=r"(r[1]), "=r"(r[2]), "=r"(r[3]) : "r"(addr));
}
__device__ __forceinline__ void ldm_x4t(unsigned* r, uint32_t addr) {
    asm volatile("ldmatrix.sync.aligned.m8n8.x4.trans.shared.b16 {%0,%1,%2,%3}, [%4];"
        : "=r"(r[0]), "=r"(r[1]), "=r"(r[2]), "=r"(r[3]) : "r"(addr));
}

// cp.async 16B global -> shared (attention K/V only)
__device__ __forceinline__ void cp16(uint32_t dst, const void* src) {
    asm volatile("cp.async.cg.shared.global [%0], [%1], 16;"
        :: "r"(dst), "l"(__cvta_generic_to_global(src)) : "memory");
}
#define CP_COMMIT() asm volatile("cp.async.commit_group;" ::: "memory")
#define CP_WAIT1()  asm volatile("cp.async.wait_group 1;" ::: "memory")
#define CP_WAIT0()  asm volatile("cp.async.wait_group 0;" ::: "memory")

// pack two f32 -> bf16x2 register (lo = first arg)
__device__ __forceinline__ unsigned pack_bf2(float lo, float hi) {
    unsigned r;
    asm("cvt.rn.bf16x2.f32 %0, %1, %2;" : "=r"(r) : "f"(hi), "f"(lo));
    return r;
}
__device__ __forceinline__ float bf_round(float x) {
    return __bfloat162float(__float2bfloat16(x));
}

// ---------------------------------------------------------------------------
// LayerNorm -> bf16 hi/lo split output
// ---------------------------------------------------------------------------
__global__ void ln_split_kernel(const float* __restrict__ x,
                                const float* __restrict__ g,
                                const float* __restrict__ b,
                                bf16* __restrict__ oh,
                                bf16* __restrict__ ol) {
    int row = blockIdx.x;
    int t = threadIdx.x;
    const float4* xr = reinterpret_cast<const float4*>(x + (size_t)row * CC);
    float4 v = xr[t];
    float s  = v.x + v.y + v.z + v.w;
    float ss = v.x * v.x + v.y * v.y + v.z * v.z + v.w * v.w;

    #pragma unroll
    for (int o = 16; o > 0; o >>= 1) {
        s  += __shfl_down_sync(0xFFFFFFFFu, s,  o);
        ss += __shfl_down_sync(0xFFFFFFFFu, ss, o);
    }
    __shared__ float sh[8][2];
    int w = t >> 5, l = t & 31;
    if (l == 0) { sh[w][0] = s; sh[w][1] = ss; }
    __syncthreads();
    if (w == 0) {
        s  = (l < 8) ? sh[l][0] : 0.0f;
        ss = (l < 8) ? sh[l][1] : 0.0f;
        #pragma unroll
        for (int o = 4; o > 0; o >>= 1) {
            s  += __shfl_down_sync(0xFFFFFFFFu, s,  o);
            ss += __shfl_down_sync(0xFFFFFFFFu, ss, o);
        }
        if (l == 0) { sh[0][0] = s; sh[0][1] = ss; }
    }
    __syncthreads();
    s = sh[0][0]; ss = sh[0][1];

    float mu  = s * (1.0f / CC);
    float var = ss * (1.0f / CC) - mu * mu;
    float inv = rsqrtf(var + 1e-5f);

    const float4 gv = reinterpret_cast<const float4*>(g)[t];
    const float4 bv = reinterpret_cast<const float4*>(b)[t];
    float o0 = (v.x - mu) * inv * gv.x + bv.x;
    float o1 = (v.y - mu) * inv * gv.y + bv.y;
    float o2 = (v.z - mu) * inv * gv.z + bv.z;
    float o3 = (v.w - mu) * inv * gv.w + bv.w;

    unsigned h01 = pack_bf2(o0, o1), h23 = pack_bf2(o2, o3);
    unsigned l01 = pack_bf2(o0 - bf_round(o0), o1 - bf_round(o1));
    unsigned l23 = pack_bf2(o2 - bf_round(o2), o3 - bf_round(o3));
    uint2* hp = reinterpret_cast<uint2*>(oh + (size_t)row * CC + t * 4);
    uint2* lp = reinterpret_cast<uint2*>(ol + (size_t)row * CC + t * 4);
    *hp = make_uint2(h01, h23);
    *lp = make_uint2(l01, l23);
}

// ---------------------------------------------------------------------------
// Transpose + split: w[K][N] fp32 -> wT_hi/lo[N][K] bf16
// ---------------------------------------------------------------------------
__global__ void wsplit_kernel(const float* __restrict__ w,
                              bf16* __restrict__ th,
                              bf16* __restrict__ tl,
                              int K, int N) {
    __shared__ float t[32][33];
    int bx = blockIdx.x, by = blockIdx.y;
    int x = bx * 32 + threadIdx.x;
    #pragma unroll
    for (int j = 0; j < 32; j += 8)
        t[threadIdx.y + j][threadIdx.x] = w[(size_t)(by * 32 + threadIdx.y + j) * N + x];
    __syncthreads();
    int n = bx * 32 + threadIdx.y;
    int k = by * 32 + threadIdx.x;
    #pragma unroll
    for (int j = 0; j < 32; j += 8) {
        float v = t[threadIdx.x][threadIdx.y + j];
        bf16 h = __float2bfloat16(v);
        th[(size_t)(n + j) * K + k] = h;
        tl[(size_t)(n + j) * K + k] = __float2bfloat16(v - __bfloat162float(h));
    }
}

// ---------------------------------------------------------------------------
// mma.sync bf16x3 GEMM (R5 register-prefetch version — proven fastest).
// SPLIT=false: fp32 out (+bias). SPLIT=true: bf16 hi/lo out, cols<qcols x0.125.
// CTA 128x128 tile, 8 warps (2x4), warp 64x32, K chunk 16, double-buffered.
// ---------------------------------------------------------------------------
#define KC 16
#define PAD 24

template <bool SPLIT>
__global__ void __launch_bounds__(256)
gemm_mma(const bf16* __restrict__ Ah, const bf16* __restrict__ Al,
         const bf16* __restrict__ Bh, const bf16* __restrict__ Bl,
         const float* __restrict__ bias, float* __restrict__ C,
         bf16* __restrict__ Ch, bf16* __restrict__ Cl,
         int M, int N, int K, int qcols) {
    __shared__ bf16 sAh[2][128 * PAD];
    __shared__ bf16 sAl[2][128 * PAD];
    __shared__ bf16 sBh[2][128 * PAD];
    __shared__ bf16 sBl[2][128 * PAD];

    int tid = threadIdx.x;
    int warp = tid >> 5, lane = tid & 31;
    int wm = warp >> 2, wn = warp & 3;
    int m0 = blockIdx.y * 128, n0 = blockIdx.x * 128;

    int lr = tid >> 1;
    int lk = (tid & 1) * 8;
    const bf16* gAh = Ah + (size_t)(m0 + lr) * K + lk;
    const bf16* gAl = Al + (size_t)(m0 + lr) * K + lk;
    const bf16* gBh = Bh + (size_t)(n0 + lr) * K + lk;
    const bf16* gBl = Bl + (size_t)(n0 + lr) * K + lk;
    int so = lr * PAD + lk;

    float acc[4][4][4];
    #pragma unroll
    for (int i = 0; i < 4; i++)
        #pragma unroll
        for (int j = 0; j < 4; j++)
            #pragma unroll
            for (int q = 0; q < 4; q++) acc[i][j][q] = 0.0f;

    int a_row = wm * 64 + (lane & 15);
    int a_cb  = ((lane >> 4) & 1) * 16;
    int b_row = wn * 32 + ((lane >> 4) & 1) * 8 + (lane & 7);
    int b_cb  = ((lane >> 3) & 1) * 16;

    uint4 ra = *reinterpret_cast<const uint4*>(gAh);
    uint4 rb = *reinterpret_cast<const uint4*>(gAl);
    uint4 rc = *reinterpret_cast<const uint4*>(gBh);
    uint4 rd = *reinterpret_cast<const uint4*>(gBl);
    *reinterpret_cast<uint4*>(&sAh[0][so]) = ra;
    *reinterpret_cast<uint4*>(&sAl[0][so]) = rb;
    *reinterpret_cast<uint4*>(&sBh[0][so]) = rc;
    *reinterpret_cast<uint4*>(&sBl[0][so]) = rd;
    __syncthreads();

    int nch = K / KC;
    #pragma unroll 1
    for (int c = 0; c < nch; c++) {
        int cur = c & 1;
        if (c + 1 < nch) {
            ra = *reinterpret_cast<const uint4*>(gAh + (c + 1) * KC);
            rb = *reinterpret_cast<const uint4*>(gAl + (c + 1) * KC);
            rc = *reinterpret_cast<const uint4*>(gBh + (c + 1) * KC);
            rd = *reinterpret_cast<const uint4*>(gBl + (c + 1) * KC);
        }

        uint32_t baseAh = smem_u32(&sAh[cur][0]);
        uint32_t baseAl = smem_u32(&sAl[cur][0]);
        uint32_t baseBh = smem_u32(&sBh[cur][0]);
        uint32_t baseBl = smem_u32(&sBl[cur][0]);

        unsigned fA[4][4], fBh[4][2], fBl[4][2];
        #pragma unroll
        for (int np = 0; np < 2; np++) {
            unsigned r4[4];
            uint32_t ab = baseBh + (uint32_t)(b_row + np * 16) * (PAD * 2) + b_cb;
            ldm_x4(r4, ab);
            fBh[np * 2 + 0][0] = r4[0]; fBh[np * 2 + 0][1] = r4[1];
            fBh[np * 2 + 1][0] = r4[2]; fBh[np * 2 + 1][1] = r4[3];
            ab = baseBl + (uint32_t)(b_row + np * 16) * (PAD * 2) + b_cb;
            ldm_x4(r4, ab);
            fBl[np * 2 + 0][0] = r4[0]; fBl[np * 2 + 0][1] = r4[1];
            fBl[np * 2 + 1][0] = r4[2]; fBl[np * 2 + 1][1] = r4[3];
        }
        #pragma unroll
        for (int mt = 0; mt < 4; mt++)
            ldm_x4(fA[mt], baseAh + (uint32_t)(a_row + mt * 16) * (PAD * 2) + a_cb);
        #pragma unroll
        for (int mt = 0; mt < 4; mt++)
            #pragma unroll
            for (int nt = 0; nt < 4; nt++)
                mma_bf16(acc[mt][nt], fA[mt], fBh[nt]);
        #pragma unroll
        for (int mt = 0; mt < 4; mt++)
            #pragma unroll
            for (int nt = 0; nt < 4; nt++)
                mma_bf16(acc[mt][nt], fA[mt], fBl[nt]);
        #pragma unroll
        for (int mt = 0; mt < 4; mt++)
            ldm_x4(fA[mt], baseAl + (uint32_t)(a_row + mt * 16) * (PAD * 2) + a_cb);
        #pragma unroll
        for (int mt = 0; mt < 4; mt++)
            #pragma unroll
            for (int nt = 0; nt < 4; nt++)
                mma_bf16(acc[mt][nt], fA[mt], fBh[nt]);

        if (c + 1 < nch) {
            int nxt = cur ^ 1;
            *reinterpret_cast<uint4*>(&sAh[nxt][so]) = ra;
            *reinterpret_cast<uint4*>(&sAl[nxt][so]) = rb;
            *reinterpret_cast<uint4*>(&sBh[nxt][so]) = rc;
            *reinterpret_cast<uint4*>(&sBl[nxt][so]) = rd;
        }
        __syncthreads();
    }

    // epilogue
    #pragma unroll
    for (int mt = 0; mt < 4; mt++) {
        int row = m0 + wm * 64 + mt * 16 + (lane >> 2);
        #pragma unroll
        for (int nt = 0; nt < 4; nt++) {
            int col = n0 + wn * 32 + nt * 8 + (lane & 3) * 2;
            if (SPLIT) {
                float sc = (col < qcols) ? 0.125f : 1.0f;
                #pragma unroll
                for (int half = 0; half < 2; half++) {
                    int rr = row + half * 8;
                    float v0 = acc[mt][nt][half * 2 + 0] * sc;
                    float v1 = acc[mt][nt][half * 2 + 1] * sc;
                    unsigned hp = pack_bf2(v0, v1);
                    unsigned lp = pack_bf2(v0 - bf_round(v0), v1 - bf_round(v1));
                    *reinterpret_cast<unsigned*>(Ch + (size_t)rr * N + col) = hp;
                    *reinterpret_cast<unsigned*>(Cl + (size_t)rr * N + col) = lp;
                }
            } else {
                float bx = bias[col], by = bias[col + 1];
                float2 r0 = make_float2(acc[mt][nt][0] + bx, acc[mt][nt][1] + by);
                float2 r1 = make_float2(acc[mt][nt][2] + bx, acc[mt][nt][3] + by);
                *reinterpret_cast<float2*>(C + (size_t)row * N + col) = r0;
                *reinterpret_cast<float2*>(C + (size_t)(row + 8) * N + col) = r1;
            }
        }
    }
}

// ---------------------------------------------------------------------------
// Flash attention on tensor cores (bf16x3, FA2-style register softmax).
// BQ=64 (4 warps x 16 rows), 128 threads -> 2-3 CTAs/SM for phase overlap.
// K/V double-buffered via cp.async. Q pre-scaled by 0.125.
// ---------------------------------------------------------------------------
#define APAD 72
#define KVB (4 * 64 * APAD)      // bf16 elems per K/V buffer
#define ASMEM (2 * KVB * 2)      // bytes (73728)

__global__ void __launch_bounds__(128)
attn_mma(const bf16* __restrict__ qkh, const bf16* __restrict__ qkl,
         const bf16* __restrict__ vh, const bf16* __restrict__ vl,
         float* __restrict__ out) {
    extern __shared__ bf16 sm[];
    const uint32_t sb = smem_u32(sm);

    int qt = blockIdx.x, h = blockIdx.y, b = blockIdx.z;
    int tid = threadIdx.x, warp = tid >> 5, lane = tid & 31;
    int quad = lane >> 2, tq = lane & 3;

    // --- stage Q hi/lo (64 rows each) in buf0 region; build persistent frags ---
    for (int i = tid; i < 64 * 8; i += 128) {
        int r = i >> 3, c8 = (i & 7) * 8;
        size_t grow = (size_t)(b * NN + qt * 64 + r) * (2 * CC) + h * HD + c8;
        *reinterpret_cast<uint4*>(&sm[r * APAD + c8]) =
            *reinterpret_cast<const uint4*>(qkh + grow);
        *reinterpret_cast<uint4*>(&sm[(64 + r) * APAD + c8]) =
            *reinterpret_cast<const uint4*>(qkl + grow);
    }
    __syncthreads();
    unsigned fQh[4][4], fQl[4][4];
    {
        int ar = warp * 16 + (lane & 15);
        int cb = ((lane >> 4) & 1) * 16;
        #pragma unroll
        for (int kk = 0; kk < 4; kk++) {
            ldm_x4(fQh[kk], sb + (uint32_t)(ar * APAD) * 2 + kk * 32 + cb);
            ldm_x4(fQl[kk], sb + (uint32_t)((64 + ar) * APAD) * 2 + kk * 32 + cb);
        }
    }
    __syncthreads();

    float O[8][4];
    #pragma unroll
    for (int nt = 0; nt < 8; nt++)
        #pragma unroll
        for (int q = 0; q < 4; q++) O[nt][q] = 0.0f;
    float m0 = -1e30f, m1 = -1e30f, l0 = 0.0f, l1 = 0.0f;

    // cp.async addressing: thread covers rows (tid>>3)+{0,16,32,48}, col (tid&7)*8
    int krow = tid >> 3, kcol = (tid & 7) * 8;

    // B-frag ldmatrix lane addressing
    int kb_row = ((lane >> 4) & 1) * 8 + (lane & 7);
    int kb_cb  = ((lane >> 3) & 1) * 16;
    int vb_row = ((lane >> 3) & 1) * 8 + (lane & 7);
    int vb_cb  = ((lane >> 4) & 1) * 16;

    auto kv_issue = [&](int it, int buf) {
        uint32_t base = sb + (uint32_t)buf * (KVB * 2);
        #pragma unroll
        for (int rr = 0; rr < 64; rr += 16) {
            int r = krow + rr;
            size_t gk = (size_t)(b * NN + it * 64 + r) * (2 * CC) + CC + h * HD + kcol;
            size_t gv = (size_t)(b * NN + it * 64 + r) * CC + h * HD + kcol;
            cp16(base + (uint32_t)(0 * 64 * APAD + r * APAD + kcol) * 2, qkh + gk);
            cp16(base + (uint32_t)(1 * 64 * APAD + r * APAD + kcol) * 2, qkl + gk);
            cp16(base + (uint32_t)(2 * 64 * APAD + r * APAD + kcol) * 2, vh + gv);
            cp16(base + (uint32_t)(3 * 64 * APAD + r * APAD + kcol) * 2, vl + gv);
        }
        CP_COMMIT();
    };

    kv_issue(0, 0);

    const int NIT = NN / 64;
    #pragma unroll 1
    for (int it = 0; it < NIT; it++) {
        int cur = it & 1;
        if (it + 1 < NIT) {
            kv_issue(it + 1, cur ^ 1);
            CP_WAIT1();
        } else {
            CP_WAIT0();
        }
        __syncthreads();

        uint32_t base = sb + (uint32_t)cur * (KVB * 2);
        uint32_t sKh = base;
        uint32_t sKl = base + 64 * APAD * 2;
        uint32_t sVh = base + 2 * 64 * APAD * 2;
        uint32_t sVl = base + 3 * 64 * APAD * 2;

        // ---- S = Q @ K^T (3 passes) ----
        float S[8][4];
        #pragma unroll
        for (int nt = 0; nt < 8; nt++)
            #pragma unroll
            for (int q = 0; q < 4; q++) S[nt][q] = 0.0f;

        #pragma unroll
        for (int kk = 0; kk < 4; kk++) {
            unsigned fKh[8][2], fKl[8][2];
            #pragma unroll
            for (int np = 0; np < 4; np++) {
                unsigned r4[4];
                uint32_t off = (uint32_t)(kb_row + np * 16) * (APAD * 2) + kb_cb + kk * 32;
                ldm_x4(r4, sKh + off);
                fKh[np * 2 + 0][0] = r4[0]; fKh[np * 2 + 0][1] = r4[1];
                fKh[np * 2 + 1][0] = r4[2]; fKh[np * 2 + 1][1] = r4[3];
                ldm_x4(r4, sKl + off);
                fKl[np * 2 + 0][0] = r4[0]; fKl[np * 2 + 0][1] = r4[1];
                fKl[np * 2 + 1][0] = r4[2]; fKl[np * 2 + 1][1] = r4[3];
            }
            #pragma unroll
            for (int nt = 0; nt < 8; nt++) {
                mma_bf16(S[nt], fQh[kk], fKh[nt]);
                mma_bf16(S[nt], fQh[kk], fKl[nt]);
                mma_bf16(S[nt], fQl[kk], fKh[nt]);
            }
        }

        // ---- online softmax in registers ----
        float mx0 = -1e30f, mx1 = -1e30f;
        #pragma unroll
        for (int nt = 0; nt < 8; nt++) {
            mx0 = fmaxf(mx0, fmaxf(S[nt][0], S[nt][1]));
            mx1 = fmaxf(mx1, fmaxf(S[nt][2], S[nt][3]));
        }
        mx0 = fmaxf(mx0, __shfl_xor_sync(0xFFFFFFFFu, mx0, 1));
        mx0 = fmaxf(mx0, __shfl_xor_sync(0xFFFFFFFFu, mx0, 2));
        mx1 = fmaxf(mx1, __shfl_xor_sync(0xFFFFFFFFu, mx1, 1));
        mx1 = fmaxf(mx1, __shfl_xor_sync(0xFFFFFFFFu, mx1, 2));
        float mn0 = fmaxf(m0, mx0), mn1 = fmaxf(m1, mx1);
        float al0 = __expf(m0 - mn0), al1 = __expf(m1 - mn1);
        m0 = mn0; m1 = mn1;

        float s0 = 0.0f, s1 = 0.0f;
        #pragma unroll
        for (int nt = 0; nt < 8; nt++) {
            S[nt][0] = __expf(S[nt][0] - mn0); s0 += S[nt][0];
            S[nt][1] = __expf(S[nt][1] - mn0); s0 += S[nt][1];
            S[nt][2] = __expf(S[nt][2] - mn1); s1 += S[nt][2];
            S[nt][3] = __expf(S[nt][3] - mn1); s1 += S[nt][3];
        }
        s0 += __shfl_xor_sync(0xFFFFFFFFu, s0, 1);
        s0 += __shfl_xor_sync(0xFFFFFFFFu, s0, 2);
        s1 += __shfl_xor_sync(0xFFFFFFFFu, s1, 1);
        s1 += __shfl_xor_sync(0xFFFFFFFFu, s1, 2);
        l0 = l0 * al0 + s0;
        l1 = l1 * al1 + s1;

        // rescale O
        #pragma unroll
        for (int nt = 0; nt < 8; nt++) {
            O[nt][0] *= al0; O[nt][1] *= al0;
            O[nt][2] *= al1; O[nt][3] *= al1;
        }

        // pack P hi/lo (C-frag -> A-frag identity)
        unsigned Phi[8][2], Plo[8][2];
        #pragma unroll
        for (int nt = 0; nt < 8; nt++) {
            float p0 = S[nt][0], p1 = S[nt][1], p2 = S[nt][2], p3 = S[nt][3];
            Phi[nt][0] = pack_bf2(p0, p1);
            Phi[nt][1] = pack_bf2(p2, p3);
            Plo[nt][0] = pack_bf2(p0 - bf_round(p0), p1 - bf_round(p1));
            Plo[nt][1] = pack_bf2(p2 - bf_round(p2), p3 - bf_round(p3));
        }

        // ---- O += P @ V (3 passes) ----
        #pragma unroll
        for (int kk = 0; kk < 4; kk++) {
            unsigned aPh[4] = {Phi[2 * kk][0], Phi[2 * kk][1],
                               Phi[2 * kk + 1][0], Phi[2 * kk + 1][1]};
            unsigned aPl[4] = {Plo[2 * kk][0], Plo[2 * kk][1],
                               Plo[2 * kk + 1][0], Plo[2 * kk + 1][1]};
            unsigned fVh[8][2], fVl[8][2];
            #pragma unroll
            for (int nt2 = 0; nt2 < 4; nt2++) {
                unsigned r4[4];
                uint32_t off = (uint32_t)(vb_row + kk * 16) * (APAD * 2) + vb_cb + nt2 * 32;
                ldm_x4t(r4, sVh + off);
                fVh[nt2 * 2 + 0][0] = r4[0]; fVh[nt2 * 2 + 0][1] = r4[1];
                fVh[nt2 * 2 + 1][0] = r4[2]; fVh[nt2 * 2 + 1][1] = r4[3];
                ldm_x4t(r4, sVl + off);
                fVl[nt2 * 2 + 0][0] = r4[0]; fVl[nt2 * 2 + 0][1] = r4[1];
                fVl[nt2 * 2 + 1][0] = r4[2]; fVl[nt2 * 2 + 1][1] = r4[3];
            }
            #pragma unroll
            for (int nt = 0; nt < 8; nt++) {
                mma_bf16(O[nt], aPh, fVh[nt]);
                mma_bf16(O[nt], aPh, fVl[nt]);
                mma_bf16(O[nt], aPl, fVh[nt]);
            }
        }
        __syncthreads();
    }

    // ---- finalize & store ----
    float inv0 = 1.0f / l0, inv1 = 1.0f / l1;
    int row0 = b * NN + qt * 64 + warp * 16 + quad;
    #pragma unroll
    for (int nt = 0; nt < 8; nt++) {
        int col = h * HD + nt * 8 + tq * 2;
        *reinterpret_cast<float2*>(out + (size_t)row0 * CC + col) =
            make_float2(O[nt][0] * inv0, O[nt][1] * inv0);
        *reinterpret_cast<float2*>(out + (size_t)(row0 + 8) * CC + col) =
            make_float2(O[nt][2] * inv1, O[nt][3] * inv1);
    }
}

// ---------------------------------------------------------------------------
extern "C" void kernel_launch(void* const* d_in, const int* in_sizes, int n_in,
                              void* d_out, int out_size) {
    const float* x      = (const float*)d_in[0];
    const float* ln1_g  = (const float*)d_in[1];
    const float* ln1_b  = (const float*)d_in[2];
    const float* w_qk   = (const float*)d_in[3];
    const float* w_v    = (const float*)d_in[4];
    const float* ln2_g  = (const float*)d_in[5];
    const float* ln2_b  = (const float*)d_in[6];
    const float* w_proj = (const float*)d_in[7];
    const float* b_proj = (const float*)d_in[8];
    float* out = (float*)d_out;

    float* ao;
    bf16 *xh, *xl, *qkh, *qkl, *vhp, *vlp, *wqkh, *wqkl, *wvh, *wvl, *wph, *wpl;
    cudaGetSymbolAddress((void**)&ao,   g_ao);
    cudaGetSymbolAddress((void**)&xh,   g_xh);
    cudaGetSymbolAddress((void**)&xl,   g_xl);
    cudaGetSymbolAddress((void**)&qkh,  g_qkh);
    cudaGetSymbolAddress((void**)&qkl,  g_qkl);
    cudaGetSymbolAddress((void**)&vhp,  g_vh);
    cudaGetSymbolAddress((void**)&vlp,  g_vl);
    cudaGetSymbolAddress((void**)&wqkh, g_wqkT_h);
    cudaGetSymbolAddress((void**)&wqkl, g_wqkT_l);
    cudaGetSymbolAddress((void**)&wvh,  g_wvT_h);
    cudaGetSymbolAddress((void**)&wvl,  g_wvT_l);
    cudaGetSymbolAddress((void**)&wph,  g_wpT_h);
    cudaGetSymbolAddress((void**)&wpl,  g_wpT_l);

    cudaFuncSetAttribute(attn_mma, cudaFuncAttributeMaxDynamicSharedMemorySize, ASMEM);

    // weight transpose+split
    wsplit_kernel<<<dim3(2 * CC / 32, CC / 32), dim3(32, 8)>>>(w_qk, wqkh, wqkl, CC, 2 * CC);
    wsplit_kernel<<<dim3(CC / 32, CC / 32), dim3(32, 8)>>>(w_v, wvh, wvl, CC, CC);
    wsplit_kernel<<<dim3(CC / 32, CC / 32), dim3(32, 8)>>>(w_proj, wph, wpl, CC, CC);

    // 1. LN1 -> bf16 hi/lo
    ln_split_kernel<<<MM, 256>>>(x, ln1_g, ln1_b, xh, xl);

    // 2. projections -> bf16 hi/lo (q pre-scaled by 0.125)
    gemm_mma<true><<<dim3(2 * CC / 128, MM / 128), 256>>>(
        xh, xl, wqkh, wqkl, nullptr, nullptr, qkh, qkl, MM, 2 * CC, CC, CC);
    gemm_mma<true><<<dim3(CC / 128, MM / 128), 256>>>(
        xh, xl, wvh, wvl, nullptr, nullptr, vhp, vlp, MM, CC, CC, 0);

    // 3. tensor-core flash attention (BQ=64, 2-3 CTAs/SM)
    attn_mma<<<dim3(NN / 64, HH, BB), 128, ASMEM>>>(qkh, qkl, vhp, vlp, ao);

    // 4. LN2 -> bf16 hi/lo
    ln_split_kernel<<<MM, 256>>>(ao, ln2_g, ln2_b, xh, xl);

    // 5. output projection + bias (fp32 out)
    gemm_mma<false><<<dim3(CC / 128, MM / 128), 256>>>(
        xh, xl, wph, wpl, b_proj, out, nullptr, nullptr, MM, CC, CC, 0);
}

// round 9
// speedup vs baseline: 1.3357x; 1.1386x over previous
#include <cuda_runtime.h>
#include <cuda_bf16.h>
#include <cuda_fp16.h>
#include <cstdint>

// Problem constants (fixed shapes)
#define BB 2
#define NN 2048
#define CC 1024
#define HH 16
#define HD 64
#define MM (BB * NN)   // 4096 rows

typedef __nv_bfloat16 bf16;
typedef __half f16;

// ---------------------------------------------------------------------------
// Scratch (device globals — no allocations allowed)
// ---------------------------------------------------------------------------
__device__ float g_ao[MM * CC];
__device__ bf16 g_xh[MM * CC], g_xl[MM * CC];
__device__ f16 g_qkh[MM * 2 * CC];             // q|k in fp16 (1-pass fp16 QK)
__device__ bf16 g_vh[MM * CC], g_vl[MM * CC];
__device__ bf16 g_wqkT_h[2 * CC * CC], g_wqkT_l[2 * CC * CC];
__device__ bf16 g_wvT_h[CC * CC], g_wvT_l[CC * CC];
__device__ bf16 g_wpT_h[CC * CC], g_wpT_l[CC * CC];

// ---------------------------------------------------------------------------
// helpers
// ---------------------------------------------------------------------------
__device__ __forceinline__ uint32_t smem_u32(const void* p) {
    uint32_t a;
    asm("{ .reg .u64 t; cvta.to.shared.u64 t, %1; cvt.u32.u64 %0, t; }"
        : "=r"(a) : "l"(p));
    return a;
}

__device__ __forceinline__ void mma_bf16(float* c, const unsigned* a, const unsigned* b) {
    asm volatile(
        "mma.sync.aligned.m16n8k16.row.col.f32.bf16.bf16.f32 "
        "{%0,%1,%2,%3}, {%4,%5,%6,%7}, {%8,%9}, {%0,%1,%2,%3};"
        : "+f"(c[0]), "+f"(c[1]), "+f"(c[2]), "+f"(c[3])
        : "r"(a[0]), "r"(a[1]), "r"(a[2]), "r"(a[3]), "r"(b[0]), "r"(b[1]));
}
__device__ __forceinline__ void mma_f16(float* c, const unsigned* a, const unsigned* b) {
    asm volatile(
        "mma.sync.aligned.m16n8k16.row.col.f32.f16.f16.f32 "
        "{%0,%1,%2,%3}, {%4,%5,%6,%7}, {%8,%9}, {%0,%1,%2,%3};"
        : "+f"(c[0]), "+f"(c[1]), "+f"(c[2]), "+f"(c[3])
        : "r"(a[0]), "r"(a[1]), "r"(a[2]), "r"(a[3]), "r"(b[0]), "r"(b[1]));
}

__device__ __forceinline__ void ldm_x4(unsigned* r, uint32_t addr) {
    asm volatile("ldmatrix.sync.aligned.m8n8.x4.shared.b16 {%0,%1,%2,%3}, [%4];"
        : "=r"(r[0]), "=r"(r[1]), "=r"(r[2]), "=r"(r[3]) : "r"(addr));
}
__device__ __forceinline__ void ldm_x4t(unsigned* r, uint32_t addr) {
    asm volatile("ldmatrix.sync.aligned.m8n8.x4.trans.shared.b16 {%0,%1,%2,%3}, [%4];"
        : "=r"(r[0]), "=r"(r[1]), "=r"(r[2]), "=r"(r[3]) : "r"(addr));
}

// cp.async 16B global -> shared (attention K/V only)
__device__ __forceinline__ void cp16(uint32_t dst, const void* src) {
    asm volatile("cp.async.cg.shared.global [%0], [%1], 16;"
        :: "r"(dst), "l"(__cvta_generic_to_global(src)) : "memory");
}
#define CP_COMMIT() asm volatile("cp.async.commit_group;" ::: "memory")
#define CP_WAIT1()  asm volatile("cp.async.wait_group 1;" ::: "memory")
#define CP_WAIT0()  asm volatile("cp.async.wait_group 0;" ::: "memory")

// pack two f32 -> bf16x2 / f16x2 register (lo = first arg)
__device__ __forceinline__ unsigned pack_bf2(float lo, float hi) {
    unsigned r;
    asm("cvt.rn.bf16x2.f32 %0, %1, %2;" : "=r"(r) : "f"(hi), "f"(lo));
    return r;
}
__device__ __forceinline__ unsigned pack_f162(float lo, float hi) {
    unsigned r;
    asm("cvt.rn.f16x2.f32 %0, %1, %2;" : "=r"(r) : "f"(hi), "f"(lo));
    return r;
}
__device__ __forceinline__ float bf_round(float x) {
    return __bfloat162float(__float2bfloat16(x));
}

// ---------------------------------------------------------------------------
// LayerNorm -> bf16 hi/lo split output
// ---------------------------------------------------------------------------
__global__ void ln_split_kernel(const float* __restrict__ x,
                                const float* __restrict__ g,
                                const float* __restrict__ b,
                                bf16* __restrict__ oh,
                                bf16* __restrict__ ol) {
    int row = blockIdx.x;
    int t = threadIdx.x;
    const float4* xr = reinterpret_cast<const float4*>(x + (size_t)row * CC);
    float4 v = xr[t];
    float s  = v.x + v.y + v.z + v.w;
    float ss = v.x * v.x + v.y * v.y + v.z * v.z + v.w * v.w;

    #pragma unroll
    for (int o = 16; o > 0; o >>= 1) {
        s  += __shfl_down_sync(0xFFFFFFFFu, s,  o);
        ss += __shfl_down_sync(0xFFFFFFFFu, ss, o);
    }
    __shared__ float sh[8][2];
    int w = t >> 5, l = t & 31;
    if (l == 0) { sh[w][0] = s; sh[w][1] = ss; }
    __syncthreads();
    if (w == 0) {
        s  = (l < 8) ? sh[l][0] : 0.0f;
        ss = (l < 8) ? sh[l][1] : 0.0f;
        #pragma unroll
        for (int o = 4; o > 0; o >>= 1) {
            s  += __shfl_down_sync(0xFFFFFFFFu, s,  o);
            ss += __shfl_down_sync(0xFFFFFFFFu, ss, o);
        }
        if (l == 0) { sh[0][0] = s; sh[0][1] = ss; }
    }
    __syncthreads();
    s = sh[0][0]; ss = sh[0][1];

    float mu  = s * (1.0f / CC);
    float var = ss * (1.0f / CC) - mu * mu;
    float inv = rsqrtf(var + 1e-5f);

    const float4 gv = reinterpret_cast<const float4*>(g)[t];
    const float4 bv = reinterpret_cast<const float4*>(b)[t];
    float o0 = (v.x - mu) * inv * gv.x + bv.x;
    float o1 = (v.y - mu) * inv * gv.y + bv.y;
    float o2 = (v.z - mu) * inv * gv.z + bv.z;
    float o3 = (v.w - mu) * inv * gv.w + bv.w;

    unsigned h01 = pack_bf2(o0, o1), h23 = pack_bf2(o2, o3);
    unsigned l01 = pack_bf2(o0 - bf_round(o0), o1 - bf_round(o1));
    unsigned l23 = pack_bf2(o2 - bf_round(o2), o3 - bf_round(o3));
    uint2* hp = reinterpret_cast<uint2*>(oh + (size_t)row * CC + t * 4);
    uint2* lp = reinterpret_cast<uint2*>(ol + (size_t)row * CC + t * 4);
    *hp = make_uint2(h01, h23);
    *lp = make_uint2(l01, l23);
}

// ---------------------------------------------------------------------------
// Transpose + split: w[K][N] fp32 -> wT_hi/lo[N][K] bf16
// ---------------------------------------------------------------------------
__global__ void wsplit_kernel(const float* __restrict__ w,
                              bf16* __restrict__ th,
                              bf16* __restrict__ tl,
                              int K, int N) {
    __shared__ float t[32][33];
    int bx = blockIdx.x, by = blockIdx.y;
    int x = bx * 32 + threadIdx.x;
    #pragma unroll
    for (int j = 0; j < 32; j += 8)
        t[threadIdx.y + j][threadIdx.x] = w[(size_t)(by * 32 + threadIdx.y + j) * N + x];
    __syncthreads();
    int n = bx * 32 + threadIdx.y;
    int k = by * 32 + threadIdx.x;
    #pragma unroll
    for (int j = 0; j < 32; j += 8) {
        float v = t[threadIdx.x][threadIdx.y + j];
        bf16 h = __float2bfloat16(v);
        th[(size_t)(n + j) * K + k] = h;
        tl[(size_t)(n + j) * K + k] = __float2bfloat16(v - __bfloat162float(h));
    }
}

// ---------------------------------------------------------------------------
// mma.sync bf16x3 GEMM (register-prefetch, double-buffered; proven fastest).
// MODE 0: fp32 out (+bias). MODE 1: bf16 hi/lo out. MODE 2: fp16 hi-only out,
// cols<qcols scaled x0.125 (q pre-scale; exact exponent shift).
// CTA 128x128 tile, 8 warps (2x4), warp 64x32, K chunk 16.
// ---------------------------------------------------------------------------
#define KC 16
#define PAD 24

template <int MODE>
__global__ void __launch_bounds__(256)
gemm_mma(const bf16* __restrict__ Ah, const bf16* __restrict__ Al,
         const bf16* __restrict__ Bh, const bf16* __restrict__ Bl,
         const float* __restrict__ bias, float* __restrict__ C,
         bf16* __restrict__ Ch, bf16* __restrict__ Cl,
         int M, int N, int K, int qcols) {
    __shared__ bf16 sAh[2][128 * PAD];
    __shared__ bf16 sAl[2][128 * PAD];
    __shared__ bf16 sBh[2][128 * PAD];
    __shared__ bf16 sBl[2][128 * PAD];

    int tid = threadIdx.x;
    int warp = tid >> 5, lane = tid & 31;
    int wm = warp >> 2, wn = warp & 3;
    int m0 = blockIdx.y * 128, n0 = blockIdx.x * 128;

    int lr = tid >> 1;
    int lk = (tid & 1) * 8;
    const bf16* gAh = Ah + (size_t)(m0 + lr) * K + lk;
    const bf16* gAl = Al + (size_t)(m0 + lr) * K + lk;
    const bf16* gBh = Bh + (size_t)(n0 + lr) * K + lk;
    const bf16* gBl = Bl + (size_t)(n0 + lr) * K + lk;
    int so = lr * PAD + lk;

    float acc[4][4][4];
    #pragma unroll
    for (int i = 0; i < 4; i++)
        #pragma unroll
        for (int j = 0; j < 4; j++)
            #pragma unroll
            for (int q = 0; q < 4; q++) acc[i][j][q] = 0.0f;

    int a_row = wm * 64 + (lane & 15);
    int a_cb  = ((lane >> 4) & 1) * 16;
    int b_row = wn * 32 + ((lane >> 4) & 1) * 8 + (lane & 7);
    int b_cb  = ((lane >> 3) & 1) * 16;

    uint4 ra = *reinterpret_cast<const uint4*>(gAh);
    uint4 rb = *reinterpret_cast<const uint4*>(gAl);
    uint4 rc = *reinterpret_cast<const uint4*>(gBh);
    uint4 rd = *reinterpret_cast<const uint4*>(gBl);
    *reinterpret_cast<uint4*>(&sAh[0][so]) = ra;
    *reinterpret_cast<uint4*>(&sAl[0][so]) = rb;
    *reinterpret_cast<uint4*>(&sBh[0][so]) = rc;
    *reinterpret_cast<uint4*>(&sBl[0][so]) = rd;
    __syncthreads();

    int nch = K / KC;
    #pragma unroll 1
    for (int c = 0; c < nch; c++) {
        int cur = c & 1;
        if (c + 1 < nch) {
            ra = *reinterpret_cast<const uint4*>(gAh + (c + 1) * KC);
            rb = *reinterpret_cast<const uint4*>(gAl + (c + 1) * KC);
            rc = *reinterpret_cast<const uint4*>(gBh + (c + 1) * KC);
            rd = *reinterpret_cast<const uint4*>(gBl + (c + 1) * KC);
        }

        uint32_t baseAh = smem_u32(&sAh[cur][0]);
        uint32_t baseAl = smem_u32(&sAl[cur][0]);
        uint32_t baseBh = smem_u32(&sBh[cur][0]);
        uint32_t baseBl = smem_u32(&sBl[cur][0]);

        unsigned fA[4][4], fBh[4][2], fBl[4][2];
        #pragma unroll
        for (int np = 0; np < 2; np++) {
            unsigned r4[4];
            uint32_t ab = baseBh + (uint32_t)(b_row + np * 16) * (PAD * 2) + b_cb;
            ldm_x4(r4, ab);
            fBh[np * 2 + 0][0] = r4[0]; fBh[np * 2 + 0][1] = r4[1];
            fBh[np * 2 + 1][0] = r4[2]; fBh[np * 2 + 1][1] = r4[3];
            ab = baseBl + (uint32_t)(b_row + np * 16) * (PAD * 2) + b_cb;
            ldm_x4(r4, ab);
            fBl[np * 2 + 0][0] = r4[0]; fBl[np * 2 + 0][1] = r4[1];
            fBl[np * 2 + 1][0] = r4[2]; fBl[np * 2 + 1][1] = r4[3];
        }
        #pragma unroll
        for (int mt = 0; mt < 4; mt++)
            ldm_x4(fA[mt], baseAh + (uint32_t)(a_row + mt * 16) * (PAD * 2) + a_cb);
        #pragma unroll
        for (int mt = 0; mt < 4; mt++)
            #pragma unroll
            for (int nt = 0; nt < 4; nt++)
                mma_bf16(acc[mt][nt], fA[mt], fBh[nt]);
        #pragma unroll
        for (int mt = 0; mt < 4; mt++)
            #pragma unroll
            for (int nt = 0; nt < 4; nt++)
                mma_bf16(acc[mt][nt], fA[mt], fBl[nt]);
        #pragma unroll
        for (int mt = 0; mt < 4; mt++)
            ldm_x4(fA[mt], baseAl + (uint32_t)(a_row + mt * 16) * (PAD * 2) + a_cb);
        #pragma unroll
        for (int mt = 0; mt < 4; mt++)
            #pragma unroll
            for (int nt = 0; nt < 4; nt++)
                mma_bf16(acc[mt][nt], fA[mt], fBh[nt]);

        if (c + 1 < nch) {
            int nxt = cur ^ 1;
            *reinterpret_cast<uint4*>(&sAh[nxt][so]) = ra;
            *reinterpret_cast<uint4*>(&sAl[nxt][so]) = rb;
            *reinterpret_cast<uint4*>(&sBh[nxt][so]) = rc;
            *reinterpret_cast<uint4*>(&sBl[nxt][so]) = rd;
        }
        __syncthreads();
    }

    // epilogue
    #pragma unroll
    for (int mt = 0; mt < 4; mt++) {
        int row = m0 + wm * 64 + mt * 16 + (lane >> 2);
        #pragma unroll
        for (int nt = 0; nt < 4; nt++) {
            int col = n0 + wn * 32 + nt * 8 + (lane & 3) * 2;
            if (MODE == 2) {
                float sc = (col < qcols) ? 0.125f : 1.0f;
                #pragma unroll
                for (int half = 0; half < 2; half++) {
                    int rr = row + half * 8;
                    float v0 = acc[mt][nt][half * 2 + 0] * sc;
                    float v1 = acc[mt][nt][half * 2 + 1] * sc;
                    *reinterpret_cast<unsigned*>(Ch + (size_t)rr * N + col) = pack_f162(v0, v1);
                }
            } else if (MODE == 1) {
                #pragma unroll
                for (int half = 0; half < 2; half++) {
                    int rr = row + half * 8;
                    float v0 = acc[mt][nt][half * 2 + 0];
                    float v1 = acc[mt][nt][half * 2 + 1];
                    unsigned hp = pack_bf2(v0, v1);
                    unsigned lp = pack_bf2(v0 - bf_round(v0), v1 - bf_round(v1));
                    *reinterpret_cast<unsigned*>(Ch + (size_t)rr * N + col) = hp;
                    *reinterpret_cast<unsigned*>(Cl + (size_t)rr * N + col) = lp;
                }
            } else {
                float bx = bias[col], by = bias[col + 1];
                float2 r0 = make_float2(acc[mt][nt][0] + bx, acc[mt][nt][1] + by);
                float2 r1 = make_float2(acc[mt][nt][2] + bx, acc[mt][nt][3] + by);
                *reinterpret_cast<float2*>(C + (size_t)row * N + col) = r0;
                *reinterpret_cast<float2*>(C + (size_t)(row + 8) * N + col) = r1;
            }
        }
    }
}

// ---------------------------------------------------------------------------
// Flash attention on tensor cores. 1-pass fp16 QK (fp16 roundoff 2^-11 is 8x
// finer than bf16; measured bf16 1-pass error 2.18e-3 -> ~2.7e-4 here).
// 3-pass bf16 PV (those errors don't average — kept exact-ish).
// BQ=64 (4 warps x 16 rows), 128 threads. K/V double-buffered via cp.async.
// Q pre-scaled by 0.125.
// ---------------------------------------------------------------------------
#define APAD 72
#define KVB (3 * 64 * APAD)      // elems per K/V buffer (Kh | Vh | Vl)
#define ASMEM (2 * KVB * 2)      // bytes (55296)

__global__ void __launch_bounds__(128)
attn_mma(const f16* __restrict__ qkh,
         const bf16* __restrict__ vh, const bf16* __restrict__ vl,
         float* __restrict__ out) {
    extern __shared__ bf16 sm[];
    const uint32_t sb = smem_u32(sm);

    int qt = blockIdx.x, h = blockIdx.y, b = blockIdx.z;
    int tid = threadIdx.x, warp = tid >> 5, lane = tid & 31;
    int quad = lane >> 2, tq = lane & 3;

    // --- stage Q (fp16, 64 rows) in buf0 region; build persistent frags ---
    for (int i = tid; i < 64 * 8; i += 128) {
        int r = i >> 3, c8 = (i & 7) * 8;
        size_t grow = (size_t)(b * NN + qt * 64 + r) * (2 * CC) + h * HD + c8;
        *reinterpret_cast<uint4*>(&sm[r * APAD + c8]) =
            *reinterpret_cast<const uint4*>(qkh + grow);
    }
    __syncthreads();
    unsigned fQh[4][4];
    {
        int ar = warp * 16 + (lane & 15);
        int cb = ((lane >> 4) & 1) * 16;
        #pragma unroll
        for (int kk = 0; kk < 4; kk++)
            ldm_x4(fQh[kk], sb + (uint32_t)(ar * APAD) * 2 + kk * 32 + cb);
    }
    __syncthreads();

    float O[8][4];
    #pragma unroll
    for (int nt = 0; nt < 8; nt++)
        #pragma unroll
        for (int q = 0; q < 4; q++) O[nt][q] = 0.0f;
    float m0 = -1e30f, m1 = -1e30f, l0 = 0.0f, l1 = 0.0f;

    // cp.async addressing: thread covers rows (tid>>3)+{0,16,32,48}, col (tid&7)*8
    int krow = tid >> 3, kcol = (tid & 7) * 8;

    // B-frag ldmatrix lane addressing
    int kb_row = ((lane >> 4) & 1) * 8 + (lane & 7);
    int kb_cb  = ((lane >> 3) & 1) * 16;
    int vb_row = ((lane >> 3) & 1) * 8 + (lane & 7);
    int vb_cb  = ((lane >> 4) & 1) * 16;

    auto kv_issue = [&](int it, int buf) {
        uint32_t base = sb + (uint32_t)buf * (KVB * 2);
        #pragma unroll
        for (int rr = 0; rr < 64; rr += 16) {
            int r = krow + rr;
            size_t gk = (size_t)(b * NN + it * 64 + r) * (2 * CC) + CC + h * HD + kcol;
            size_t gv = (size_t)(b * NN + it * 64 + r) * CC + h * HD + kcol;
            cp16(base + (uint32_t)(0 * 64 * APAD + r * APAD + kcol) * 2, qkh + gk);
            cp16(base + (uint32_t)(1 * 64 * APAD + r * APAD + kcol) * 2, vh + gv);
            cp16(base + (uint32_t)(2 * 64 * APAD + r * APAD + kcol) * 2, vl + gv);
        }
        CP_COMMIT();
    };

    kv_issue(0, 0);

    const int NIT = NN / 64;
    #pragma unroll 1
    for (int it = 0; it < NIT; it++) {
        int cur = it & 1;
        if (it + 1 < NIT) {
            kv_issue(it + 1, cur ^ 1);
            CP_WAIT1();
        } else {
            CP_WAIT0();
        }
        __syncthreads();

        uint32_t base = sb + (uint32_t)cur * (KVB * 2);
        uint32_t sKh = base;
        uint32_t sVh = base + 1 * 64 * APAD * 2;
        uint32_t sVl = base + 2 * 64 * APAD * 2;

        // ---- S = Q @ K^T (1 pass, fp16) ----
        float S[8][4];
        #pragma unroll
        for (int nt = 0; nt < 8; nt++)
            #pragma unroll
            for (int q = 0; q < 4; q++) S[nt][q] = 0.0f;

        #pragma unroll
        for (int kk = 0; kk < 4; kk++) {
            unsigned fKh[8][2];
            #pragma unroll
            for (int np = 0; np < 4; np++) {
                unsigned r4[4];
                uint32_t off = (uint32_t)(kb_row + np * 16) * (APAD * 2) + kb_cb + kk * 32;
                ldm_x4(r4, sKh + off);
                fKh[np * 2 + 0][0] = r4[0]; fKh[np * 2 + 0][1] = r4[1];
                fKh[np * 2 + 1][0] = r4[2]; fKh[np * 2 + 1][1] = r4[3];
            }
            #pragma unroll
            for (int nt = 0; nt < 8; nt++)
                mma_f16(S[nt], fQh[kk], fKh[nt]);
        }

        // ---- online softmax in registers ----
        float mx0 = -1e30f, mx1 = -1e30f;
        #pragma unroll
        for (int nt = 0; nt < 8; nt++) {
            mx0 = fmaxf(mx0, fmaxf(S[nt][0], S[nt][1]));
            mx1 = fmaxf(mx1, fmaxf(S[nt][2], S[nt][3]));
        }
        mx0 = fmaxf(mx0, __shfl_xor_sync(0xFFFFFFFFu, mx0, 1));
        mx0 = fmaxf(mx0, __shfl_xor_sync(0xFFFFFFFFu, mx0, 2));
        mx1 = fmaxf(mx1, __shfl_xor_sync(0xFFFFFFFFu, mx1, 1));
        mx1 = fmaxf(mx1, __shfl_xor_sync(0xFFFFFFFFu, mx1, 2));
        float mn0 = fmaxf(m0, mx0), mn1 = fmaxf(m1, mx1);
        float al0 = __expf(m0 - mn0), al1 = __expf(m1 - mn1);
        m0 = mn0; m1 = mn1;

        float s0 = 0.0f, s1 = 0.0f;
        #pragma unroll
        for (int nt = 0; nt < 8; nt++) {
            S[nt][0] = __expf(S[nt][0] - mn0); s0 += S[nt][0];
            S[nt][1] = __expf(S[nt][1] - mn0); s0 += S[nt][1];
            S[nt][2] = __expf(S[nt][2] - mn1); s1 += S[nt][2];
            S[nt][3] = __expf(S[nt][3] - mn1); s1 += S[nt][3];
        }
        s0 += __shfl_xor_sync(0xFFFFFFFFu, s0, 1);
        s0 += __shfl_xor_sync(0xFFFFFFFFu, s0, 2);
        s1 += __shfl_xor_sync(0xFFFFFFFFu, s1, 1);
        s1 += __shfl_xor_sync(0xFFFFFFFFu, s1, 2);
        l0 = l0 * al0 + s0;
        l1 = l1 * al1 + s1;

        // rescale O
        #pragma unroll
        for (int nt = 0; nt < 8; nt++) {
            O[nt][0] *= al0; O[nt][1] *= al0;
            O[nt][2] *= al1; O[nt][3] *= al1;
        }

        // pack P hi/lo (C-frag -> A-frag identity)
        unsigned Phi[8][2], Plo[8][2];
        #pragma unroll
        for (int nt = 0; nt < 8; nt++) {
            float p0 = S[nt][0], p1 = S[nt][1], p2 = S[nt][2], p3 = S[nt][3];
            Phi[nt][0] = pack_bf2(p0, p1);
            Phi[nt][1] = pack_bf2(p2, p3);
            Plo[nt][0] = pack_bf2(p0 - bf_round(p0), p1 - bf_round(p1));
            Plo[nt][1] = pack_bf2(p2 - bf_round(p2), p3 - bf_round(p3));
        }

        // ---- O += P @ V (3 passes; P_lo/V_lo errors don't average out) ----
        #pragma unroll
        for (int kk = 0; kk < 4; kk++) {
            unsigned aPh[4] = {Phi[2 * kk][0], Phi[2 * kk][1],
                               Phi[2 * kk + 1][0], Phi[2 * kk + 1][1]};
            unsigned aPl[4] = {Plo[2 * kk][0], Plo[2 * kk][1],
                               Plo[2 * kk + 1][0], Plo[2 * kk + 1][1]};
            unsigned fVh[8][2], fVl[8][2];
            #pragma unroll
            for (int nt2 = 0; nt2 < 4; nt2++) {
                unsigned r4[4];
                uint32_t off = (uint32_t)(vb_row + kk * 16) * (APAD * 2) + vb_cb + nt2 * 32;
                ldm_x4t(r4, sVh + off);
                fVh[nt2 * 2 + 0][0] = r4[0]; fVh[nt2 * 2 + 0][1] = r4[1];
                fVh[nt2 * 2 + 1][0] = r4[2]; fVh[nt2 * 2 + 1][1] = r4[3];
                ldm_x4t(r4, sVl + off);
                fVl[nt2 * 2 + 0][0] = r4[0]; fVl[nt2 * 2 + 0][1] = r4[1];
                fVl[nt2 * 2 + 1][0] = r4[2]; fVl[nt2 * 2 + 1][1] = r4[3];
            }
            #pragma unroll
            for (int nt = 0; nt < 8; nt++) {
                mma_bf16(O[nt], aPh, fVh[nt]);
                mma_bf16(O[nt], aPh, fVl[nt]);
                mma_bf16(O[nt], aPl, fVh[nt]);
            }
        }
        __syncthreads();
    }

    // ---- finalize & store ----
    float inv0 = 1.0f / l0, inv1 = 1.0f / l1;
    int row0 = b * NN + qt * 64 + warp * 16 + quad;
    #pragma unroll
    for (int nt = 0; nt < 8; nt++) {
        int col = h * HD + nt * 8 + tq * 2;
        *reinterpret_cast<float2*>(out + (size_t)row0 * CC + col) =
            make_float2(O[nt][0] * inv0, O[nt][1] * inv0);
        *reinterpret_cast<float2*>(out + (size_t)(row0 + 8) * CC + col) =
            make_float2(O[nt][2] * inv1, O[nt][3] * inv1);
    }
}

// ---------------------------------------------------------------------------
extern "C" void kernel_launch(void* const* d_in, const int* in_sizes, int n_in,
                              void* d_out, int out_size) {
    const float* x      = (const float*)d_in[0];
    const float* ln1_g  = (const float*)d_in[1];
    const float* ln1_b  = (const float*)d_in[2];
    const float* w_qk   = (const float*)d_in[3];
    const float* w_v    = (const float*)d_in[4];
    const float* ln2_g  = (const float*)d_in[5];
    const float* ln2_b  = (const float*)d_in[6];
    const float* w_proj = (const float*)d_in[7];
    const float* b_proj = (const float*)d_in[8];
    float* out = (float*)d_out;

    float* ao;
    f16* qkh;
    bf16 *xh, *xl, *vhp, *vlp, *wqkh, *wqkl, *wvh, *wvl, *wph, *wpl;
    cudaGetSymbolAddress((void**)&ao,   g_ao);
    cudaGetSymbolAddress((void**)&xh,   g_xh);
    cudaGetSymbolAddress((void**)&xl,   g_xl);
    cudaGetSymbolAddress((void**)&qkh,  g_qkh);
    cudaGetSymbolAddress((void**)&vhp,  g_vh);
    cudaGetSymbolAddress((void**)&vlp,  g_vl);
    cudaGetSymbolAddress((void**)&wqkh, g_wqkT_h);
    cudaGetSymbolAddress((void**)&wqkl, g_wqkT_l);
    cudaGetSymbolAddress((void**)&wvh,  g_wvT_h);
    cudaGetSymbolAddress((void**)&wvl,  g_wvT_l);
    cudaGetSymbolAddress((void**)&wph,  g_wpT_h);
    cudaGetSymbolAddress((void**)&wpl,  g_wpT_l);

    cudaFuncSetAttribute(attn_mma, cudaFuncAttributeMaxDynamicSharedMemorySize, ASMEM);

    // weight transpose+split
    wsplit_kernel<<<dim3(2 * CC / 32, CC / 32), dim3(32, 8)>>>(w_qk, wqkh, wqkl, CC, 2 * CC);
    wsplit_kernel<<<dim3(CC / 32, CC / 32), dim3(32, 8)>>>(w_v, wvh, wvl, CC, CC);
    wsplit_kernel<<<dim3(CC / 32, CC / 32), dim3(32, 8)>>>(w_proj, wph, wpl, CC, CC);

    // 1. LN1 -> bf16 hi/lo
    ln_split_kernel<<<MM, 256>>>(x, ln1_g, ln1_b, xh, xl);

    // 2. projections: qk -> fp16 (q pre-scaled 0.125); v -> bf16 hi/lo
    gemm_mma<2><<<dim3(2 * CC / 128, MM / 128), 256>>>(
        xh, xl, wqkh, wqkl, nullptr, nullptr,
        reinterpret_cast<bf16*>(qkh), nullptr, MM, 2 * CC, CC, CC);
    gemm_mma<1><<<dim3(CC / 128, MM / 128), 256>>>(
        xh, xl, wvh, wvl, nullptr, nullptr, vhp, vlp, MM, CC, CC, 0);

    // 3. tensor-core flash attention (1-pass fp16 QK)
    attn_mma<<<dim3(NN / 64, HH, BB), 128, ASMEM>>>(qkh, vhp, vlp, ao);

    // 4. LN2 -> bf16 hi/lo
    ln_split_kernel<<<MM, 256>>>(ao, ln2_g, ln2_b, xh, xl);

    // 5. output projection + bias (fp32 out)
    gemm_mma<0><<<dim3(CC / 128, MM / 128), 256>>>(
        xh, xl, wph, wpl, b_proj, out, nullptr, nullptr, MM, CC, CC, 0);
}

// round 10
// speedup vs baseline: 1.5522x; 1.1621x over previous
#include <cuda_runtime.h>
#include <cuda_bf16.h>
#include <cuda_fp16.h>
#include <cstdint>

// Problem constants (fixed shapes)
#define BB 2
#define NN 2048
#define CC 1024
#define HH 16
#define HD 64
#define MM (BB * NN)   // 4096 rows

typedef __nv_bfloat16 bf16;
typedef __half f16;

// ---------------------------------------------------------------------------
// Scratch (device globals — no allocations allowed)
// ---------------------------------------------------------------------------
__device__ float g_ao[MM * CC];
__device__ bf16 g_xh[MM * CC], g_xl[MM * CC];
__device__ f16 g_qkh[MM * 2 * CC];             // q|k in fp16 (1-pass fp16 QK)
__device__ f16 g_v[MM * CC];                   // v in fp16 (1-pass fp16 PV)
__device__ bf16 g_wqkT_h[2 * CC * CC], g_wqkT_l[2 * CC * CC];
__device__ bf16 g_wvT_h[CC * CC], g_wvT_l[CC * CC];
__device__ bf16 g_wpT_h[CC * CC], g_wpT_l[CC * CC];

// ---------------------------------------------------------------------------
// helpers
// ---------------------------------------------------------------------------
__device__ __forceinline__ uint32_t smem_u32(const void* p) {
    uint32_t a;
    asm("{ .reg .u64 t; cvta.to.shared.u64 t, %1; cvt.u32.u64 %0, t; }"
        : "=r"(a) : "l"(p));
    return a;
}

__device__ __forceinline__ void mma_bf16(float* c, const unsigned* a, const unsigned* b) {
    asm volatile(
        "mma.sync.aligned.m16n8k16.row.col.f32.bf16.bf16.f32 "
        "{%0,%1,%2,%3}, {%4,%5,%6,%7}, {%8,%9}, {%0,%1,%2,%3};"
        : "+f"(c[0]), "+f"(c[1]), "+f"(c[2]), "+f"(c[3])
        : "r"(a[0]), "r"(a[1]), "r"(a[2]), "r"(a[3]), "r"(b[0]), "r"(b[1]));
}
__device__ __forceinline__ void mma_f16(float* c, const unsigned* a, const unsigned* b) {
    asm volatile(
        "mma.sync.aligned.m16n8k16.row.col.f32.f16.f16.f32 "
        "{%0,%1,%2,%3}, {%4,%5,%6,%7}, {%8,%9}, {%0,%1,%2,%3};"
        : "+f"(c[0]), "+f"(c[1]), "+f"(c[2]), "+f"(c[3])
        : "r"(a[0]), "r"(a[1]), "r"(a[2]), "r"(a[3]), "r"(b[0]), "r"(b[1]));
}

__device__ __forceinline__ void ldm_x4(unsigned* r, uint32_t addr) {
    asm volatile("ldmatrix.sync.aligned.m8n8.x4.shared.b16 {%0,%1,%2,%3}, [%4];"
        : "=r"(r[0]), "=r"(r[1]), "=r"(r[2]), "=r"(r[3]) : "r"(addr));
}
__device__ __forceinline__ void ldm_x4t(unsigned* r, uint32_t addr) {
    asm volatile("ldmatrix.sync.aligned.m8n8.x4.trans.shared.b16 {%0,%1,%2,%3}, [%4];"
        : "=r"(r[0]), "=r"(r[1]), "=r"(r[2]), "=r"(r[3]) : "r"(addr));
}

// cp.async 16B global -> shared (attention K/V only)
__device__ __forceinline__ void cp16(uint32_t dst, const void* src) {
    asm volatile("cp.async.cg.shared.global [%0], [%1], 16;"
        :: "r"(dst), "l"(__cvta_generic_to_global(src)) : "memory");
}
#define CP_COMMIT() asm volatile("cp.async.commit_group;" ::: "memory")
#define CP_WAIT1()  asm volatile("cp.async.wait_group 1;" ::: "memory")
#define CP_WAIT0()  asm volatile("cp.async.wait_group 0;" ::: "memory")

// pack two f32 -> bf16x2 / f16x2 register (lo = first arg)
__device__ __forceinline__ unsigned pack_bf2(float lo, float hi) {
    unsigned r;
    asm("cvt.rn.bf16x2.f32 %0, %1, %2;" : "=r"(r) : "f"(hi), "f"(lo));
    return r;
}
__device__ __forceinline__ unsigned pack_f162(float lo, float hi) {
    unsigned r;
    asm("cvt.rn.f16x2.f32 %0, %1, %2;" : "=r"(r) : "f"(hi), "f"(lo));
    return r;
}
__device__ __forceinline__ float bf_round(float x) {
    return __bfloat162float(__float2bfloat16(x));
}

// ---------------------------------------------------------------------------
// LayerNorm -> bf16 hi/lo split output
// ---------------------------------------------------------------------------
__global__ void ln_split_kernel(const float* __restrict__ x,
                                const float* __restrict__ g,
                                const float* __restrict__ b,
                                bf16* __restrict__ oh,
                                bf16* __restrict__ ol) {
    int row = blockIdx.x;
    int t = threadIdx.x;
    const float4* xr = reinterpret_cast<const float4*>(x + (size_t)row * CC);
    float4 v = xr[t];
    float s  = v.x + v.y + v.z + v.w;
    float ss = v.x * v.x + v.y * v.y + v.z * v.z + v.w * v.w;

    #pragma unroll
    for (int o = 16; o > 0; o >>= 1) {
        s  += __shfl_down_sync(0xFFFFFFFFu, s,  o);
        ss += __shfl_down_sync(0xFFFFFFFFu, ss, o);
    }
    __shared__ float sh[8][2];
    int w = t >> 5, l = t & 31;
    if (l == 0) { sh[w][0] = s; sh[w][1] = ss; }
    __syncthreads();
    if (w == 0) {
        s  = (l < 8) ? sh[l][0] : 0.0f;
        ss = (l < 8) ? sh[l][1] : 0.0f;
        #pragma unroll
        for (int o = 4; o > 0; o >>= 1) {
            s  += __shfl_down_sync(0xFFFFFFFFu, s,  o);
            ss += __shfl_down_sync(0xFFFFFFFFu, ss, o);
        }
        if (l == 0) { sh[0][0] = s; sh[0][1] = ss; }
    }
    __syncthreads();
    s = sh[0][0]; ss = sh[0][1];

    float mu  = s * (1.0f / CC);
    float var = ss * (1.0f / CC) - mu * mu;
    float inv = rsqrtf(var + 1e-5f);

    const float4 gv = reinterpret_cast<const float4*>(g)[t];
    const float4 bv = reinterpret_cast<const float4*>(b)[t];
    float o0 = (v.x - mu) * inv * gv.x + bv.x;
    float o1 = (v.y - mu) * inv * gv.y + bv.y;
    float o2 = (v.z - mu) * inv * gv.z + bv.z;
    float o3 = (v.w - mu) * inv * gv.w + bv.w;

    unsigned h01 = pack_bf2(o0, o1), h23 = pack_bf2(o2, o3);
    unsigned l01 = pack_bf2(o0 - bf_round(o0), o1 - bf_round(o1));
    unsigned l23 = pack_bf2(o2 - bf_round(o2), o3 - bf_round(o3));
    uint2* hp = reinterpret_cast<uint2*>(oh + (size_t)row * CC + t * 4);
    uint2* lp = reinterpret_cast<uint2*>(ol + (size_t)row * CC + t * 4);
    *hp = make_uint2(h01, h23);
    *lp = make_uint2(l01, l23);
}

// ---------------------------------------------------------------------------
// Transpose + split: w[K][N] fp32 -> wT_hi/lo[N][K] bf16
// ---------------------------------------------------------------------------
__global__ void wsplit_kernel(const float* __restrict__ w,
                              bf16* __restrict__ th,
                              bf16* __restrict__ tl,
                              int K, int N) {
    __shared__ float t[32][33];
    int bx = blockIdx.x, by = blockIdx.y;
    int x = bx * 32 + threadIdx.x;
    #pragma unroll
    for (int j = 0; j < 32; j += 8)
        t[threadIdx.y + j][threadIdx.x] = w[(size_t)(by * 32 + threadIdx.y + j) * N + x];
    __syncthreads();
    int n = bx * 32 + threadIdx.y;
    int k = by * 32 + threadIdx.x;
    #pragma unroll
    for (int j = 0; j < 32; j += 8) {
        float v = t[threadIdx.x][threadIdx.y + j];
        bf16 h = __float2bfloat16(v);
        th[(size_t)(n + j) * K + k] = h;
        tl[(size_t)(n + j) * K + k] = __float2bfloat16(v - __bfloat162float(h));
    }
}

// ---------------------------------------------------------------------------
// mma.sync bf16x3 GEMM (register-prefetch, double-buffered; proven fastest).
// MODE 0: fp32 out (+bias). MODE 1: bf16 hi/lo out. MODE 2: fp16 out,
// cols<qcols scaled x0.125 (q pre-scale; exact exponent shift).
// CTA 128x128 tile, 8 warps (2x4), warp 64x32, K chunk 16.
// ---------------------------------------------------------------------------
#define KC 16
#define PAD 24

template <int MODE>
__global__ void __launch_bounds__(256)
gemm_mma(const bf16* __restrict__ Ah, const bf16* __restrict__ Al,
         const bf16* __restrict__ Bh, const bf16* __restrict__ Bl,
         const float* __restrict__ bias, float* __restrict__ C,
         bf16* __restrict__ Ch, bf16* __restrict__ Cl,
         int M, int N, int K, int qcols) {
    __shared__ bf16 sAh[2][128 * PAD];
    __shared__ bf16 sAl[2][128 * PAD];
    __shared__ bf16 sBh[2][128 * PAD];
    __shared__ bf16 sBl[2][128 * PAD];

    int tid = threadIdx.x;
    int warp = tid >> 5, lane = tid & 31;
    int wm = warp >> 2, wn = warp & 3;
    int m0 = blockIdx.y * 128, n0 = blockIdx.x * 128;

    int lr = tid >> 1;
    int lk = (tid & 1) * 8;
    const bf16* gAh = Ah + (size_t)(m0 + lr) * K + lk;
    const bf16* gAl = Al + (size_t)(m0 + lr) * K + lk;
    const bf16* gBh = Bh + (size_t)(n0 + lr) * K + lk;
    const bf16* gBl = Bl + (size_t)(n0 + lr) * K + lk;
    int so = lr * PAD + lk;

    float acc[4][4][4];
    #pragma unroll
    for (int i = 0; i < 4; i++)
        #pragma unroll
        for (int j = 0; j < 4; j++)
            #pragma unroll
            for (int q = 0; q < 4; q++) acc[i][j][q] = 0.0f;

    int a_row = wm * 64 + (lane & 15);
    int a_cb  = ((lane >> 4) & 1) * 16;
    int b_row = wn * 32 + ((lane >> 4) & 1) * 8 + (lane & 7);
    int b_cb  = ((lane >> 3) & 1) * 16;

    uint4 ra = *reinterpret_cast<const uint4*>(gAh);
    uint4 rb = *reinterpret_cast<const uint4*>(gAl);
    uint4 rc = *reinterpret_cast<const uint4*>(gBh);
    uint4 rd = *reinterpret_cast<const uint4*>(gBl);
    *reinterpret_cast<uint4*>(&sAh[0][so]) = ra;
    *reinterpret_cast<uint4*>(&sAl[0][so]) = rb;
    *reinterpret_cast<uint4*>(&sBh[0][so]) = rc;
    *reinterpret_cast<uint4*>(&sBl[0][so]) = rd;
    __syncthreads();

    int nch = K / KC;
    #pragma unroll 1
    for (int c = 0; c < nch; c++) {
        int cur = c & 1;
        if (c + 1 < nch) {
            ra = *reinterpret_cast<const uint4*>(gAh + (c + 1) * KC);
            rb = *reinterpret_cast<const uint4*>(gAl + (c + 1) * KC);
            rc = *reinterpret_cast<const uint4*>(gBh + (c + 1) * KC);
            rd = *reinterpret_cast<const uint4*>(gBl + (c + 1) * KC);
        }

        uint32_t baseAh = smem_u32(&sAh[cur][0]);
        uint32_t baseAl = smem_u32(&sAl[cur][0]);
        uint32_t baseBh = smem_u32(&sBh[cur][0]);
        uint32_t baseBl = smem_u32(&sBl[cur][0]);

        unsigned fA[4][4], fBh[4][2], fBl[4][2];
        #pragma unroll
        for (int np = 0; np < 2; np++) {
            unsigned r4[4];
            uint32_t ab = baseBh + (uint32_t)(b_row + np * 16) * (PAD * 2) + b_cb;
            ldm_x4(r4, ab);
            fBh[np * 2 + 0][0] = r4[0]; fBh[np * 2 + 0][1] = r4[1];
            fBh[np * 2 + 1][0] = r4[2]; fBh[np * 2 + 1][1] = r4[3];
            ab = baseBl + (uint32_t)(b_row + np * 16) * (PAD * 2) + b_cb;
            ldm_x4(r4, ab);
            fBl[np * 2 + 0][0] = r4[0]; fBl[np * 2 + 0][1] = r4[1];
            fBl[np * 2 + 1][0] = r4[2]; fBl[np * 2 + 1][1] = r4[3];
        }
        #pragma unroll
        for (int mt = 0; mt < 4; mt++)
            ldm_x4(fA[mt], baseAh + (uint32_t)(a_row + mt * 16) * (PAD * 2) + a_cb);
        #pragma unroll
        for (int mt = 0; mt < 4; mt++)
            #pragma unroll
            for (int nt = 0; nt < 4; nt++)
                mma_bf16(acc[mt][nt], fA[mt], fBh[nt]);
        #pragma unroll
        for (int mt = 0; mt < 4; mt++)
            #pragma unroll
            for (int nt = 0; nt < 4; nt++)
                mma_bf16(acc[mt][nt], fA[mt], fBl[nt]);
        #pragma unroll
        for (int mt = 0; mt < 4; mt++)
            ldm_x4(fA[mt], baseAl + (uint32_t)(a_row + mt * 16) * (PAD * 2) + a_cb);
        #pragma unroll
        for (int mt = 0; mt < 4; mt++)
            #pragma unroll
            for (int nt = 0; nt < 4; nt++)
                mma_bf16(acc[mt][nt], fA[mt], fBh[nt]);

        if (c + 1 < nch) {
            int nxt = cur ^ 1;
            *reinterpret_cast<uint4*>(&sAh[nxt][so]) = ra;
            *reinterpret_cast<uint4*>(&sAl[nxt][so]) = rb;
            *reinterpret_cast<uint4*>(&sBh[nxt][so]) = rc;
            *reinterpret_cast<uint4*>(&sBl[nxt][so]) = rd;
        }
        __syncthreads();
    }

    // epilogue
    #pragma unroll
    for (int mt = 0; mt < 4; mt++) {
        int row = m0 + wm * 64 + mt * 16 + (lane >> 2);
        #pragma unroll
        for (int nt = 0; nt < 4; nt++) {
            int col = n0 + wn * 32 + nt * 8 + (lane & 3) * 2;
            if (MODE == 2) {
                float sc = (col < qcols) ? 0.125f : 1.0f;
                #pragma unroll
                for (int half = 0; half < 2; half++) {
                    int rr = row + half * 8;
                    float v0 = acc[mt][nt][half * 2 + 0] * sc;
                    float v1 = acc[mt][nt][half * 2 + 1] * sc;
                    *reinterpret_cast<unsigned*>(Ch + (size_t)rr * N + col) = pack_f162(v0, v1);
                }
            } else if (MODE == 1) {
                #pragma unroll
                for (int half = 0; half < 2; half++) {
                    int rr = row + half * 8;
                    float v0 = acc[mt][nt][half * 2 + 0];
                    float v1 = acc[mt][nt][half * 2 + 1];
                    unsigned hp = pack_bf2(v0, v1);
                    unsigned lp = pack_bf2(v0 - bf_round(v0), v1 - bf_round(v1));
                    *reinterpret_cast<unsigned*>(Ch + (size_t)rr * N + col) = hp;
                    *reinterpret_cast<unsigned*>(Cl + (size_t)rr * N + col) = lp;
                }
            } else {
                float bx = bias[col], by = bias[col + 1];
                float2 r0 = make_float2(acc[mt][nt][0] + bx, acc[mt][nt][1] + by);
                float2 r1 = make_float2(acc[mt][nt][2] + bx, acc[mt][nt][3] + by);
                *reinterpret_cast<float2*>(C + (size_t)row * N + col) = r0;
                *reinterpret_cast<float2*>(C + (size_t)(row + 8) * N + col) = r1;
            }
        }
    }
}

// ---------------------------------------------------------------------------
// Flash attention on tensor cores — all-fp16 operands, fp32 accumulate.
// 1-pass fp16 QK (measured 2.72e-4) + 1-pass fp16 PV (predicted +2.7e-4 in
// quadrature -> ~3.9e-4 total). BQ=64 (4 warps x 16 rows), 128 threads.
// K/V double-buffered via cp.async. Q pre-scaled by 0.125.
// ---------------------------------------------------------------------------
#define APAD 72
#define KVB (2 * 64 * APAD)      // elems per K/V buffer (K | V)
#define ASMEM (2 * KVB * 2)      // bytes (36864)

__global__ void __launch_bounds__(128)
attn_mma(const f16* __restrict__ qkh, const f16* __restrict__ vp,
         float* __restrict__ out) {
    extern __shared__ f16 sm[];
    const uint32_t sb = smem_u32(sm);

    int qt = blockIdx.x, h = blockIdx.y, b = blockIdx.z;
    int tid = threadIdx.x, warp = tid >> 5, lane = tid & 31;
    int quad = lane >> 2, tq = lane & 3;

    // --- stage Q (fp16, 64 rows) in buf0 region; build persistent frags ---
    for (int i = tid; i < 64 * 8; i += 128) {
        int r = i >> 3, c8 = (i & 7) * 8;
        size_t grow = (size_t)(b * NN + qt * 64 + r) * (2 * CC) + h * HD + c8;
        *reinterpret_cast<uint4*>(&sm[r * APAD + c8]) =
            *reinterpret_cast<const uint4*>(qkh + grow);
    }
    __syncthreads();
    unsigned fQh[4][4];
    {
        int ar = warp * 16 + (lane & 15);
        int cb = ((lane >> 4) & 1) * 16;
        #pragma unroll
        for (int kk = 0; kk < 4; kk++)
            ldm_x4(fQh[kk], sb + (uint32_t)(ar * APAD) * 2 + kk * 32 + cb);
    }
    __syncthreads();

    float O[8][4];
    #pragma unroll
    for (int nt = 0; nt < 8; nt++)
        #pragma unroll
        for (int q = 0; q < 4; q++) O[nt][q] = 0.0f;
    float m0 = -1e30f, m1 = -1e30f, l0 = 0.0f, l1 = 0.0f;

    // cp.async addressing: thread covers rows (tid>>3)+{0,16,32,48}, col (tid&7)*8
    int krow = tid >> 3, kcol = (tid & 7) * 8;

    // B-frag ldmatrix lane addressing
    int kb_row = ((lane >> 4) & 1) * 8 + (lane & 7);
    int kb_cb  = ((lane >> 3) & 1) * 16;
    int vb_row = ((lane >> 3) & 1) * 8 + (lane & 7);
    int vb_cb  = ((lane >> 4) & 1) * 16;

    auto kv_issue = [&](int it, int buf) {
        uint32_t base = sb + (uint32_t)buf * (KVB * 2);
        #pragma unroll
        for (int rr = 0; rr < 64; rr += 16) {
            int r = krow + rr;
            size_t gk = (size_t)(b * NN + it * 64 + r) * (2 * CC) + CC + h * HD + kcol;
            size_t gv = (size_t)(b * NN + it * 64 + r) * CC + h * HD + kcol;
            cp16(base + (uint32_t)(0 * 64 * APAD + r * APAD + kcol) * 2, qkh + gk);
            cp16(base + (uint32_t)(1 * 64 * APAD + r * APAD + kcol) * 2, vp + gv);
        }
        CP_COMMIT();
    };

    kv_issue(0, 0);

    const int NIT = NN / 64;
    #pragma unroll 1
    for (int it = 0; it < NIT; it++) {
        int cur = it & 1;
        if (it + 1 < NIT) {
            kv_issue(it + 1, cur ^ 1);
            CP_WAIT1();
        } else {
            CP_WAIT0();
        }
        __syncthreads();

        uint32_t base = sb + (uint32_t)cur * (KVB * 2);
        uint32_t sKh = base;
        uint32_t sVh = base + 1 * 64 * APAD * 2;

        // ---- S = Q @ K^T (1 pass, fp16) ----
        float S[8][4];
        #pragma unroll
        for (int nt = 0; nt < 8; nt++)
            #pragma unroll
            for (int q = 0; q < 4; q++) S[nt][q] = 0.0f;

        #pragma unroll
        for (int kk = 0; kk < 4; kk++) {
            unsigned fKh[8][2];
            #pragma unroll
            for (int np = 0; np < 4; np++) {
                unsigned r4[4];
                uint32_t off = (uint32_t)(kb_row + np * 16) * (APAD * 2) + kb_cb + kk * 32;
                ldm_x4(r4, sKh + off);
                fKh[np * 2 + 0][0] = r4[0]; fKh[np * 2 + 0][1] = r4[1];
                fKh[np * 2 + 1][0] = r4[2]; fKh[np * 2 + 1][1] = r4[3];
            }
            #pragma unroll
            for (int nt = 0; nt < 8; nt++)
                mma_f16(S[nt], fQh[kk], fKh[nt]);
        }

        // ---- online softmax in registers ----
        float mx0 = -1e30f, mx1 = -1e30f;
        #pragma unroll
        for (int nt = 0; nt < 8; nt++) {
            mx0 = fmaxf(mx0, fmaxf(S[nt][0], S[nt][1]));
            mx1 = fmaxf(mx1, fmaxf(S[nt][2], S[nt][3]));
        }
        mx0 = fmaxf(mx0, __shfl_xor_sync(0xFFFFFFFFu, mx0, 1));
        mx0 = fmaxf(mx0, __shfl_xor_sync(0xFFFFFFFFu, mx0, 2));
        mx1 = fmaxf(mx1, __shfl_xor_sync(0xFFFFFFFFu, mx1, 1));
        mx1 = fmaxf(mx1, __shfl_xor_sync(0xFFFFFFFFu, mx1, 2));
        float mn0 = fmaxf(m0, mx0), mn1 = fmaxf(m1, mx1);
        float al0 = __expf(m0 - mn0), al1 = __expf(m1 - mn1);
        m0 = mn0; m1 = mn1;

        float s0 = 0.0f, s1 = 0.0f;
        #pragma unroll
        for (int nt = 0; nt < 8; nt++) {
            S[nt][0] = __expf(S[nt][0] - mn0); s0 += S[nt][0];
            S[nt][1] = __expf(S[nt][1] - mn0); s0 += S[nt][1];
            S[nt][2] = __expf(S[nt][2] - mn1); s1 += S[nt][2];
            S[nt][3] = __expf(S[nt][3] - mn1); s1 += S[nt][3];
        }
        s0 += __shfl_xor_sync(0xFFFFFFFFu, s0, 1);
        s0 += __shfl_xor_sync(0xFFFFFFFFu, s0, 2);
        s1 += __shfl_xor_sync(0xFFFFFFFFu, s1, 1);
        s1 += __shfl_xor_sync(0xFFFFFFFFu, s1, 2);
        l0 = l0 * al0 + s0;
        l1 = l1 * al1 + s1;

        // rescale O
        #pragma unroll
        for (int nt = 0; nt < 8; nt++) {
            O[nt][0] *= al0; O[nt][1] *= al0;
            O[nt][2] *= al1; O[nt][3] *= al1;
        }

        // pack P -> fp16 (C-frag -> A-frag identity)
        unsigned Phi[8][2];
        #pragma unroll
        for (int nt = 0; nt < 8; nt++) {
            Phi[nt][0] = pack_f162(S[nt][0], S[nt][1]);
            Phi[nt][1] = pack_f162(S[nt][2], S[nt][3]);
        }

        // ---- O += P @ V (1 pass, fp16) ----
        #pragma unroll
        for (int kk = 0; kk < 4; kk++) {
            unsigned aPh[4] = {Phi[2 * kk][0], Phi[2 * kk][1],
                               Phi[2 * kk + 1][0], Phi[2 * kk + 1][1]};
            unsigned fVh[8][2];
            #pragma unroll
            for (int nt2 = 0; nt2 < 4; nt2++) {
                unsigned r4[4];
                uint32_t off = (uint32_t)(vb_row + kk * 16) * (APAD * 2) + vb_cb + nt2 * 32;
                ldm_x4t(r4, sVh + off);
                fVh[nt2 * 2 + 0][0] = r4[0]; fVh[nt2 * 2 + 0][1] = r4[1];
                fVh[nt2 * 2 + 1][0] = r4[2]; fVh[nt2 * 2 + 1][1] = r4[3];
            }
            #pragma unroll
            for (int nt = 0; nt < 8; nt++)
                mma_f16(O[nt], aPh, fVh[nt]);
        }
        __syncthreads();
    }

    // ---- finalize & store ----
    float inv0 = 1.0f / l0, inv1 = 1.0f / l1;
    int row0 = b * NN + qt * 64 + warp * 16 + quad;
    #pragma unroll
    for (int nt = 0; nt < 8; nt++) {
        int col = h * HD + nt * 8 + tq * 2;
        *reinterpret_cast<float2*>(out + (size_t)row0 * CC + col) =
            make_float2(O[nt][0] * inv0, O[nt][1] * inv0);
        *reinterpret_cast<float2*>(out + (size_t)(row0 + 8) * CC + col) =
            make_float2(O[nt][2] * inv1, O[nt][3] * inv1);
    }
}

// ---------------------------------------------------------------------------
extern "C" void kernel_launch(void* const* d_in, const int* in_sizes, int n_in,
                              void* d_out, int out_size) {
    const float* x      = (const float*)d_in[0];
    const float* ln1_g  = (const float*)d_in[1];
    const float* ln1_b  = (const float*)d_in[2];
    const float* w_qk   = (const float*)d_in[3];
    const float* w_v    = (const float*)d_in[4];
    const float* ln2_g  = (const float*)d_in[5];
    const float* ln2_b  = (const float*)d_in[6];
    const float* w_proj = (const float*)d_in[7];
    const float* b_proj = (const float*)d_in[8];
    float* out = (float*)d_out;

    float* ao;
    f16 *qkh, *vp;
    bf16 *xh, *xl, *wqkh, *wqkl, *wvh, *wvl, *wph, *wpl;
    cudaGetSymbolAddress((void**)&ao,   g_ao);
    cudaGetSymbolAddress((void**)&xh,   g_xh);
    cudaGetSymbolAddress((void**)&xl,   g_xl);
    cudaGetSymbolAddress((void**)&qkh,  g_qkh);
    cudaGetSymbolAddress((void**)&vp,   g_v);
    cudaGetSymbolAddress((void**)&wqkh, g_wqkT_h);
    cudaGetSymbolAddress((void**)&wqkl, g_wqkT_l);
    cudaGetSymbolAddress((void**)&wvh,  g_wvT_h);
    cudaGetSymbolAddress((void**)&wvl,  g_wvT_l);
    cudaGetSymbolAddress((void**)&wph,  g_wpT_h);
    cudaGetSymbolAddress((void**)&wpl,  g_wpT_l);

    cudaFuncSetAttribute(attn_mma, cudaFuncAttributeMaxDynamicSharedMemorySize, ASMEM);

    // weight transpose+split
    wsplit_kernel<<<dim3(2 * CC / 32, CC / 32), dim3(32, 8)>>>(w_qk, wqkh, wqkl, CC, 2 * CC);
    wsplit_kernel<<<dim3(CC / 32, CC / 32), dim3(32, 8)>>>(w_v, wvh, wvl, CC, CC);
    wsplit_kernel<<<dim3(CC / 32, CC / 32), dim3(32, 8)>>>(w_proj, wph, wpl, CC, CC);

    // 1. LN1 -> bf16 hi/lo
    ln_split_kernel<<<MM, 256>>>(x, ln1_g, ln1_b, xh, xl);

    // 2. projections: qk -> fp16 (q pre-scaled 0.125); v -> fp16
    gemm_mma<2><<<dim3(2 * CC / 128, MM / 128), 256>>>(
        xh, xl, wqkh, wqkl, nullptr, nullptr,
        reinterpret_cast<bf16*>(qkh), nullptr, MM, 2 * CC, CC, CC);
    gemm_mma<2><<<dim3(CC / 128, MM / 128), 256>>>(
        xh, xl, wvh, wvl, nullptr, nullptr,
        reinterpret_cast<bf16*>(vp), nullptr, MM, CC, CC, 0);

    // 3. tensor-core flash attention (all-fp16 operands, fp32 accum)
    attn_mma<<<dim3(NN / 64, HH, BB), 128, ASMEM>>>(qkh, vp, ao);

    // 4. LN2 -> bf16 hi/lo
    ln_split_kernel<<<MM, 256>>>(ao, ln2_g, ln2_b, xh, xl);

    // 5. output projection + bias (fp32 out)
    gemm_mma<0><<<dim3(CC / 128, MM / 128), 256>>>(
        xh, xl, wph, wpl, b_proj, out, nullptr, nullptr, MM, CC, CC, 0);
}

// round 11
// speedup vs baseline: 2.5864x; 1.6663x over previous
#include <cuda_runtime.h>
#include <cuda_bf16.h>
#include <cuda_fp16.h>
#include <cstdint>

// Problem constants (fixed shapes)
#define BB 2
#define NN 2048
#define CC 1024
#define HH 16
#define HD 64
#define MM (BB * NN)   // 4096 rows

typedef __half f16;

// ---------------------------------------------------------------------------
// Scratch (device globals — no allocations allowed)
// ---------------------------------------------------------------------------
__device__ float g_ao[MM * CC];
__device__ f16 g_xf[MM * CC];                  // LN output, fp16
__device__ f16 g_qkh[MM * 2 * CC];             // q|k fp16 (q pre-scaled 0.125)
__device__ f16 g_v[MM * CC];                   // v fp16
__device__ f16 g_wqkT[2 * CC * CC];            // w_qk^T fp16
__device__ f16 g_wvT[CC * CC];                 // w_v^T fp16
__device__ f16 g_wpT[CC * CC];                 // w_proj^T fp16

// ---------------------------------------------------------------------------
// helpers
// ---------------------------------------------------------------------------
__device__ __forceinline__ uint32_t smem_u32(const void* p) {
    uint32_t a;
    asm("{ .reg .u64 t; cvta.to.shared.u64 t, %1; cvt.u32.u64 %0, t; }"
        : "=r"(a) : "l"(p));
    return a;
}

__device__ __forceinline__ void mma_f16(float* c, const unsigned* a, const unsigned* b) {
    asm volatile(
        "mma.sync.aligned.m16n8k16.row.col.f32.f16.f16.f32 "
        "{%0,%1,%2,%3}, {%4,%5,%6,%7}, {%8,%9}, {%0,%1,%2,%3};"
        : "+f"(c[0]), "+f"(c[1]), "+f"(c[2]), "+f"(c[3])
        : "r"(a[0]), "r"(a[1]), "r"(a[2]), "r"(a[3]), "r"(b[0]), "r"(b[1]));
}

__device__ __forceinline__ void ldm_x4(unsigned* r, uint32_t addr) {
    asm volatile("ldmatrix.sync.aligned.m8n8.x4.shared.b16 {%0,%1,%2,%3}, [%4];"
        : "=r"(r[0]), "=r"(r[1]), "=r"(r[2]), "=r"(r[3]) : "r"(addr));
}
__device__ __forceinline__ void ldm_x4t(unsigned* r, uint32_t addr) {
    asm volatile("ldmatrix.sync.aligned.m8n8.x4.trans.shared.b16 {%0,%1,%2,%3}, [%4];"
        : "=r"(r[0]), "=r"(r[1]), "=r"(r[2]), "=r"(r[3]) : "r"(addr));
}

// cp.async 16B global -> shared (attention K/V only)
__device__ __forceinline__ void cp16(uint32_t dst, const void* src) {
    asm volatile("cp.async.cg.shared.global [%0], [%1], 16;"
        :: "r"(dst), "l"(__cvta_generic_to_global(src)) : "memory");
}
#define CP_COMMIT() asm volatile("cp.async.commit_group;" ::: "memory")
#define CP_WAIT1()  asm volatile("cp.async.wait_group 1;" ::: "memory")
#define CP_WAIT0()  asm volatile("cp.async.wait_group 0;" ::: "memory")

// pack two f32 -> f16x2 register (lo = first arg)
__device__ __forceinline__ unsigned pack_f162(float lo, float hi) {
    unsigned r;
    asm("cvt.rn.f16x2.f32 %0, %1, %2;" : "=r"(r) : "f"(hi), "f"(lo));
    return r;
}

// ---------------------------------------------------------------------------
// LayerNorm -> fp16 output
// ---------------------------------------------------------------------------
__global__ void ln_f16_kernel(const float* __restrict__ x,
                              const float* __restrict__ g,
                              const float* __restrict__ b,
                              f16* __restrict__ o) {
    int row = blockIdx.x;
    int t = threadIdx.x;
    const float4* xr = reinterpret_cast<const float4*>(x + (size_t)row * CC);
    float4 v = xr[t];
    float s  = v.x + v.y + v.z + v.w;
    float ss = v.x * v.x + v.y * v.y + v.z * v.z + v.w * v.w;

    #pragma unroll
    for (int of = 16; of > 0; of >>= 1) {
        s  += __shfl_down_sync(0xFFFFFFFFu, s,  of);
        ss += __shfl_down_sync(0xFFFFFFFFu, ss, of);
    }
    __shared__ float sh[8][2];
    int w = t >> 5, l = t & 31;
    if (l == 0) { sh[w][0] = s; sh[w][1] = ss; }
    __syncthreads();
    if (w == 0) {
        s  = (l < 8) ? sh[l][0] : 0.0f;
        ss = (l < 8) ? sh[l][1] : 0.0f;
        #pragma unroll
        for (int of = 4; of > 0; of >>= 1) {
            s  += __shfl_down_sync(0xFFFFFFFFu, s,  of);
            ss += __shfl_down_sync(0xFFFFFFFFu, ss, of);
        }
        if (l == 0) { sh[0][0] = s; sh[0][1] = ss; }
    }
    __syncthreads();
    s = sh[0][0]; ss = sh[0][1];

    float mu  = s * (1.0f / CC);
    float var = ss * (1.0f / CC) - mu * mu;
    float inv = rsqrtf(var + 1e-5f);

    const float4 gv = reinterpret_cast<const float4*>(g)[t];
    const float4 bv = reinterpret_cast<const float4*>(b)[t];
    float o0 = (v.x - mu) * inv * gv.x + bv.x;
    float o1 = (v.y - mu) * inv * gv.y + bv.y;
    float o2 = (v.z - mu) * inv * gv.z + bv.z;
    float o3 = (v.w - mu) * inv * gv.w + bv.w;

    *reinterpret_cast<uint2*>(o + (size_t)row * CC + t * 4) =
        make_uint2(pack_f162(o0, o1), pack_f162(o2, o3));
}

// ---------------------------------------------------------------------------
// Transpose: w[K][N] fp32 -> wT[N][K] fp16
// ---------------------------------------------------------------------------
__global__ void wsplit_f16(const float* __restrict__ w,
                           f16* __restrict__ tOut,
                           int K, int N) {
    __shared__ float t[32][33];
    int bx = blockIdx.x, by = blockIdx.y;
    int x = bx * 32 + threadIdx.x;
    #pragma unroll
    for (int j = 0; j < 32; j += 8)
        t[threadIdx.y + j][threadIdx.x] = w[(size_t)(by * 32 + threadIdx.y + j) * N + x];
    __syncthreads();
    int n = bx * 32 + threadIdx.y;
    int k = by * 32 + threadIdx.x;
    #pragma unroll
    for (int j = 0; j < 32; j += 8)
        tOut[(size_t)(n + j) * K + k] = __float2half(t[threadIdx.x][threadIdx.y + j]);
}

// ---------------------------------------------------------------------------
// 1-pass fp16 GEMM (fp32 accumulate): C[M,N] = A[M,K] @ B[N,K]^T.
// MODE 0: fp32 out (+bias). MODE 2: fp16 out, cols<qcols scaled x0.125.
// CTA 128x128 tile, 8 warps (2x4), warp 64x32. K chunk 32, register-prefetch
// double buffer (proven pattern). Rows padded to 40 f16 (80B): ldmatrix
// 8-row phases hit banks (5r mod 8) — all distinct, conflict-free.
// ---------------------------------------------------------------------------
#define KCG 32
#define PADG 40

template <int MODE>
__global__ void __launch_bounds__(256)
gemm_f16(const f16* __restrict__ A, const f16* __restrict__ B,
         const float* __restrict__ bias, float* __restrict__ C,
         f16* __restrict__ Cf,
         int M, int N, int K, int qcols) {
    __shared__ f16 sA[2][128 * PADG];
    __shared__ f16 sB[2][128 * PADG];

    int tid = threadIdx.x;
    int warp = tid >> 5, lane = tid & 31;
    int wm = warp >> 2, wn = warp & 3;
    int m0 = blockIdx.y * 128, n0 = blockIdx.x * 128;

    // gmem load mapping: 2 uint4 per tensor per thread per chunk
    // idx = p*256 + tid: row = idx>>2 (0..127), c8 = (idx&3)*8 (0..24)
    int lr0 = tid >> 2, lc0 = (tid & 3) * 8;
    int lr1 = (tid + 256) >> 2;
    const f16* gA0 = A + (size_t)(m0 + lr0) * K + lc0;
    const f16* gA1 = A + (size_t)(m0 + lr1) * K + lc0;
    const f16* gB0 = B + (size_t)(n0 + lr0) * K + lc0;
    const f16* gB1 = B + (size_t)(n0 + lr1) * K + lc0;
    int so0 = lr0 * PADG + lc0;
    int so1 = lr1 * PADG + lc0;

    float acc[4][4][4];
    #pragma unroll
    for (int i = 0; i < 4; i++)
        #pragma unroll
        for (int j = 0; j < 4; j++)
            #pragma unroll
            for (int q = 0; q < 4; q++) acc[i][j][q] = 0.0f;

    int a_row = wm * 64 + (lane & 15);
    int a_cb  = ((lane >> 4) & 1) * 16;
    int b_row = wn * 32 + ((lane >> 4) & 1) * 8 + (lane & 7);
    int b_cb  = ((lane >> 3) & 1) * 16;

    // prologue: chunk 0
    uint4 ra0 = *reinterpret_cast<const uint4*>(gA0);
    uint4 ra1 = *reinterpret_cast<const uint4*>(gA1);
    uint4 rb0 = *reinterpret_cast<const uint4*>(gB0);
    uint4 rb1 = *reinterpret_cast<const uint4*>(gB1);
    *reinterpret_cast<uint4*>(&sA[0][so0]) = ra0;
    *reinterpret_cast<uint4*>(&sA[0][so1]) = ra1;
    *reinterpret_cast<uint4*>(&sB[0][so0]) = rb0;
    *reinterpret_cast<uint4*>(&sB[0][so1]) = rb1;
    __syncthreads();

    int nch = K / KCG;
    #pragma unroll 1
    for (int c = 0; c < nch; c++) {
        int cur = c & 1;
        if (c + 1 < nch) {
            ra0 = *reinterpret_cast<const uint4*>(gA0 + (c + 1) * KCG);
            ra1 = *reinterpret_cast<const uint4*>(gA1 + (c + 1) * KCG);
            rb0 = *reinterpret_cast<const uint4*>(gB0 + (c + 1) * KCG);
            rb1 = *reinterpret_cast<const uint4*>(gB1 + (c + 1) * KCG);
        }

        uint32_t baseA = smem_u32(&sA[cur][0]);
        uint32_t baseB = smem_u32(&sB[cur][0]);

        #pragma unroll
        for (int kk = 0; kk < 2; kk++) {
            unsigned fA[4][4], fB[4][2];
            #pragma unroll
            for (int np = 0; np < 2; np++) {
                unsigned r4[4];
                uint32_t ab = baseB + (uint32_t)(b_row + np * 16) * (PADG * 2)
                              + kk * 32 + b_cb;
                ldm_x4(r4, ab);
                fB[np * 2 + 0][0] = r4[0]; fB[np * 2 + 0][1] = r4[1];
                fB[np * 2 + 1][0] = r4[2]; fB[np * 2 + 1][1] = r4[3];
            }
            #pragma unroll
            for (int mt = 0; mt < 4; mt++)
                ldm_x4(fA[mt], baseA + (uint32_t)(a_row + mt * 16) * (PADG * 2)
                                + kk * 32 + a_cb);
            #pragma unroll
            for (int mt = 0; mt < 4; mt++)
                #pragma unroll
                for (int nt = 0; nt < 4; nt++)
                    mma_f16(acc[mt][nt], fA[mt], fB[nt]);
        }

        if (c + 1 < nch) {
            int nxt = cur ^ 1;
            *reinterpret_cast<uint4*>(&sA[nxt][so0]) = ra0;
            *reinterpret_cast<uint4*>(&sA[nxt][so1]) = ra1;
            *reinterpret_cast<uint4*>(&sB[nxt][so0]) = rb0;
            *reinterpret_cast<uint4*>(&sB[nxt][so1]) = rb1;
        }
        __syncthreads();
    }

    // epilogue
    #pragma unroll
    for (int mt = 0; mt < 4; mt++) {
        int row = m0 + wm * 64 + mt * 16 + (lane >> 2);
        #pragma unroll
        for (int nt = 0; nt < 4; nt++) {
            int col = n0 + wn * 32 + nt * 8 + (lane & 3) * 2;
            if (MODE == 2) {
                float sc = (col < qcols) ? 0.125f : 1.0f;
                #pragma unroll
                for (int half = 0; half < 2; half++) {
                    int rr = row + half * 8;
                    float v0 = acc[mt][nt][half * 2 + 0] * sc;
                    float v1 = acc[mt][nt][half * 2 + 1] * sc;
                    *reinterpret_cast<unsigned*>(Cf + (size_t)rr * N + col) =
                        pack_f162(v0, v1);
                }
            } else {
                float bx = bias[col], by = bias[col + 1];
                float2 r0 = make_float2(acc[mt][nt][0] + bx, acc[mt][nt][1] + by);
                float2 r1 = make_float2(acc[mt][nt][2] + bx, acc[mt][nt][3] + by);
                *reinterpret_cast<float2*>(C + (size_t)row * N + col) = r0;
                *reinterpret_cast<float2*>(C + (size_t)(row + 8) * N + col) = r1;
            }
        }
    }
}

// ---------------------------------------------------------------------------
// Flash attention on tensor cores — all-fp16 operands, fp32 accumulate
// (unchanged from R10: 1-pass fp16 QK + 1-pass fp16 PV, measured 3.46e-4).
// BQ=64 (4 warps x 16 rows), 128 threads. K/V double-buffered via cp.async.
// Q pre-scaled by 0.125.
// ---------------------------------------------------------------------------
#define APAD 72
#define KVB (2 * 64 * APAD)      // elems per K/V buffer (K | V)
#define ASMEM (2 * KVB * 2)      // bytes (36864)

__global__ void __launch_bounds__(128)
attn_mma(const f16* __restrict__ qkh, const f16* __restrict__ vp,
         float* __restrict__ out) {
    extern __shared__ f16 sm[];
    const uint32_t sb = smem_u32(sm);

    int qt = blockIdx.x, h = blockIdx.y, b = blockIdx.z;
    int tid = threadIdx.x, warp = tid >> 5, lane = tid & 31;
    int quad = lane >> 2, tq = lane & 3;

    // --- stage Q (fp16, 64 rows) in buf0 region; build persistent frags ---
    for (int i = tid; i < 64 * 8; i += 128) {
        int r = i >> 3, c8 = (i & 7) * 8;
        size_t grow = (size_t)(b * NN + qt * 64 + r) * (2 * CC) + h * HD + c8;
        *reinterpret_cast<uint4*>(&sm[r * APAD + c8]) =
            *reinterpret_cast<const uint4*>(qkh + grow);
    }
    __syncthreads();
    unsigned fQh[4][4];
    {
        int ar = warp * 16 + (lane & 15);
        int cb = ((lane >> 4) & 1) * 16;
        #pragma unroll
        for (int kk = 0; kk < 4; kk++)
            ldm_x4(fQh[kk], sb + (uint32_t)(ar * APAD) * 2 + kk * 32 + cb);
    }
    __syncthreads();

    float O[8][4];
    #pragma unroll
    for (int nt = 0; nt < 8; nt++)
        #pragma unroll
        for (int q = 0; q < 4; q++) O[nt][q] = 0.0f;
    float m0 = -1e30f, m1 = -1e30f, l0 = 0.0f, l1 = 0.0f;

    int krow = tid >> 3, kcol = (tid & 7) * 8;

    int kb_row = ((lane >> 4) & 1) * 8 + (lane & 7);
    int kb_cb  = ((lane >> 3) & 1) * 16;
    int vb_row = ((lane >> 3) & 1) * 8 + (lane & 7);
    int vb_cb  = ((lane >> 4) & 1) * 16;

    auto kv_issue = [&](int it, int buf) {
        uint32_t base = sb + (uint32_t)buf * (KVB * 2);
        #pragma unroll
        for (int rr = 0; rr < 64; rr += 16) {
            int r = krow + rr;
            size_t gk = (size_t)(b * NN + it * 64 + r) * (2 * CC) + CC + h * HD + kcol;
            size_t gv = (size_t)(b * NN + it * 64 + r) * CC + h * HD + kcol;
            cp16(base + (uint32_t)(0 * 64 * APAD + r * APAD + kcol) * 2, qkh + gk);
            cp16(base + (uint32_t)(1 * 64 * APAD + r * APAD + kcol) * 2, vp + gv);
        }
        CP_COMMIT();
    };

    kv_issue(0, 0);

    const int NIT = NN / 64;
    #pragma unroll 1
    for (int it = 0; it < NIT; it++) {
        int cur = it & 1;
        if (it + 1 < NIT) {
            kv_issue(it + 1, cur ^ 1);
            CP_WAIT1();
        } else {
            CP_WAIT0();
        }
        __syncthreads();

        uint32_t base = sb + (uint32_t)cur * (KVB * 2);
        uint32_t sKh = base;
        uint32_t sVh = base + 1 * 64 * APAD * 2;

        // ---- S = Q @ K^T (1 pass, fp16) ----
        float S[8][4];
        #pragma unroll
        for (int nt = 0; nt < 8; nt++)
            #pragma unroll
            for (int q = 0; q < 4; q++) S[nt][q] = 0.0f;

        #pragma unroll
        for (int kk = 0; kk < 4; kk++) {
            unsigned fKh[8][2];
            #pragma unroll
            for (int np = 0; np < 4; np++) {
                unsigned r4[4];
                uint32_t off = (uint32_t)(kb_row + np * 16) * (APAD * 2) + kb_cb + kk * 32;
                ldm_x4(r4, sKh + off);
                fKh[np * 2 + 0][0] = r4[0]; fKh[np * 2 + 0][1] = r4[1];
                fKh[np * 2 + 1][0] = r4[2]; fKh[np * 2 + 1][1] = r4[3];
            }
            #pragma unroll
            for (int nt = 0; nt < 8; nt++)
                mma_f16(S[nt], fQh[kk], fKh[nt]);
        }

        // ---- online softmax in registers ----
        float mx0 = -1e30f, mx1 = -1e30f;
        #pragma unroll
        for (int nt = 0; nt < 8; nt++) {
            mx0 = fmaxf(mx0, fmaxf(S[nt][0], S[nt][1]));
            mx1 = fmaxf(mx1, fmaxf(S[nt][2], S[nt][3]));
        }
        mx0 = fmaxf(mx0, __shfl_xor_sync(0xFFFFFFFFu, mx0, 1));
        mx0 = fmaxf(mx0, __shfl_xor_sync(0xFFFFFFFFu, mx0, 2));
        mx1 = fmaxf(mx1, __shfl_xor_sync(0xFFFFFFFFu, mx1, 1));
        mx1 = fmaxf(mx1, __shfl_xor_sync(0xFFFFFFFFu, mx1, 2));
        float mn0 = fmaxf(m0, mx0), mn1 = fmaxf(m1, mx1);
        float al0 = __expf(m0 - mn0), al1 = __expf(m1 - mn1);
        m0 = mn0; m1 = mn1;

        float s0 = 0.0f, s1 = 0.0f;
        #pragma unroll
        for (int nt = 0; nt < 8; nt++) {
            S[nt][0] = __expf(S[nt][0] - mn0); s0 += S[nt][0];
            S[nt][1] = __expf(S[nt][1] - mn0); s0 += S[nt][1];
            S[nt][2] = __expf(S[nt][2] - mn1); s1 += S[nt][2];
            S[nt][3] = __expf(S[nt][3] - mn1); s1 += S[nt][3];
        }
        s0 += __shfl_xor_sync(0xFFFFFFFFu, s0, 1);
        s0 += __shfl_xor_sync(0xFFFFFFFFu, s0, 2);
        s1 += __shfl_xor_sync(0xFFFFFFFFu, s1, 1);
        s1 += __shfl_xor_sync(0xFFFFFFFFu, s1, 2);
        l0 = l0 * al0 + s0;
        l1 = l1 * al1 + s1;

        #pragma unroll
        for (int nt = 0; nt < 8; nt++) {
            O[nt][0] *= al0; O[nt][1] *= al0;
            O[nt][2] *= al1; O[nt][3] *= al1;
        }

        unsigned Phi[8][2];
        #pragma unroll
        for (int nt = 0; nt < 8; nt++) {
            Phi[nt][0] = pack_f162(S[nt][0], S[nt][1]);
            Phi[nt][1] = pack_f162(S[nt][2], S[nt][3]);
        }

        // ---- O += P @ V (1 pass, fp16) ----
        #pragma unroll
        for (int kk = 0; kk < 4; kk++) {
            unsigned aPh[4] = {Phi[2 * kk][0], Phi[2 * kk][1],
                               Phi[2 * kk + 1][0], Phi[2 * kk + 1][1]};
            unsigned fVh[8][2];
            #pragma unroll
            for (int nt2 = 0; nt2 < 4; nt2++) {
                unsigned r4[4];
                uint32_t off = (uint32_t)(vb_row + kk * 16) * (APAD * 2) + vb_cb + nt2 * 32;
                ldm_x4t(r4, sVh + off);
                fVh[nt2 * 2 + 0][0] = r4[0]; fVh[nt2 * 2 + 0][1] = r4[1];
                fVh[nt2 * 2 + 1][0] = r4[2]; fVh[nt2 * 2 + 1][1] = r4[3];
            }
            #pragma unroll
            for (int nt = 0; nt < 8; nt++)
                mma_f16(O[nt], aPh, fVh[nt]);
        }
        __syncthreads();
    }

    // ---- finalize & store ----
    float inv0 = 1.0f / l0, inv1 = 1.0f / l1;
    int row0 = b * NN + qt * 64 + warp * 16 + quad;
    #pragma unroll
    for (int nt = 0; nt < 8; nt++) {
        int col = h * HD + nt * 8 + tq * 2;
        *reinterpret_cast<float2*>(out + (size_t)row0 * CC + col) =
            make_float2(O[nt][0] * inv0, O[nt][1] * inv0);
        *reinterpret_cast<float2*>(out + (size_t)(row0 + 8) * CC + col) =
            make_float2(O[nt][2] * inv1, O[nt][3] * inv1);
    }
}

// ---------------------------------------------------------------------------
extern "C" void kernel_launch(void* const* d_in, const int* in_sizes, int n_in,
                              void* d_out, int out_size) {
    const float* x      = (const float*)d_in[0];
    const float* ln1_g  = (const float*)d_in[1];
    const float* ln1_b  = (const float*)d_in[2];
    const float* w_qk   = (const float*)d_in[3];
    const float* w_v    = (const float*)d_in[4];
    const float* ln2_g  = (const float*)d_in[5];
    const float* ln2_b  = (const float*)d_in[6];
    const float* w_proj = (const float*)d_in[7];
    const float* b_proj = (const float*)d_in[8];
    float* out = (float*)d_out;

    float* ao;
    f16 *xf, *qkh, *vp, *wqkT, *wvT, *wpT;
    cudaGetSymbolAddress((void**)&ao,   g_ao);
    cudaGetSymbolAddress((void**)&xf,   g_xf);
    cudaGetSymbolAddress((void**)&qkh,  g_qkh);
    cudaGetSymbolAddress((void**)&vp,   g_v);
    cudaGetSymbolAddress((void**)&wqkT, g_wqkT);
    cudaGetSymbolAddress((void**)&wvT,  g_wvT);
    cudaGetSymbolAddress((void**)&wpT,  g_wpT);

    cudaFuncSetAttribute(attn_mma, cudaFuncAttributeMaxDynamicSharedMemorySize, ASMEM);

    // weight transpose -> fp16
    wsplit_f16<<<dim3(2 * CC / 32, CC / 32), dim3(32, 8)>>>(w_qk, wqkT, CC, 2 * CC);
    wsplit_f16<<<dim3(CC / 32, CC / 32), dim3(32, 8)>>>(w_v, wvT, CC, CC);
    wsplit_f16<<<dim3(CC / 32, CC / 32), dim3(32, 8)>>>(w_proj, wpT, CC, CC);

    // 1. LN1 -> fp16
    ln_f16_kernel<<<MM, 256>>>(x, ln1_g, ln1_b, xf);

    // 2. projections (1-pass fp16): qk (q pre-scaled 0.125), v
    gemm_f16<2><<<dim3(2 * CC / 128, MM / 128), 256>>>(
        xf, wqkT, nullptr, nullptr, qkh, MM, 2 * CC, CC, CC);
    gemm_f16<2><<<dim3(CC / 128, MM / 128), 256>>>(
        xf, wvT, nullptr, nullptr, vp, MM, CC, CC, 0);

    // 3. tensor-core flash attention (all-fp16 operands, fp32 accum)
    attn_mma<<<dim3(NN / 64, HH, BB), 128, ASMEM>>>(qkh, vp, ao);

    // 4. LN2 -> fp16
    ln_f16_kernel<<<MM, 256>>>(ao, ln2_g, ln2_b, xf);

    // 5. output projection + bias (1-pass fp16, fp32 out)
    gemm_f16<0><<<dim3(CC / 128, MM / 128), 256>>>(
        xf, wpT, b_proj, out, nullptr, MM, CC, CC, 0);
}

// round 12
// speedup vs baseline: 2.6034x; 1.0065x over previous
#include <cuda_runtime.h>
#include <cuda_bf16.h>
#include <cuda_fp16.h>
#include <cstdint>

// Problem constants (fixed shapes)
#define BB 2
#define NN 2048
#define CC 1024
#define HH 16
#define HD 64
#define MM (BB * NN)   // 4096 rows

typedef __half f16;

// ---------------------------------------------------------------------------
// Scratch (device globals — no allocations allowed)
// ---------------------------------------------------------------------------
__device__ float g_ao[MM * CC];
__device__ f16 g_xf[MM * CC];                  // LN output, fp16
__device__ f16 g_qkh[MM * 2 * CC];             // q|k fp16 (q pre-scaled 0.125)
__device__ f16 g_v[MM * CC];                   // v fp16
__device__ f16 g_wT[3 * CC * CC];              // fused w^T fp16: qk rows [0,2C), v rows [2C,3C)
__device__ f16 g_wpT[CC * CC];                 // w_proj^T fp16

// ---------------------------------------------------------------------------
// helpers
// ---------------------------------------------------------------------------
__device__ __forceinline__ uint32_t smem_u32(const void* p) {
    uint32_t a;
    asm("{ .reg .u64 t; cvta.to.shared.u64 t, %1; cvt.u32.u64 %0, t; }"
        : "=r"(a) : "l"(p));
    return a;
}

__device__ __forceinline__ void mma_f16(float* c, const unsigned* a, const unsigned* b) {
    asm volatile(
        "mma.sync.aligned.m16n8k16.row.col.f32.f16.f16.f32 "
        "{%0,%1,%2,%3}, {%4,%5,%6,%7}, {%8,%9}, {%0,%1,%2,%3};"
        : "+f"(c[0]), "+f"(c[1]), "+f"(c[2]), "+f"(c[3])
        : "r"(a[0]), "r"(a[1]), "r"(a[2]), "r"(a[3]), "r"(b[0]), "r"(b[1]));
}

__device__ __forceinline__ void ldm_x4(unsigned* r, uint32_t addr) {
    asm volatile("ldmatrix.sync.aligned.m8n8.x4.shared.b16 {%0,%1,%2,%3}, [%4];"
        : "=r"(r[0]), "=r"(r[1]), "=r"(r[2]), "=r"(r[3]) : "r"(addr));
}
__device__ __forceinline__ void ldm_x4t(unsigned* r, uint32_t addr) {
    asm volatile("ldmatrix.sync.aligned.m8n8.x4.trans.shared.b16 {%0,%1,%2,%3}, [%4];"
        : "=r"(r[0]), "=r"(r[1]), "=r"(r[2]), "=r"(r[3]) : "r"(addr));
}

// cp.async 16B global -> shared (attention K/V only)
__device__ __forceinline__ void cp16(uint32_t dst, const void* src) {
    asm volatile("cp.async.cg.shared.global [%0], [%1], 16;"
        :: "r"(dst), "l"(__cvta_generic_to_global(src)) : "memory");
}
#define CP_COMMIT() asm volatile("cp.async.commit_group;" ::: "memory")
#define CP_WAIT1()  asm volatile("cp.async.wait_group 1;" ::: "memory")
#define CP_WAIT0()  asm volatile("cp.async.wait_group 0;" ::: "memory")

// pack two f32 -> f16x2 register (lo = first arg)
__device__ __forceinline__ unsigned pack_f162(float lo, float hi) {
    unsigned r;
    asm("cvt.rn.f16x2.f32 %0, %1, %2;" : "=r"(r) : "f"(hi), "f"(lo));
    return r;
}

// ---------------------------------------------------------------------------
// LayerNorm -> fp16 output
// ---------------------------------------------------------------------------
__global__ void ln_f16_kernel(const float* __restrict__ x,
                              const float* __restrict__ g,
                              const float* __restrict__ b,
                              f16* __restrict__ o) {
    int row = blockIdx.x;
    int t = threadIdx.x;
    const float4* xr = reinterpret_cast<const float4*>(x + (size_t)row * CC);
    float4 v = xr[t];
    float s  = v.x + v.y + v.z + v.w;
    float ss = v.x * v.x + v.y * v.y + v.z * v.z + v.w * v.w;

    #pragma unroll
    for (int of = 16; of > 0; of >>= 1) {
        s  += __shfl_down_sync(0xFFFFFFFFu, s,  of);
        ss += __shfl_down_sync(0xFFFFFFFFu, ss, of);
    }
    __shared__ float sh[8][2];
    int w = t >> 5, l = t & 31;
    if (l == 0) { sh[w][0] = s; sh[w][1] = ss; }
    __syncthreads();
    if (w == 0) {
        s  = (l < 8) ? sh[l][0] : 0.0f;
        ss = (l < 8) ? sh[l][1] : 0.0f;
        #pragma unroll
        for (int of = 4; of > 0; of >>= 1) {
            s  += __shfl_down_sync(0xFFFFFFFFu, s,  of);
            ss += __shfl_down_sync(0xFFFFFFFFu, ss, of);
        }
        if (l == 0) { sh[0][0] = s; sh[0][1] = ss; }
    }
    __syncthreads();
    s = sh[0][0]; ss = sh[0][1];

    float mu  = s * (1.0f / CC);
    float var = ss * (1.0f / CC) - mu * mu;
    float inv = rsqrtf(var + 1e-5f);

    const float4 gv = reinterpret_cast<const float4*>(g)[t];
    const float4 bv = reinterpret_cast<const float4*>(b)[t];
    float o0 = (v.x - mu) * inv * gv.x + bv.x;
    float o1 = (v.y - mu) * inv * gv.y + bv.y;
    float o2 = (v.z - mu) * inv * gv.z + bv.z;
    float o3 = (v.w - mu) * inv * gv.w + bv.w;

    *reinterpret_cast<uint2*>(o + (size_t)row * CC + t * 4) =
        make_uint2(pack_f162(o0, o1), pack_f162(o2, o3));
}

// ---------------------------------------------------------------------------
// Transpose: w[K][N] fp32 -> wT[N][K] fp16
// ---------------------------------------------------------------------------
__global__ void wsplit_f16(const float* __restrict__ w,
                           f16* __restrict__ tOut,
                           int K, int N) {
    __shared__ float t[32][33];
    int bx = blockIdx.x, by = blockIdx.y;
    int x = bx * 32 + threadIdx.x;
    #pragma unroll
    for (int j = 0; j < 32; j += 8)
        t[threadIdx.y + j][threadIdx.x] = w[(size_t)(by * 32 + threadIdx.y + j) * N + x];
    __syncthreads();
    int n = bx * 32 + threadIdx.y;
    int k = by * 32 + threadIdx.x;
    #pragma unroll
    for (int j = 0; j < 32; j += 8)
        tOut[(size_t)(n + j) * K + k] = __float2half(t[threadIdx.x][threadIdx.y + j]);
}

// ---------------------------------------------------------------------------
// 1-pass fp16 GEMM (fp32 accumulate): C[M,N] = A[M,K] @ B[N,K]^T.
// MODE 0: fp32 out (+bias). MODE 2: fused qkv epilogue — cols [0,2C) -> Cq
// (x0.125 for cols < C), cols [2C,3C) -> Cv at col-2C.
// CTA 128x128 tile, 8 warps (2x4), warp 64x32. K chunk 32, register-prefetch
// double buffer. __launch_bounds__(256,2) -> regs<=128 -> 2 CTAs/SM.
// ---------------------------------------------------------------------------
#define KCG 32
#define PADG 40

template <int MODE>
__global__ void __launch_bounds__(256, 2)
gemm_f16(const f16* __restrict__ A, const f16* __restrict__ B,
         const float* __restrict__ bias, float* __restrict__ C,
         f16* __restrict__ Cq, f16* __restrict__ Cv,
         int M, int N, int K) {
    __shared__ f16 sA[2][128 * PADG];
    __shared__ f16 sB[2][128 * PADG];

    int tid = threadIdx.x;
    int warp = tid >> 5, lane = tid & 31;
    int wm = warp >> 2, wn = warp & 3;
    int m0 = blockIdx.y * 128, n0 = blockIdx.x * 128;

    int lr0 = tid >> 2, lc0 = (tid & 3) * 8;
    int lr1 = (tid + 256) >> 2;
    const f16* gA0 = A + (size_t)(m0 + lr0) * K + lc0;
    const f16* gA1 = A + (size_t)(m0 + lr1) * K + lc0;
    const f16* gB0 = B + (size_t)(n0 + lr0) * K + lc0;
    const f16* gB1 = B + (size_t)(n0 + lr1) * K + lc0;
    int so0 = lr0 * PADG + lc0;
    int so1 = lr1 * PADG + lc0;

    float acc[4][4][4];
    #pragma unroll
    for (int i = 0; i < 4; i++)
        #pragma unroll
        for (int j = 0; j < 4; j++)
            #pragma unroll
            for (int q = 0; q < 4; q++) acc[i][j][q] = 0.0f;

    int a_row = wm * 64 + (lane & 15);
    int a_cb  = ((lane >> 4) & 1) * 16;
    int b_row = wn * 32 + ((lane >> 4) & 1) * 8 + (lane & 7);
    int b_cb  = ((lane >> 3) & 1) * 16;

    // prologue: chunk 0
    uint4 ra0 = *reinterpret_cast<const uint4*>(gA0);
    uint4 ra1 = *reinterpret_cast<const uint4*>(gA1);
    uint4 rb0 = *reinterpret_cast<const uint4*>(gB0);
    uint4 rb1 = *reinterpret_cast<const uint4*>(gB1);
    *reinterpret_cast<uint4*>(&sA[0][so0]) = ra0;
    *reinterpret_cast<uint4*>(&sA[0][so1]) = ra1;
    *reinterpret_cast<uint4*>(&sB[0][so0]) = rb0;
    *reinterpret_cast<uint4*>(&sB[0][so1]) = rb1;
    __syncthreads();

    int nch = K / KCG;
    #pragma unroll 1
    for (int c = 0; c < nch; c++) {
        int cur = c & 1;
        if (c + 1 < nch) {
            ra0 = *reinterpret_cast<const uint4*>(gA0 + (c + 1) * KCG);
            ra1 = *reinterpret_cast<const uint4*>(gA1 + (c + 1) * KCG);
            rb0 = *reinterpret_cast<const uint4*>(gB0 + (c + 1) * KCG);
            rb1 = *reinterpret_cast<const uint4*>(gB1 + (c + 1) * KCG);
        }

        uint32_t baseA = smem_u32(&sA[cur][0]);
        uint32_t baseB = smem_u32(&sB[cur][0]);

        #pragma unroll
        for (int kk = 0; kk < 2; kk++) {
            unsigned fA[4][4], fB[4][2];
            #pragma unroll
            for (int np = 0; np < 2; np++) {
                unsigned r4[4];
                uint32_t ab = baseB + (uint32_t)(b_row + np * 16) * (PADG * 2)
                              + kk * 32 + b_cb;
                ldm_x4(r4, ab);
                fB[np * 2 + 0][0] = r4[0]; fB[np * 2 + 0][1] = r4[1];
                fB[np * 2 + 1][0] = r4[2]; fB[np * 2 + 1][1] = r4[3];
            }
            #pragma unroll
            for (int mt = 0; mt < 4; mt++)
                ldm_x4(fA[mt], baseA + (uint32_t)(a_row + mt * 16) * (PADG * 2)
                                + kk * 32 + a_cb);
            #pragma unroll
            for (int mt = 0; mt < 4; mt++)
                #pragma unroll
                for (int nt = 0; nt < 4; nt++)
                    mma_f16(acc[mt][nt], fA[mt], fB[nt]);
        }

        if (c + 1 < nch) {
            int nxt = cur ^ 1;
            *reinterpret_cast<uint4*>(&sA[nxt][so0]) = ra0;
            *reinterpret_cast<uint4*>(&sA[nxt][so1]) = ra1;
            *reinterpret_cast<uint4*>(&sB[nxt][so0]) = rb0;
            *reinterpret_cast<uint4*>(&sB[nxt][so1]) = rb1;
        }
        __syncthreads();
    }

    // epilogue
    #pragma unroll
    for (int mt = 0; mt < 4; mt++) {
        int row = m0 + wm * 64 + mt * 16 + (lane >> 2);
        #pragma unroll
        for (int nt = 0; nt < 4; nt++) {
            int col = n0 + wn * 32 + nt * 8 + (lane & 3) * 2;
            if (MODE == 2) {
                // fused qkv routing: [0,C)=q (x0.125), [C,2C)=k, [2C,3C)=v
                float sc = (col < CC) ? 0.125f : 1.0f;
                f16* dst;
                if (col < 2 * CC) dst = Cq + (size_t)row * (2 * CC) + col;
                else              dst = Cv + (size_t)row * CC + (col - 2 * CC);
                #pragma unroll
                for (int half = 0; half < 2; half++) {
                    float v0 = acc[mt][nt][half * 2 + 0] * sc;
                    float v1 = acc[mt][nt][half * 2 + 1] * sc;
                    *reinterpret_cast<unsigned*>(
                        dst + (size_t)(half * 8) * ((col < 2 * CC) ? 2 * CC : CC)) =
                        pack_f162(v0, v1);
                }
            } else {
                float bx = bias[col], by = bias[col + 1];
                float2 r0 = make_float2(acc[mt][nt][0] + bx, acc[mt][nt][1] + by);
                float2 r1 = make_float2(acc[mt][nt][2] + bx, acc[mt][nt][3] + by);
                *reinterpret_cast<float2*>(C + (size_t)row * N + col) = r0;
                *reinterpret_cast<float2*>(C + (size_t)(row + 8) * N + col) = r1;
            }
        }
    }
}

// ---------------------------------------------------------------------------
// Flash attention on tensor cores — all-fp16 operands, fp32 accumulate
// (unchanged from R11: measured 3.46e-4 contribution). BQ=64 (4 warps x 16
// rows), 128 threads. K/V double-buffered via cp.async. Q pre-scaled 0.125.
// ---------------------------------------------------------------------------
#define APAD 72
#define KVB (2 * 64 * APAD)      // elems per K/V buffer (K | V)
#define ASMEM (2 * KVB * 2)      // bytes (36864)

__global__ void __launch_bounds__(128)
attn_mma(const f16* __restrict__ qkh, const f16* __restrict__ vp,
         float* __restrict__ out) {
    extern __shared__ f16 sm[];
    const uint32_t sb = smem_u32(sm);

    int qt = blockIdx.x, h = blockIdx.y, b = blockIdx.z;
    int tid = threadIdx.x, warp = tid >> 5, lane = tid & 31;
    int quad = lane >> 2, tq = lane & 3;

    // --- stage Q (fp16, 64 rows) in buf0 region; build persistent frags ---
    for (int i = tid; i < 64 * 8; i += 128) {
        int r = i >> 3, c8 = (i & 7) * 8;
        size_t grow = (size_t)(b * NN + qt * 64 + r) * (2 * CC) + h * HD + c8;
        *reinterpret_cast<uint4*>(&sm[r * APAD + c8]) =
            *reinterpret_cast<const uint4*>(qkh + grow);
    }
    __syncthreads();
    unsigned fQh[4][4];
    {
        int ar = warp * 16 + (lane & 15);
        int cb = ((lane >> 4) & 1) * 16;
        #pragma unroll
        for (int kk = 0; kk < 4; kk++)
            ldm_x4(fQh[kk], sb + (uint32_t)(ar * APAD) * 2 + kk * 32 + cb);
    }
    __syncthreads();

    float O[8][4];
    #pragma unroll
    for (int nt = 0; nt < 8; nt++)
        #pragma unroll
        for (int q = 0; q < 4; q++) O[nt][q] = 0.0f;
    float m0 = -1e30f, m1 = -1e30f, l0 = 0.0f, l1 = 0.0f;

    int krow = tid >> 3, kcol = (tid & 7) * 8;

    int kb_row = ((lane >> 4) & 1) * 8 + (lane & 7);
    int kb_cb  = ((lane >> 3) & 1) * 16;
    int vb_row = ((lane >> 3) & 1) * 8 + (lane & 7);
    int vb_cb  = ((lane >> 4) & 1) * 16;

    auto kv_issue = [&](int it, int buf) {
        uint32_t base = sb + (uint32_t)buf * (KVB * 2);
        #pragma unroll
        for (int rr = 0; rr < 64; rr += 16) {
            int r = krow + rr;
            size_t gk = (size_t)(b * NN + it * 64 + r) * (2 * CC) + CC + h * HD + kcol;
            size_t gv = (size_t)(b * NN + it * 64 + r) * CC + h * HD + kcol;
            cp16(base + (uint32_t)(0 * 64 * APAD + r * APAD + kcol) * 2, qkh + gk);
            cp16(base + (uint32_t)(1 * 64 * APAD + r * APAD + kcol) * 2, vp + gv);
        }
        CP_COMMIT();
    };

    kv_issue(0, 0);

    const int NIT = NN / 64;
    #pragma unroll 1
    for (int it = 0; it < NIT; it++) {
        int cur = it & 1;
        if (it + 1 < NIT) {
            kv_issue(it + 1, cur ^ 1);
            CP_WAIT1();
        } else {
            CP_WAIT0();
        }
        __syncthreads();

        uint32_t base = sb + (uint32_t)cur * (KVB * 2);
        uint32_t sKh = base;
        uint32_t sVh = base + 1 * 64 * APAD * 2;

        // ---- S = Q @ K^T (1 pass, fp16) ----
        float S[8][4];
        #pragma unroll
        for (int nt = 0; nt < 8; nt++)
            #pragma unroll
            for (int q = 0; q < 4; q++) S[nt][q] = 0.0f;

        #pragma unroll
        for (int kk = 0; kk < 4; kk++) {
            unsigned fKh[8][2];
            #pragma unroll
            for (int np = 0; np < 4; np++) {
                unsigned r4[4];
                uint32_t off = (uint32_t)(kb_row + np * 16) * (APAD * 2) + kb_cb + kk * 32;
                ldm_x4(r4, sKh + off);
                fKh[np * 2 + 0][0] = r4[0]; fKh[np * 2 + 0][1] = r4[1];
                fKh[np * 2 + 1][0] = r4[2]; fKh[np * 2 + 1][1] = r4[3];
            }
            #pragma unroll
            for (int nt = 0; nt < 8; nt++)
                mma_f16(S[nt], fQh[kk], fKh[nt]);
        }

        // ---- online softmax in registers ----
        float mx0 = -1e30f, mx1 = -1e30f;
        #pragma unroll
        for (int nt = 0; nt < 8; nt++) {
            mx0 = fmaxf(mx0, fmaxf(S[nt][0], S[nt][1]));
            mx1 = fmaxf(mx1, fmaxf(S[nt][2], S[nt][3]));
        }
        mx0 = fmaxf(mx0, __shfl_xor_sync(0xFFFFFFFFu, mx0, 1));
        mx0 = fmaxf(mx0, __shfl_xor_sync(0xFFFFFFFFu, mx0, 2));
        mx1 = fmaxf(mx1, __shfl_xor_sync(0xFFFFFFFFu, mx1, 1));
        mx1 = fmaxf(mx1, __shfl_xor_sync(0xFFFFFFFFu, mx1, 2));
        float mn0 = fmaxf(m0, mx0), mn1 = fmaxf(m1, mx1);
        float al0 = __expf(m0 - mn0), al1 = __expf(m1 - mn1);
        m0 = mn0; m1 = mn1;

        float s0 = 0.0f, s1 = 0.0f;
        #pragma unroll
        for (int nt = 0; nt < 8; nt++) {
            S[nt][0] = __expf(S[nt][0] - mn0); s0 += S[nt][0];
            S[nt][1] = __expf(S[nt][1] - mn0); s0 += S[nt][1];
            S[nt][2] = __expf(S[nt][2] - mn1); s1 += S[nt][2];
            S[nt][3] = __expf(S[nt][3] - mn1); s1 += S[nt][3];
        }
        s0 += __shfl_xor_sync(0xFFFFFFFFu, s0, 1);
        s0 += __shfl_xor_sync(0xFFFFFFFFu, s0, 2);
        s1 += __shfl_xor_sync(0xFFFFFFFFu, s1, 1);
        s1 += __shfl_xor_sync(0xFFFFFFFFu, s1, 2);
        l0 = l0 * al0 + s0;
        l1 = l1 * al1 + s1;

        #pragma unroll
        for (int nt = 0; nt < 8; nt++) {
            O[nt][0] *= al0; O[nt][1] *= al0;
            O[nt][2] *= al1; O[nt][3] *= al1;
        }

        unsigned Phi[8][2];
        #pragma unroll
        for (int nt = 0; nt < 8; nt++) {
            Phi[nt][0] = pack_f162(S[nt][0], S[nt][1]);
            Phi[nt][1] = pack_f162(S[nt][2], S[nt][3]);
        }

        // ---- O += P @ V (1 pass, fp16) ----
        #pragma unroll
        for (int kk = 0; kk < 4; kk++) {
            unsigned aPh[4] = {Phi[2 * kk][0], Phi[2 * kk][1],
                               Phi[2 * kk + 1][0], Phi[2 * kk + 1][1]};
            unsigned fVh[8][2];
            #pragma unroll
            for (int nt2 = 0; nt2 < 4; nt2++) {
                unsigned r4[4];
                uint32_t off = (uint32_t)(vb_row + kk * 16) * (APAD * 2) + vb_cb + nt2 * 32;
                ldm_x4t(r4, sVh + off);
                fVh[nt2 * 2 + 0][0] = r4[0]; fVh[nt2 * 2 + 0][1] = r4[1];
                fVh[nt2 * 2 + 1][0] = r4[2]; fVh[nt2 * 2 + 1][1] = r4[3];
            }
            #pragma unroll
            for (int nt = 0; nt < 8; nt++)
                mma_f16(O[nt], aPh, fVh[nt]);
        }
        __syncthreads();
    }

    // ---- finalize & store ----
    float inv0 = 1.0f / l0, inv1 = 1.0f / l1;
    int row0 = b * NN + qt * 64 + warp * 16 + quad;
    #pragma unroll
    for (int nt = 0; nt < 8; nt++) {
        int col = h * HD + nt * 8 + tq * 2;
        *reinterpret_cast<float2*>(out + (size_t)row0 * CC + col) =
            make_float2(O[nt][0] * inv0, O[nt][1] * inv0);
        *reinterpret_cast<float2*>(out + (size_t)(row0 + 8) * CC + col) =
            make_float2(O[nt][2] * inv1, O[nt][3] * inv1);
    }
}

// ---------------------------------------------------------------------------
extern "C" void kernel_launch(void* const* d_in, const int* in_sizes, int n_in,
                              void* d_out, int out_size) {
    const float* x      = (const float*)d_in[0];
    const float* ln1_g  = (const float*)d_in[1];
    const float* ln1_b  = (const float*)d_in[2];
    const float* w_qk   = (const float*)d_in[3];
    const float* w_v    = (const float*)d_in[4];
    const float* ln2_g  = (const float*)d_in[5];
    const float* ln2_b  = (const float*)d_in[6];
    const float* w_proj = (const float*)d_in[7];
    const float* b_proj = (const float*)d_in[8];
    float* out = (float*)d_out;

    float* ao;
    f16 *xf, *qkh, *vp, *wT, *wpT;
    cudaGetSymbolAddress((void**)&ao,   g_ao);
    cudaGetSymbolAddress((void**)&xf,   g_xf);
    cudaGetSymbolAddress((void**)&qkh,  g_qkh);
    cudaGetSymbolAddress((void**)&vp,   g_v);
    cudaGetSymbolAddress((void**)&wT,   g_wT);
    cudaGetSymbolAddress((void**)&wpT,  g_wpT);

    cudaFuncSetAttribute(attn_mma, cudaFuncAttributeMaxDynamicSharedMemorySize, ASMEM);

    // weight transpose -> fp16 (fused buffer: qk rows [0,2C), v rows [2C,3C))
    wsplit_f16<<<dim3(2 * CC / 32, CC / 32), dim3(32, 8)>>>(w_qk, wT, CC, 2 * CC);
    wsplit_f16<<<dim3(CC / 32, CC / 32), dim3(32, 8)>>>(
        w_v, wT + (size_t)2 * CC * CC, CC, CC);
    wsplit_f16<<<dim3(CC / 32, CC / 32), dim3(32, 8)>>>(w_proj, wpT, CC, CC);

    // 1. LN1 -> fp16
    ln_f16_kernel<<<MM, 256>>>(x, ln1_g, ln1_b, xf);

    // 2. fused qkv projection (1-pass fp16; q pre-scaled 0.125)
    gemm_f16<2><<<dim3(3 * CC / 128, MM / 128), 256>>>(
        xf, wT, nullptr, nullptr, qkh, vp, MM, 3 * CC, CC);

    // 3. tensor-core flash attention (all-fp16 operands, fp32 accum)
    attn_mma<<<dim3(NN / 64, HH, BB), 128, ASMEM>>>(qkh, vp, ao);

    // 4. LN2 -> fp16
    ln_f16_kernel<<<MM, 256>>>(ao, ln2_g, ln2_b, xf);

    // 5. output projection + bias (1-pass fp16, fp32 out)
    gemm_f16<0><<<dim3(CC / 128, MM / 128), 256>>>(
        xf, wpT, b_proj, out, nullptr, nullptr, MM, CC, CC);
}

// round 13
// speedup vs baseline: 2.6217x; 1.0070x over previous
#include <cuda_runtime.h>
#include <cuda_bf16.h>
#include <cuda_fp16.h>
#include <cstdint>

// Problem constants (fixed shapes)
#define BB 2
#define NN 2048
#define CC 1024
#define HH 16
#define HD 64
#define MM (BB * NN)   // 4096 rows

typedef __half f16;

// ---------------------------------------------------------------------------
// Scratch (device globals — no allocations allowed)
// ---------------------------------------------------------------------------
__device__ float g_ao[MM * CC];
__device__ f16 g_xf[MM * CC];                  // LN output, fp16
__device__ f16 g_qkh[MM * 2 * CC];             // q|k fp16 (q pre-scaled 0.125)
__device__ f16 g_v[MM * CC];                   // v fp16
__device__ f16 g_wT[3 * CC * CC];              // fused w^T fp16: qk rows [0,2C), v rows [2C,3C)
__device__ f16 g_wpT[CC * CC];                 // w_proj^T fp16

// ---------------------------------------------------------------------------
// helpers
// ---------------------------------------------------------------------------
__device__ __forceinline__ uint32_t smem_u32(const void* p) {
    uint32_t a;
    asm("{ .reg .u64 t; cvta.to.shared.u64 t, %1; cvt.u32.u64 %0, t; }"
        : "=r"(a) : "l"(p));
    return a;
}

__device__ __forceinline__ void mma_f16(float* c, const unsigned* a, const unsigned* b) {
    asm volatile(
        "mma.sync.aligned.m16n8k16.row.col.f32.f16.f16.f32 "
        "{%0,%1,%2,%3}, {%4,%5,%6,%7}, {%8,%9}, {%0,%1,%2,%3};"
        : "+f"(c[0]), "+f"(c[1]), "+f"(c[2]), "+f"(c[3])
        : "r"(a[0]), "r"(a[1]), "r"(a[2]), "r"(a[3]), "r"(b[0]), "r"(b[1]));
}

__device__ __forceinline__ void ldm_x4(unsigned* r, uint32_t addr) {
    asm volatile("ldmatrix.sync.aligned.m8n8.x4.shared.b16 {%0,%1,%2,%3}, [%4];"
        : "=r"(r[0]), "=r"(r[1]), "=r"(r[2]), "=r"(r[3]) : "r"(addr));
}
__device__ __forceinline__ void ldm_x4t(unsigned* r, uint32_t addr) {
    asm volatile("ldmatrix.sync.aligned.m8n8.x4.trans.shared.b16 {%0,%1,%2,%3}, [%4];"
        : "=r"(r[0]), "=r"(r[1]), "=r"(r[2]), "=r"(r[3]) : "r"(addr));
}

// cp.async 16B global -> shared (attention K/V only)
__device__ __forceinline__ void cp16(uint32_t dst, const void* src) {
    asm volatile("cp.async.cg.shared.global [%0], [%1], 16;"
        :: "r"(dst), "l"(__cvta_generic_to_global(src)) : "memory");
}
#define CP_COMMIT() asm volatile("cp.async.commit_group;" ::: "memory")
#define CP_WAIT1()  asm volatile("cp.async.wait_group 1;" ::: "memory")
#define CP_WAIT0()  asm volatile("cp.async.wait_group 0;" ::: "memory")

// pack two f32 -> f16x2 register (lo = first arg)
__device__ __forceinline__ unsigned pack_f162(float lo, float hi) {
    unsigned r;
    asm("cvt.rn.f16x2.f32 %0, %1, %2;" : "=r"(r) : "f"(hi), "f"(lo));
    return r;
}

// ---------------------------------------------------------------------------
// LayerNorm -> fp16 output
// ---------------------------------------------------------------------------
__global__ void ln_f16_kernel(const float* __restrict__ x,
                              const float* __restrict__ g,
                              const float* __restrict__ b,
                              f16* __restrict__ o) {
    int row = blockIdx.x;
    int t = threadIdx.x;
    const float4* xr = reinterpret_cast<const float4*>(x + (size_t)row * CC);
    float4 v = xr[t];
    float s  = v.x + v.y + v.z + v.w;
    float ss = v.x * v.x + v.y * v.y + v.z * v.z + v.w * v.w;

    #pragma unroll
    for (int of = 16; of > 0; of >>= 1) {
        s  += __shfl_down_sync(0xFFFFFFFFu, s,  of);
        ss += __shfl_down_sync(0xFFFFFFFFu, ss, of);
    }
    __shared__ float sh[8][2];
    int w = t >> 5, l = t & 31;
    if (l == 0) { sh[w][0] = s; sh[w][1] = ss; }
    __syncthreads();
    if (w == 0) {
        s  = (l < 8) ? sh[l][0] : 0.0f;
        ss = (l < 8) ? sh[l][1] : 0.0f;
        #pragma unroll
        for (int of = 4; of > 0; of >>= 1) {
            s  += __shfl_down_sync(0xFFFFFFFFu, s,  of);
            ss += __shfl_down_sync(0xFFFFFFFFu, ss, of);
        }
        if (l == 0) { sh[0][0] = s; sh[0][1] = ss; }
    }
    __syncthreads();
    s = sh[0][0]; ss = sh[0][1];

    float mu  = s * (1.0f / CC);
    float var = ss * (1.0f / CC) - mu * mu;
    float inv = rsqrtf(var + 1e-5f);

    const float4 gv = reinterpret_cast<const float4*>(g)[t];
    const float4 bv = reinterpret_cast<const float4*>(b)[t];
    float o0 = (v.x - mu) * inv * gv.x + bv.x;
    float o1 = (v.y - mu) * inv * gv.y + bv.y;
    float o2 = (v.z - mu) * inv * gv.z + bv.z;
    float o3 = (v.w - mu) * inv * gv.w + bv.w;

    *reinterpret_cast<uint2*>(o + (size_t)row * CC + t * 4) =
        make_uint2(pack_f162(o0, o1), pack_f162(o2, o3));
}

// ---------------------------------------------------------------------------
// Transpose: w[K][N] fp32 -> wT[N][K] fp16
// ---------------------------------------------------------------------------
__global__ void wsplit_f16(const float* __restrict__ w,
                           f16* __restrict__ tOut,
                           int K, int N) {
    __shared__ float t[32][33];
    int bx = blockIdx.x, by = blockIdx.y;
    int x = bx * 32 + threadIdx.x;
    #pragma unroll
    for (int j = 0; j < 32; j += 8)
        t[threadIdx.y + j][threadIdx.x] = w[(size_t)(by * 32 + threadIdx.y + j) * N + x];
    __syncthreads();
    int n = bx * 32 + threadIdx.y;
    int k = by * 32 + threadIdx.x;
    #pragma unroll
    for (int j = 0; j < 32; j += 8)
        tOut[(size_t)(n + j) * K + k] = __float2half(t[threadIdx.x][threadIdx.y + j]);
}

// ---------------------------------------------------------------------------
// 1-pass fp16 GEMM (fp32 accumulate): C[M,N] = A[M,K] @ B[N,K]^T.
// MODE 0: fp32 out (+bias). MODE 2: fused qkv epilogue — cols [0,2C) -> Cq
// (x0.125 for cols < C), cols [2C,3C) -> Cv at col-2C.
// CTA 128x128 tile, 8 warps (2x4), warp 64x32. K chunk 32, register-prefetch
// double buffer. __launch_bounds__(256,2) -> 2 CTAs/SM.
// ---------------------------------------------------------------------------
#define KCG 32
#define PADG 40

template <int MODE>
__global__ void __launch_bounds__(256, 2)
gemm_f16(const f16* __restrict__ A, const f16* __restrict__ B,
         const float* __restrict__ bias, float* __restrict__ C,
         f16* __restrict__ Cq, f16* __restrict__ Cv,
         int M, int N, int K) {
    __shared__ f16 sA[2][128 * PADG];
    __shared__ f16 sB[2][128 * PADG];

    int tid = threadIdx.x;
    int warp = tid >> 5, lane = tid & 31;
    int wm = warp >> 2, wn = warp & 3;
    int m0 = blockIdx.y * 128, n0 = blockIdx.x * 128;

    int lr0 = tid >> 2, lc0 = (tid & 3) * 8;
    int lr1 = (tid + 256) >> 2;
    const f16* gA0 = A + (size_t)(m0 + lr0) * K + lc0;
    const f16* gA1 = A + (size_t)(m0 + lr1) * K + lc0;
    const f16* gB0 = B + (size_t)(n0 + lr0) * K + lc0;
    const f16* gB1 = B + (size_t)(n0 + lr1) * K + lc0;
    int so0 = lr0 * PADG + lc0;
    int so1 = lr1 * PADG + lc0;

    float acc[4][4][4];
    #pragma unroll
    for (int i = 0; i < 4; i++)
        #pragma unroll
        for (int j = 0; j < 4; j++)
            #pragma unroll
            for (int q = 0; q < 4; q++) acc[i][j][q] = 0.0f;

    int a_row = wm * 64 + (lane & 15);
    int a_cb  = ((lane >> 4) & 1) * 16;
    int b_row = wn * 32 + ((lane >> 4) & 1) * 8 + (lane & 7);
    int b_cb  = ((lane >> 3) & 1) * 16;

    // prologue: chunk 0
    uint4 ra0 = *reinterpret_cast<const uint4*>(gA0);
    uint4 ra1 = *reinterpret_cast<const uint4*>(gA1);
    uint4 rb0 = *reinterpret_cast<const uint4*>(gB0);
    uint4 rb1 = *reinterpret_cast<const uint4*>(gB1);
    *reinterpret_cast<uint4*>(&sA[0][so0]) = ra0;
    *reinterpret_cast<uint4*>(&sA[0][so1]) = ra1;
    *reinterpret_cast<uint4*>(&sB[0][so0]) = rb0;
    *reinterpret_cast<uint4*>(&sB[0][so1]) = rb1;
    __syncthreads();

    int nch = K / KCG;
    #pragma unroll 1
    for (int c = 0; c < nch; c++) {
        int cur = c & 1;
        if (c + 1 < nch) {
            ra0 = *reinterpret_cast<const uint4*>(gA0 + (c + 1) * KCG);
            ra1 = *reinterpret_cast<const uint4*>(gA1 + (c + 1) * KCG);
            rb0 = *reinterpret_cast<const uint4*>(gB0 + (c + 1) * KCG);
            rb1 = *reinterpret_cast<const uint4*>(gB1 + (c + 1) * KCG);
        }

        uint32_t baseA = smem_u32(&sA[cur][0]);
        uint32_t baseB = smem_u32(&sB[cur][0]);

        #pragma unroll
        for (int kk = 0; kk < 2; kk++) {
            unsigned fA[4][4], fB[4][2];
            #pragma unroll
            for (int np = 0; np < 2; np++) {
                unsigned r4[4];
                uint32_t ab = baseB + (uint32_t)(b_row + np * 16) * (PADG * 2)
                              + kk * 32 + b_cb;
                ldm_x4(r4, ab);
                fB[np * 2 + 0][0] = r4[0]; fB[np * 2 + 0][1] = r4[1];
                fB[np * 2 + 1][0] = r4[2]; fB[np * 2 + 1][1] = r4[3];
            }
            #pragma unroll
            for (int mt = 0; mt < 4; mt++)
                ldm_x4(fA[mt], baseA + (uint32_t)(a_row + mt * 16) * (PADG * 2)
                                + kk * 32 + a_cb);
            #pragma unroll
            for (int mt = 0; mt < 4; mt++)
                #pragma unroll
                for (int nt = 0; nt < 4; nt++)
                    mma_f16(acc[mt][nt], fA[mt], fB[nt]);
        }

        if (c + 1 < nch) {
            int nxt = cur ^ 1;
            *reinterpret_cast<uint4*>(&sA[nxt][so0]) = ra0;
            *reinterpret_cast<uint4*>(&sA[nxt][so1]) = ra1;
            *reinterpret_cast<uint4*>(&sB[nxt][so0]) = rb0;
            *reinterpret_cast<uint4*>(&sB[nxt][so1]) = rb1;
        }
        __syncthreads();
    }

    // epilogue
    #pragma unroll
    for (int mt = 0; mt < 4; mt++) {
        int row = m0 + wm * 64 + mt * 16 + (lane >> 2);
        #pragma unroll
        for (int nt = 0; nt < 4; nt++) {
            int col = n0 + wn * 32 + nt * 8 + (lane & 3) * 2;
            if (MODE == 2) {
                // fused qkv routing: [0,C)=q (x0.125), [C,2C)=k, [2C,3C)=v
                float sc = (col < CC) ? 0.125f : 1.0f;
                f16* dst;
                if (col < 2 * CC) dst = Cq + (size_t)row * (2 * CC) + col;
                else              dst = Cv + (size_t)row * CC + (col - 2 * CC);
                #pragma unroll
                for (int half = 0; half < 2; half++) {
                    float v0 = acc[mt][nt][half * 2 + 0] * sc;
                    float v1 = acc[mt][nt][half * 2 + 1] * sc;
                    *reinterpret_cast<unsigned*>(
                        dst + (size_t)(half * 8) * ((col < 2 * CC) ? 2 * CC : CC)) =
                        pack_f162(v0, v1);
                }
            } else {
                float bx = bias[col], by = bias[col + 1];
                float2 r0 = make_float2(acc[mt][nt][0] + bx, acc[mt][nt][1] + by);
                float2 r1 = make_float2(acc[mt][nt][2] + bx, acc[mt][nt][3] + by);
                *reinterpret_cast<float2*>(C + (size_t)row * N + col) = r0;
                *reinterpret_cast<float2*>(C + (size_t)(row + 8) * N + col) = r1;
            }
        }
    }
}

// ---------------------------------------------------------------------------
// Flash attention on tensor cores — all-fp16 operands, fp32 accumulate.
// BQ=128 with 4 warps: each warp owns 32 q-rows as TWO m16 row-groups that
// SHARE the K/V fragments (halves K/V L2 traffic vs BQ=64 and amortizes all
// per-iteration fixed costs). K/V double-buffered via cp.async. Q pre-scaled
// by 0.125. Numerics identical per-row to the BQ=64 version.
// ---------------------------------------------------------------------------
#define APAD 72
#define KVB (2 * 64 * APAD)      // elems per K/V buffer (K | V)
#define ASMEM (2 * KVB * 2)      // bytes (36864)

__global__ void __launch_bounds__(128)
attn_mma(const f16* __restrict__ qkh, const f16* __restrict__ vp,
         float* __restrict__ out) {
    extern __shared__ f16 sm[];
    const uint32_t sb = smem_u32(sm);

    int qt = blockIdx.x, h = blockIdx.y, b = blockIdx.z;
    int tid = threadIdx.x, warp = tid >> 5, lane = tid & 31;
    int quad = lane >> 2, tq = lane & 3;

    // --- stage Q (fp16, 128 rows) in buf region; build persistent frags ---
    for (int i = tid; i < 128 * 8; i += 128) {
        int r = i >> 3, c8 = (i & 7) * 8;
        size_t grow = (size_t)(b * NN + qt * 128 + r) * (2 * CC) + h * HD + c8;
        *reinterpret_cast<uint4*>(&sm[r * APAD + c8]) =
            *reinterpret_cast<const uint4*>(qkh + grow);
    }
    __syncthreads();
    unsigned fQ[2][4][4];
    {
        int cb = ((lane >> 4) & 1) * 16;
        #pragma unroll
        for (int mt = 0; mt < 2; mt++) {
            int ar = warp * 32 + mt * 16 + (lane & 15);
            #pragma unroll
            for (int kk = 0; kk < 4; kk++)
                ldm_x4(fQ[mt][kk], sb + (uint32_t)(ar * APAD) * 2 + kk * 32 + cb);
        }
    }
    __syncthreads();

    float O[2][8][4];
    #pragma unroll
    for (int mt = 0; mt < 2; mt++)
        #pragma unroll
        for (int nt = 0; nt < 8; nt++)
            #pragma unroll
            for (int q = 0; q < 4; q++) O[mt][nt][q] = 0.0f;
    float mS[2][2], lS[2][2];
    #pragma unroll
    for (int mt = 0; mt < 2; mt++) {
        mS[mt][0] = -1e30f; mS[mt][1] = -1e30f;
        lS[mt][0] = 0.0f;   lS[mt][1] = 0.0f;
    }

    int krow = tid >> 3, kcol = (tid & 7) * 8;

    int kb_row = ((lane >> 4) & 1) * 8 + (lane & 7);
    int kb_cb  = ((lane >> 3) & 1) * 16;
    int vb_row = ((lane >> 3) & 1) * 8 + (lane & 7);
    int vb_cb  = ((lane >> 4) & 1) * 16;

    auto kv_issue = [&](int it, int buf) {
        uint32_t base = sb + (uint32_t)buf * (KVB * 2);
        #pragma unroll
        for (int rr = 0; rr < 64; rr += 16) {
            int r = krow + rr;
            size_t gk = (size_t)(b * NN + it * 64 + r) * (2 * CC) + CC + h * HD + kcol;
            size_t gv = (size_t)(b * NN + it * 64 + r) * CC + h * HD + kcol;
            cp16(base + (uint32_t)(0 * 64 * APAD + r * APAD + kcol) * 2, qkh + gk);
            cp16(base + (uint32_t)(1 * 64 * APAD + r * APAD + kcol) * 2, vp + gv);
        }
        CP_COMMIT();
    };

    kv_issue(0, 0);

    const int NIT = NN / 64;
    #pragma unroll 1
    for (int it = 0; it < NIT; it++) {
        int cur = it & 1;
        if (it + 1 < NIT) {
            kv_issue(it + 1, cur ^ 1);
            CP_WAIT1();
        } else {
            CP_WAIT0();
        }
        __syncthreads();

        uint32_t base = sb + (uint32_t)cur * (KVB * 2);
        uint32_t sKh = base;
        uint32_t sVh = base + 1 * 64 * APAD * 2;

        // ---- S = Q @ K^T (1 pass, fp16; K frags shared across 2 m-tiles) ----
        float S[2][8][4];
        #pragma unroll
        for (int mt = 0; mt < 2; mt++)
            #pragma unroll
            for (int nt = 0; nt < 8; nt++)
                #pragma unroll
                for (int q = 0; q < 4; q++) S[mt][nt][q] = 0.0f;

        #pragma unroll
        for (int kk = 0; kk < 4; kk++) {
            unsigned fKh[8][2];
            #pragma unroll
            for (int np = 0; np < 4; np++) {
                unsigned r4[4];
                uint32_t off = (uint32_t)(kb_row + np * 16) * (APAD * 2) + kb_cb + kk * 32;
                ldm_x4(r4, sKh + off);
                fKh[np * 2 + 0][0] = r4[0]; fKh[np * 2 + 0][1] = r4[1];
                fKh[np * 2 + 1][0] = r4[2]; fKh[np * 2 + 1][1] = r4[3];
            }
            #pragma unroll
            for (int mt = 0; mt < 2; mt++)
                #pragma unroll
                for (int nt = 0; nt < 8; nt++)
                    mma_f16(S[mt][nt], fQ[mt][kk], fKh[nt]);
        }

        // ---- online softmax (per m-tile) + pack P ----
        unsigned Phi[2][8][2];
        #pragma unroll
        for (int mt = 0; mt < 2; mt++) {
            float mx0 = -1e30f, mx1 = -1e30f;
            #pragma unroll
            for (int nt = 0; nt < 8; nt++) {
                mx0 = fmaxf(mx0, fmaxf(S[mt][nt][0], S[mt][nt][1]));
                mx1 = fmaxf(mx1, fmaxf(S[mt][nt][2], S[mt][nt][3]));
            }
            mx0 = fmaxf(mx0, __shfl_xor_sync(0xFFFFFFFFu, mx0, 1));
            mx0 = fmaxf(mx0, __shfl_xor_sync(0xFFFFFFFFu, mx0, 2));
            mx1 = fmaxf(mx1, __shfl_xor_sync(0xFFFFFFFFu, mx1, 1));
            mx1 = fmaxf(mx1, __shfl_xor_sync(0xFFFFFFFFu, mx1, 2));
            float mn0 = fmaxf(mS[mt][0], mx0), mn1 = fmaxf(mS[mt][1], mx1);
            float al0 = __expf(mS[mt][0] - mn0), al1 = __expf(mS[mt][1] - mn1);
            mS[mt][0] = mn0; mS[mt][1] = mn1;

            float s0 = 0.0f, s1 = 0.0f;
            #pragma unroll
            for (int nt = 0; nt < 8; nt++) {
                S[mt][nt][0] = __expf(S[mt][nt][0] - mn0); s0 += S[mt][nt][0];
                S[mt][nt][1] = __expf(S[mt][nt][1] - mn0); s0 += S[mt][nt][1];
                S[mt][nt][2] = __expf(S[mt][nt][2] - mn1); s1 += S[mt][nt][2];
                S[mt][nt][3] = __expf(S[mt][nt][3] - mn1); s1 += S[mt][nt][3];
            }
            s0 += __shfl_xor_sync(0xFFFFFFFFu, s0, 1);
            s0 += __shfl_xor_sync(0xFFFFFFFFu, s0, 2);
            s1 += __shfl_xor_sync(0xFFFFFFFFu, s1, 1);
            s1 += __shfl_xor_sync(0xFFFFFFFFu, s1, 2);
            lS[mt][0] = lS[mt][0] * al0 + s0;
            lS[mt][1] = lS[mt][1] * al1 + s1;

            #pragma unroll
            for (int nt = 0; nt < 8; nt++) {
                O[mt][nt][0] *= al0; O[mt][nt][1] *= al0;
                O[mt][nt][2] *= al1; O[mt][nt][3] *= al1;
            }
            #pragma unroll
            for (int nt = 0; nt < 8; nt++) {
                Phi[mt][nt][0] = pack_f162(S[mt][nt][0], S[mt][nt][1]);
                Phi[mt][nt][1] = pack_f162(S[mt][nt][2], S[mt][nt][3]);
            }
        }

        // ---- O += P @ V (1 pass, fp16; V frags shared across 2 m-tiles) ----
        #pragma unroll
        for (int kk = 0; kk < 4; kk++) {
            unsigned fVh[8][2];
            #pragma unroll
            for (int nt2 = 0; nt2 < 4; nt2++) {
                unsigned r4[4];
                uint32_t off = (uint32_t)(vb_row + kk * 16) * (APAD * 2) + vb_cb + nt2 * 32;
                ldm_x4t(r4, sVh + off);
                fVh[nt2 * 2 + 0][0] = r4[0]; fVh[nt2 * 2 + 0][1] = r4[1];
                fVh[nt2 * 2 + 1][0] = r4[2]; fVh[nt2 * 2 + 1][1] = r4[3];
            }
            #pragma unroll
            for (int mt = 0; mt < 2; mt++) {
                unsigned aPh[4] = {Phi[mt][2 * kk][0], Phi[mt][2 * kk][1],
                                   Phi[mt][2 * kk + 1][0], Phi[mt][2 * kk + 1][1]};
                #pragma unroll
                for (int nt = 0; nt < 8; nt++)
                    mma_f16(O[mt][nt], aPh, fVh[nt]);
            }
        }
        __syncthreads();
    }

    // ---- finalize & store ----
    #pragma unroll
    for (int mt = 0; mt < 2; mt++) {
        float inv0 = 1.0f / lS[mt][0], inv1 = 1.0f / lS[mt][1];
        int row0 = b * NN + qt * 128 + warp * 32 + mt * 16 + quad;
        #pragma unroll
        for (int nt = 0; nt < 8; nt++) {
            int col = h * HD + nt * 8 + tq * 2;
            *reinterpret_cast<float2*>(out + (size_t)row0 * CC + col) =
                make_float2(O[mt][nt][0] * inv0, O[mt][nt][1] * inv0);
            *reinterpret_cast<float2*>(out + (size_t)(row0 + 8) * CC + col) =
                make_float2(O[mt][nt][2] * inv1, O[mt][nt][3] * inv1);
        }
    }
}

// ---------------------------------------------------------------------------
extern "C" void kernel_launch(void* const* d_in, const int* in_sizes, int n_in,
                              void* d_out, int out_size) {
    const float* x      = (const float*)d_in[0];
    const float* ln1_g  = (const float*)d_in[1];
    const float* ln1_b  = (const float*)d_in[2];
    const float* w_qk   = (const float*)d_in[3];
    const float* w_v    = (const float*)d_in[4];
    const float* ln2_g  = (const float*)d_in[5];
    const float* ln2_b  = (const float*)d_in[6];
    const float* w_proj = (const float*)d_in[7];
    const float* b_proj = (const float*)d_in[8];
    float* out = (float*)d_out;

    float* ao;
    f16 *xf, *qkh, *vp, *wT, *wpT;
    cudaGetSymbolAddress((void**)&ao,   g_ao);
    cudaGetSymbolAddress((void**)&xf,   g_xf);
    cudaGetSymbolAddress((void**)&qkh,  g_qkh);
    cudaGetSymbolAddress((void**)&vp,   g_v);
    cudaGetSymbolAddress((void**)&wT,   g_wT);
    cudaGetSymbolAddress((void**)&wpT,  g_wpT);

    cudaFuncSetAttribute(attn_mma, cudaFuncAttributeMaxDynamicSharedMemorySize, ASMEM);

    // weight transpose -> fp16 (fused buffer: qk rows [0,2C), v rows [2C,3C))
    wsplit_f16<<<dim3(2 * CC / 32, CC / 32), dim3(32, 8)>>>(w_qk, wT, CC, 2 * CC);
    wsplit_f16<<<dim3(CC / 32, CC / 32), dim3(32, 8)>>>(
        w_v, wT + (size_t)2 * CC * CC, CC, CC);
    wsplit_f16<<<dim3(CC / 32, CC / 32), dim3(32, 8)>>>(w_proj, wpT, CC, CC);

    // 1. LN1 -> fp16
    ln_f16_kernel<<<MM, 256>>>(x, ln1_g, ln1_b, xf);

    // 2. fused qkv projection (1-pass fp16; q pre-scaled 0.125)
    gemm_f16<2><<<dim3(3 * CC / 128, MM / 128), 256>>>(
        xf, wT, nullptr, nullptr, qkh, vp, MM, 3 * CC, CC);

    // 3. tensor-core flash attention (BQ=128, shared K/V frags)
    attn_mma<<<dim3(NN / 128, HH, BB), 128, ASMEM>>>(qkh, vp, ao);

    // 4. LN2 -> fp16
    ln_f16_kernel<<<MM, 256>>>(ao, ln2_g, ln2_b, xf);

    // 5. output projection + bias (1-pass fp16, fp32 out)
    gemm_f16<0><<<dim3(CC / 128, MM / 128), 256>>>(
        xf, wpT, b_proj, out, nullptr, nullptr, MM, CC, CC);
}

// round 14
// speedup vs baseline: 2.7718x; 1.0573x over previous
#include <cuda_runtime.h>
#include <cuda_bf16.h>
#include <cuda_fp16.h>
#include <cstdint>

// Problem constants (fixed shapes)
#define BB 2
#define NN 2048
#define CC 1024
#define HH 16
#define HD 64
#define MM (BB * NN)   // 4096 rows

// q pre-scale: 0.125 (hd^-0.5) * log2(e)  -> S comes out in log2 units
#define QSCALE 0.1803368801111137f

typedef __half f16;

// ---------------------------------------------------------------------------
// Scratch (device globals — no allocations allowed)
// ---------------------------------------------------------------------------
__device__ float g_ao[MM * CC];
__device__ f16 g_xf[MM * CC];                  // LN output, fp16
__device__ f16 g_qkh[MM * 2 * CC];             // q|k fp16 (q pre-scaled QSCALE)
__device__ f16 g_v[MM * CC];                   // v fp16
__device__ f16 g_wT[3 * CC * CC];              // fused w^T fp16: qk rows [0,2C), v rows [2C,3C)
__device__ f16 g_wpT[CC * CC];                 // w_proj^T fp16

// ---------------------------------------------------------------------------
// helpers
// ---------------------------------------------------------------------------
__device__ __forceinline__ uint32_t smem_u32(const void* p) {
    uint32_t a;
    asm("{ .reg .u64 t; cvta.to.shared.u64 t, %1; cvt.u32.u64 %0, t; }"
        : "=r"(a) : "l"(p));
    return a;
}

__device__ __forceinline__ void mma_f16(float* c, const unsigned* a, const unsigned* b) {
    asm volatile(
        "mma.sync.aligned.m16n8k16.row.col.f32.f16.f16.f32 "
        "{%0,%1,%2,%3}, {%4,%5,%6,%7}, {%8,%9}, {%0,%1,%2,%3};"
        : "+f"(c[0]), "+f"(c[1]), "+f"(c[2]), "+f"(c[3])
        : "r"(a[0]), "r"(a[1]), "r"(a[2]), "r"(a[3]), "r"(b[0]), "r"(b[1]));
}

__device__ __forceinline__ void ldm_x4(unsigned* r, uint32_t addr) {
    asm volatile("ldmatrix.sync.aligned.m8n8.x4.shared.b16 {%0,%1,%2,%3}, [%4];"
        : "=r"(r[0]), "=r"(r[1]), "=r"(r[2]), "=r"(r[3]) : "r"(addr));
}
__device__ __forceinline__ void ldm_x4t(unsigned* r, uint32_t addr) {
    asm volatile("ldmatrix.sync.aligned.m8n8.x4.trans.shared.b16 {%0,%1,%2,%3}, [%4];"
        : "=r"(r[0]), "=r"(r[1]), "=r"(r[2]), "=r"(r[3]) : "r"(addr));
}

// cp.async 16B global -> shared (attention K/V only)
__device__ __forceinline__ void cp16(uint32_t dst, const void* src) {
    asm volatile("cp.async.cg.shared.global [%0], [%1], 16;"
        :: "r"(dst), "l"(__cvta_generic_to_global(src)) : "memory");
}
#define CP_COMMIT() asm volatile("cp.async.commit_group;" ::: "memory")
#define CP_WAIT1()  asm volatile("cp.async.wait_group 1;" ::: "memory")
#define CP_WAIT0()  asm volatile("cp.async.wait_group 0;" ::: "memory")

// pack two f32 -> f16x2 register (lo = first arg)
__device__ __forceinline__ unsigned pack_f162(float lo, float hi) {
    unsigned r;
    asm("cvt.rn.f16x2.f32 %0, %1, %2;" : "=r"(r) : "f"(hi), "f"(lo));
    return r;
}
__device__ __forceinline__ unsigned hsub2(unsigned a, unsigned b) {
    unsigned r;
    asm("sub.f16x2 %0, %1, %2;" : "=r"(r) : "r"(a), "r"(b));
    return r;
}
__device__ __forceinline__ unsigned ex2_f16x2(unsigned a) {
    unsigned r;
    asm("ex2.approx.f16x2 %0, %1;" : "=r"(r) : "r"(a));
    return r;
}

// ---------------------------------------------------------------------------
// LayerNorm -> fp16: warp-per-row, pure shuffle reduce (no smem, no barriers)
// block = 128 threads = 4 rows; grid = MM/4
// ---------------------------------------------------------------------------
__global__ void ln_f16_kernel(const float* __restrict__ x,
                              const float* __restrict__ g,
                              const float* __restrict__ b,
                              f16* __restrict__ o) {
    int warp = threadIdx.x >> 5, lane = threadIdx.x & 31;
    int row = blockIdx.x * 4 + warp;
    const float4* xr = reinterpret_cast<const float4*>(x + (size_t)row * CC);

    float4 v[8];
    float s = 0.0f, ss = 0.0f;
    #pragma unroll
    for (int j = 0; j < 8; j++) {
        v[j] = xr[lane + j * 32];
        s  += v[j].x + v[j].y + v[j].z + v[j].w;
        ss += v[j].x * v[j].x + v[j].y * v[j].y + v[j].z * v[j].z + v[j].w * v[j].w;
    }
    #pragma unroll
    for (int of = 16; of > 0; of >>= 1) {
        s  += __shfl_xor_sync(0xFFFFFFFFu, s,  of);
        ss += __shfl_xor_sync(0xFFFFFFFFu, ss, of);
    }

    float mu  = s * (1.0f / CC);
    float var = ss * (1.0f / CC) - mu * mu;
    float inv = rsqrtf(var + 1e-5f);

    const float4* gr = reinterpret_cast<const float4*>(g);
    const float4* br = reinterpret_cast<const float4*>(b);
    uint2* op = reinterpret_cast<uint2*>(o + (size_t)row * CC);
    #pragma unroll
    for (int j = 0; j < 8; j++) {
        float4 gv = gr[lane + j * 32];
        float4 bv = br[lane + j * 32];
        float o0 = (v[j].x - mu) * inv * gv.x + bv.x;
        float o1 = (v[j].y - mu) * inv * gv.y + bv.y;
        float o2 = (v[j].z - mu) * inv * gv.z + bv.z;
        float o3 = (v[j].w - mu) * inv * gv.w + bv.w;
        op[lane + j * 32] = make_uint2(pack_f162(o0, o1), pack_f162(o2, o3));
    }
}

// ---------------------------------------------------------------------------
// Transpose: w[K][N] fp32 -> wT[N][K] fp16
// ---------------------------------------------------------------------------
__global__ void wsplit_f16(const float* __restrict__ w,
                           f16* __restrict__ tOut,
                           int K, int N) {
    __shared__ float t[32][33];
    int bx = blockIdx.x, by = blockIdx.y;
    int x = bx * 32 + threadIdx.x;
    #pragma unroll
    for (int j = 0; j < 32; j += 8)
        t[threadIdx.y + j][threadIdx.x] = w[(size_t)(by * 32 + threadIdx.y + j) * N + x];
    __syncthreads();
    int n = bx * 32 + threadIdx.y;
    int k = by * 32 + threadIdx.x;
    #pragma unroll
    for (int j = 0; j < 32; j += 8)
        tOut[(size_t)(n + j) * K + k] = __float2half(t[threadIdx.x][threadIdx.y + j]);
}

// ---------------------------------------------------------------------------
// 1-pass fp16 GEMM (fp32 accumulate): C[M,N] = A[M,K] @ B[N,K]^T.
// MODE 0: fp32 out (+bias). MODE 2: fused qkv epilogue — cols [0,2C) -> Cq
// (xQSCALE for cols < C), cols [2C,3C) -> Cv at col-2C.
// CTA 128x128 tile, 8 warps (2x4), warp 64x32. K chunk 32, register-prefetch
// double buffer. __launch_bounds__(256,2) -> 2 CTAs/SM.
// ---------------------------------------------------------------------------
#define KCG 32
#define PADG 40

template <int MODE>
__global__ void __launch_bounds__(256, 2)
gemm_f16(const f16* __restrict__ A, const f16* __restrict__ B,
         const float* __restrict__ bias, float* __restrict__ C,
         f16* __restrict__ Cq, f16* __restrict__ Cv,
         int M, int N, int K) {
    __shared__ f16 sA[2][128 * PADG];
    __shared__ f16 sB[2][128 * PADG];

    int tid = threadIdx.x;
    int warp = tid >> 5, lane = tid & 31;
    int wm = warp >> 2, wn = warp & 3;
    int m0 = blockIdx.y * 128, n0 = blockIdx.x * 128;

    int lr0 = tid >> 2, lc0 = (tid & 3) * 8;
    int lr1 = (tid + 256) >> 2;
    const f16* gA0 = A + (size_t)(m0 + lr0) * K + lc0;
    const f16* gA1 = A + (size_t)(m0 + lr1) * K + lc0;
    const f16* gB0 = B + (size_t)(n0 + lr0) * K + lc0;
    const f16* gB1 = B + (size_t)(n0 + lr1) * K + lc0;
    int so0 = lr0 * PADG + lc0;
    int so1 = lr1 * PADG + lc0;

    float acc[4][4][4];
    #pragma unroll
    for (int i = 0; i < 4; i++)
        #pragma unroll
        for (int j = 0; j < 4; j++)
            #pragma unroll
            for (int q = 0; q < 4; q++) acc[i][j][q] = 0.0f;

    int a_row = wm * 64 + (lane & 15);
    int a_cb  = ((lane >> 4) & 1) * 16;
    int b_row = wn * 32 + ((lane >> 4) & 1) * 8 + (lane & 7);
    int b_cb  = ((lane >> 3) & 1) * 16;

    // prologue: chunk 0
    uint4 ra0 = *reinterpret_cast<const uint4*>(gA0);
    uint4 ra1 = *reinterpret_cast<const uint4*>(gA1);
    uint4 rb0 = *reinterpret_cast<const uint4*>(gB0);
    uint4 rb1 = *reinterpret_cast<const uint4*>(gB1);
    *reinterpret_cast<uint4*>(&sA[0][so0]) = ra0;
    *reinterpret_cast<uint4*>(&sA[0][so1]) = ra1;
    *reinterpret_cast<uint4*>(&sB[0][so0]) = rb0;
    *reinterpret_cast<uint4*>(&sB[0][so1]) = rb1;
    __syncthreads();

    int nch = K / KCG;
    #pragma unroll 1
    for (int c = 0; c < nch; c++) {
        int cur = c & 1;
        if (c + 1 < nch) {
            ra0 = *reinterpret_cast<const uint4*>(gA0 + (c + 1) * KCG);
            ra1 = *reinterpret_cast<const uint4*>(gA1 + (c + 1) * KCG);
            rb0 = *reinterpret_cast<const uint4*>(gB0 + (c + 1) * KCG);
            rb1 = *reinterpret_cast<const uint4*>(gB1 + (c + 1) * KCG);
        }

        uint32_t baseA = smem_u32(&sA[cur][0]);
        uint32_t baseB = smem_u32(&sB[cur][0]);

        #pragma unroll
        for (int kk = 0; kk < 2; kk++) {
            unsigned fA[4][4], fB[4][2];
            #pragma unroll
            for (int np = 0; np < 2; np++) {
                unsigned r4[4];
                uint32_t ab = baseB + (uint32_t)(b_row + np * 16) * (PADG * 2)
                              + kk * 32 + b_cb;
                ldm_x4(r4, ab);
                fB[np * 2 + 0][0] = r4[0]; fB[np * 2 + 0][1] = r4[1];
                fB[np * 2 + 1][0] = r4[2]; fB[np * 2 + 1][1] = r4[3];
            }
            #pragma unroll
            for (int mt = 0; mt < 4; mt++)
                ldm_x4(fA[mt], baseA + (uint32_t)(a_row + mt * 16) * (PADG * 2)
                                + kk * 32 + a_cb);
            #pragma unroll
            for (int mt = 0; mt < 4; mt++)
                #pragma unroll
                for (int nt = 0; nt < 4; nt++)
                    mma_f16(acc[mt][nt], fA[mt], fB[nt]);
        }

        if (c + 1 < nch) {
            int nxt = cur ^ 1;
            *reinterpret_cast<uint4*>(&sA[nxt][so0]) = ra0;
            *reinterpret_cast<uint4*>(&sA[nxt][so1]) = ra1;
            *reinterpret_cast<uint4*>(&sB[nxt][so0]) = rb0;
            *reinterpret_cast<uint4*>(&sB[nxt][so1]) = rb1;
        }
        __syncthreads();
    }

    // epilogue
    #pragma unroll
    for (int mt = 0; mt < 4; mt++) {
        int row = m0 + wm * 64 + mt * 16 + (lane >> 2);
        #pragma unroll
        for (int nt = 0; nt < 4; nt++) {
            int col = n0 + wn * 32 + nt * 8 + (lane & 3) * 2;
            if (MODE == 2) {
                // fused qkv routing: [0,C)=q (xQSCALE), [C,2C)=k, [2C,3C)=v
                float sc = (col < CC) ? QSCALE : 1.0f;
                f16* dst;
                if (col < 2 * CC) dst = Cq + (size_t)row * (2 * CC) + col;
                else              dst = Cv + (size_t)row * CC + (col - 2 * CC);
                #pragma unroll
                for (int half = 0; half < 2; half++) {
                    float v0 = acc[mt][nt][half * 2 + 0] * sc;
                    float v1 = acc[mt][nt][half * 2 + 1] * sc;
                    *reinterpret_cast<unsigned*>(
                        dst + (size_t)(half * 8) * ((col < 2 * CC) ? 2 * CC : CC)) =
                        pack_f162(v0, v1);
                }
            } else {
                float bx = bias[col], by = bias[col + 1];
                float2 r0 = make_float2(acc[mt][nt][0] + bx, acc[mt][nt][1] + by);
                float2 r1 = make_float2(acc[mt][nt][2] + bx, acc[mt][nt][3] + by);
                *reinterpret_cast<float2*>(C + (size_t)row * N + col) = r0;
                *reinterpret_cast<float2*>(C + (size_t)(row + 8) * N + col) = r1;
            }
        }
    }
}

// ---------------------------------------------------------------------------
// Flash attention on tensor cores — fp16 operands, fp32 accumulate.
// log2-domain softmax: S in log2 units (q pre-scaled by 0.125*log2e);
// p = ex2.approx.f16x2(S - m) packed directly as PV A-frags.
// l computed by the tensor core: V smem col 64 = 1.0 (cols 65-71 = 0), one
// extra nt=8 MMA per mt/kk accumulates sum(p) in fp32 C-frags (tq=0 lanes).
// BQ=128, 4 warps (2 m-tiles/warp sharing K/V frags). cp.async double buffer.
// ---------------------------------------------------------------------------
#define APAD 72
#define KVB (2 * 64 * APAD)        // elems per K/V buffer (K | V)
#define ASMEM (2 * KVB * 2 + 16)   // bytes (+16: boundary ldmatrix guard)

__global__ void __launch_bounds__(128)
attn_mma(const f16* __restrict__ qkh, const f16* __restrict__ vp,
         float* __restrict__ out) {
    extern __shared__ f16 sm[];
    const uint32_t sb = smem_u32(sm);

    int qt = blockIdx.x, h = blockIdx.y, b = blockIdx.z;
    int tid = threadIdx.x, warp = tid >> 5, lane = tid & 31;
    int quad = lane >> 2;

    // --- stage Q (fp16, 128 rows) in smem; build persistent frags ---
    for (int i = tid; i < 128 * 8; i += 128) {
        int r = i >> 3, c8 = (i & 7) * 8;
        size_t grow = (size_t)(b * NN + qt * 128 + r) * (2 * CC) + h * HD + c8;
        *reinterpret_cast<uint4*>(&sm[r * APAD + c8]) =
            *reinterpret_cast<const uint4*>(qkh + grow);
    }
    __syncthreads();
    unsigned fQ[2][4][4];
    {
        int cb = ((lane >> 4) & 1) * 16;
        #pragma unroll
        for (int mt = 0; mt < 2; mt++) {
            int ar = warp * 32 + mt * 16 + (lane & 15);
            #pragma unroll
            for (int kk = 0; kk < 4; kk++)
                ldm_x4(fQ[mt][kk], sb + (uint32_t)(ar * APAD) * 2 + kk * 32 + cb);
        }
    }
    __syncthreads();

    // --- ones-column init: V rows col64=1.0, cols65-71=0, both buffers ---
    {
        int buf = tid >> 6, r = tid & 63;
        uint32_t addr = sb + (uint32_t)buf * (KVB * 2)
                        + (uint32_t)(64 * APAD + r * APAD + 64) * 2;
        asm volatile("st.shared.v4.b32 [%0], {%1,%2,%3,%4};"
            :: "r"(addr), "r"(0x00003C00u), "r"(0u), "r"(0u), "r"(0u) : "memory");
    }

    float O[2][8][4];
    #pragma unroll
    for (int mt = 0; mt < 2; mt++)
        #pragma unroll
        for (int nt = 0; nt < 8; nt++)
            #pragma unroll
            for (int q = 0; q < 4; q++) O[mt][nt][q] = 0.0f;
    float lacc[2][4];
    #pragma unroll
    for (int mt = 0; mt < 2; mt++)
        #pragma unroll
        for (int q = 0; q < 4; q++) lacc[mt][q] = 0.0f;
    float mS[2][2];
    #pragma unroll
    for (int mt = 0; mt < 2; mt++) { mS[mt][0] = -1e30f; mS[mt][1] = -1e30f; }

    int krow = tid >> 3, kcol = (tid & 7) * 8;

    int kb_row = ((lane >> 4) & 1) * 8 + (lane & 7);
    int kb_cb  = ((lane >> 3) & 1) * 16;
    int vb_row = ((lane >> 3) & 1) * 8 + (lane & 7);
    int vb_cb  = ((lane >> 4) & 1) * 16;

    auto kv_issue = [&](int it, int buf) {
        uint32_t base = sb + (uint32_t)buf * (KVB * 2);
        #pragma unroll
        for (int rr = 0; rr < 64; rr += 16) {
            int r = krow + rr;
            size_t gk = (size_t)(b * NN + it * 64 + r) * (2 * CC) + CC + h * HD + kcol;
            size_t gv = (size_t)(b * NN + it * 64 + r) * CC + h * HD + kcol;
            cp16(base + (uint32_t)(0 * 64 * APAD + r * APAD + kcol) * 2, qkh + gk);
            cp16(base + (uint32_t)(1 * 64 * APAD + r * APAD + kcol) * 2, vp + gv);
        }
        CP_COMMIT();
    };

    kv_issue(0, 0);

    const int NIT = NN / 64;
    #pragma unroll 1
    for (int it = 0; it < NIT; it++) {
        int cur = it & 1;
        if (it + 1 < NIT) {
            kv_issue(it + 1, cur ^ 1);
            CP_WAIT1();
        } else {
            CP_WAIT0();
        }
        __syncthreads();

        uint32_t base = sb + (uint32_t)cur * (KVB * 2);
        uint32_t sKh = base;
        uint32_t sVh = base + 1 * 64 * APAD * 2;

        // ---- S = Q @ K^T (1 pass, fp16; K frags shared across 2 m-tiles) ----
        float S[2][8][4];
        #pragma unroll
        for (int mt = 0; mt < 2; mt++)
            #pragma unroll
            for (int nt = 0; nt < 8; nt++)
                #pragma unroll
                for (int q = 0; q < 4; q++) S[mt][nt][q] = 0.0f;

        #pragma unroll
        for (int kk = 0; kk < 4; kk++) {
            unsigned fKh[8][2];
            #pragma unroll
            for (int np = 0; np < 4; np++) {
                unsigned r4[4];
                uint32_t off = (uint32_t)(kb_row + np * 16) * (APAD * 2) + kb_cb + kk * 32;
                ldm_x4(r4, sKh + off);
                fKh[np * 2 + 0][0] = r4[0]; fKh[np * 2 + 0][1] = r4[1];
                fKh[np * 2 + 1][0] = r4[2]; fKh[np * 2 + 1][1] = r4[3];
            }
            #pragma unroll
            for (int mt = 0; mt < 2; mt++)
                #pragma unroll
                for (int nt = 0; nt < 8; nt++)
                    mma_f16(S[mt][nt], fQ[mt][kk], fKh[nt]);
        }

        // ---- log2-domain softmax + fp16x2 exp + pack P ----
        unsigned Phi[2][8][2];
        #pragma unroll
        for (int mt = 0; mt < 2; mt++) {
            float mx0 = -1e30f, mx1 = -1e30f;
            #pragma unroll
            for (int nt = 0; nt < 8; nt++) {
                mx0 = fmaxf(mx0, fmaxf(S[mt][nt][0], S[mt][nt][1]));
                mx1 = fmaxf(mx1, fmaxf(S[mt][nt][2], S[mt][nt][3]));
            }
            mx0 = fmaxf(mx0, __shfl_xor_sync(0xFFFFFFFFu, mx0, 1));
            mx0 = fmaxf(mx0, __shfl_xor_sync(0xFFFFFFFFu, mx0, 2));
            mx1 = fmaxf(mx1, __shfl_xor_sync(0xFFFFFFFFu, mx1, 1));
            mx1 = fmaxf(mx1, __shfl_xor_sync(0xFFFFFFFFu, mx1, 2));
            float mn0 = fmaxf(mS[mt][0], mx0), mn1 = fmaxf(mS[mt][1], mx1);
            float al0 = exp2f(mS[mt][0] - mn0), al1 = exp2f(mS[mt][1] - mn1);
            mS[mt][0] = mn0; mS[mt][1] = mn1;

            unsigned m00 = pack_f162(mn0, mn0);
            unsigned m11 = pack_f162(mn1, mn1);

            // rescale O and l
            #pragma unroll
            for (int nt = 0; nt < 8; nt++) {
                O[mt][nt][0] *= al0; O[mt][nt][1] *= al0;
                O[mt][nt][2] *= al1; O[mt][nt][3] *= al1;
            }
            lacc[mt][0] *= al0; lacc[mt][1] *= al0;
            lacc[mt][2] *= al1; lacc[mt][3] *= al1;

            // p = 2^(S - m), computed pairwise in fp16x2
            #pragma unroll
            for (int nt = 0; nt < 8; nt++) {
                unsigned s01 = pack_f162(S[mt][nt][0], S[mt][nt][1]);
                unsigned s23 = pack_f162(S[mt][nt][2], S[mt][nt][3]);
                Phi[mt][nt][0] = ex2_f16x2(hsub2(s01, m00));
                Phi[mt][nt][1] = ex2_f16x2(hsub2(s23, m11));
            }
        }

        // ---- O += P @ V; l += P @ ones (fp16 MMA; V frags shared) ----
        #pragma unroll
        for (int kk = 0; kk < 4; kk++) {
            unsigned fVh[8][2], fL[2];
            #pragma unroll
            for (int nt2 = 0; nt2 < 4; nt2++) {
                unsigned r4[4];
                uint32_t off = (uint32_t)(vb_row + kk * 16) * (APAD * 2) + vb_cb + nt2 * 32;
                ldm_x4t(r4, sVh + off);
                fVh[nt2 * 2 + 0][0] = r4[0]; fVh[nt2 * 2 + 0][1] = r4[1];
                fVh[nt2 * 2 + 1][0] = r4[2]; fVh[nt2 * 2 + 1][1] = r4[3];
            }
            {
                unsigned r4[4];
                uint32_t off = (uint32_t)(vb_row + kk * 16) * (APAD * 2) + vb_cb + 4 * 32;
                ldm_x4t(r4, sVh + off);
                fL[0] = r4[0]; fL[1] = r4[1];   // cols 64-71 (ones | zeros)
            }
            #pragma unroll
            for (int mt = 0; mt < 2; mt++) {
                unsigned aPh[4] = {Phi[mt][2 * kk][0], Phi[mt][2 * kk][1],
                                   Phi[mt][2 * kk + 1][0], Phi[mt][2 * kk + 1][1]};
                #pragma unroll
                for (int nt = 0; nt < 8; nt++)
                    mma_f16(O[mt][nt], aPh, fVh[nt]);
                mma_f16(lacc[mt], aPh, fL);
            }
        }
        __syncthreads();
    }

    // ---- finalize & store (l lives in tq=0 lanes' c0/c2) ----
    #pragma unroll
    for (int mt = 0; mt < 2; mt++) {
        float l0 = __shfl_sync(0xFFFFFFFFu, lacc[mt][0], lane & 28);
        float l1 = __shfl_sync(0xFFFFFFFFu, lacc[mt][2], lane & 28);
        float inv0 = 1.0f / l0, inv1 = 1.0f / l1;
        int row0 = b * NN + qt * 128 + warp * 32 + mt * 16 + quad;
        #pragma unroll
        for (int nt = 0; nt < 8; nt++) {
            int col = h * HD + nt * 8 + (lane & 3) * 2;
            *reinterpret_cast<float2*>(out + (size_t)row0 * CC + col) =
                make_float2(O[mt][nt][0] * inv0, O[mt][nt][1] * inv0);
            *reinterpret_cast<float2*>(out + (size_t)(row0 + 8) * CC + col) =
                make_float2(O[mt][nt][2] * inv1, O[mt][nt][3] * inv1);
        }
    }
}

// ---------------------------------------------------------------------------
extern "C" void kernel_launch(void* const* d_in, const int* in_sizes, int n_in,
                              void* d_out, int out_size) {
    const float* x      = (const float*)d_in[0];
    const float* ln1_g  = (const float*)d_in[1];
    const float* ln1_b  = (const float*)d_in[2];
    const float* w_qk   = (const float*)d_in[3];
    const float* w_v    = (const float*)d_in[4];
    const float* ln2_g  = (const float*)d_in[5];
    const float* ln2_b  = (const float*)d_in[6];
    const float* w_proj = (const float*)d_in[7];
    const float* b_proj = (const float*)d_in[8];
    float* out = (float*)d_out;

    float* ao;
    f16 *xf, *qkh, *vp, *wT, *wpT;
    cudaGetSymbolAddress((void**)&ao,   g_ao);
    cudaGetSymbolAddress((void**)&xf,   g_xf);
    cudaGetSymbolAddress((void**)&qkh,  g_qkh);
    cudaGetSymbolAddress((void**)&vp,   g_v);
    cudaGetSymbolAddress((void**)&wT,   g_wT);
    cudaGetSymbolAddress((void**)&wpT,  g_wpT);

    cudaFuncSetAttribute(attn_mma, cudaFuncAttributeMaxDynamicSharedMemorySize, ASMEM);

    // weight transpose -> fp16 (fused buffer: qk rows [0,2C), v rows [2C,3C))
    wsplit_f16<<<dim3(2 * CC / 32, CC / 32), dim3(32, 8)>>>(w_qk, wT, CC, 2 * CC);
    wsplit_f16<<<dim3(CC / 32, CC / 32), dim3(32, 8)>>>(
        w_v, wT + (size_t)2 * CC * CC, CC, CC);
    wsplit_f16<<<dim3(CC / 32, CC / 32), dim3(32, 8)>>>(w_proj, wpT, CC, CC);

    // 1. LN1 -> fp16 (warp-per-row)
    ln_f16_kernel<<<MM / 4, 128>>>(x, ln1_g, ln1_b, xf);

    // 2. fused qkv projection (1-pass fp16; q pre-scaled by 0.125*log2e)
    gemm_f16<2><<<dim3(3 * CC / 128, MM / 128), 256>>>(
        xf, wT, nullptr, nullptr, qkh, vp, MM, 3 * CC, CC);

    // 3. tensor-core flash attention (log2-softmax, f16x2 exp, MMA-computed l)
    attn_mma<<<dim3(NN / 128, HH, BB), 128, ASMEM>>>(qkh, vp, ao);

    // 4. LN2 -> fp16
    ln_f16_kernel<<<MM / 4, 128>>>(ao, ln2_g, ln2_b, xf);

    // 5. output projection + bias (1-pass fp16, fp32 out)
    gemm_f16<0><<<dim3(CC / 128, MM / 128), 256>>>(
        xf, wpT, b_proj, out, nullptr, nullptr, MM, CC, CC);
}

// round 15
// speedup vs baseline: 2.9617x; 1.0685x over previous
#include <cuda_runtime.h>
#include <cuda_bf16.h>
#include <cuda_fp16.h>
#include <cstdint>

// Problem constants (fixed shapes)
#define BB 2
#define NN 2048
#define CC 1024
#define HH 16
#define HD 64
#define MM (BB * NN)   // 4096 rows

// q pre-scale: 0.125 (hd^-0.5) * log2(e)  -> S comes out in log2 units
#define QSCALE 0.1803368801111137f

typedef __half f16;

// ---------------------------------------------------------------------------
// Scratch (device globals — no allocations allowed)
// ---------------------------------------------------------------------------
__device__ float g_ao[MM * CC];
__device__ f16 g_xf[MM * CC];                  // LN output, fp16
__device__ f16 g_qkh[MM * 2 * CC];             // q|k fp16 (q pre-scaled QSCALE)
__device__ f16 g_v[MM * CC];                   // v fp16
__device__ f16 g_wT[3 * CC * CC];              // fused w^T fp16: qk rows [0,2C), v rows [2C,3C)
__device__ f16 g_wpT[CC * CC];                 // w_proj^T fp16

// ---------------------------------------------------------------------------
// helpers
// ---------------------------------------------------------------------------
__device__ __forceinline__ uint32_t smem_u32(const void* p) {
    uint32_t a;
    asm("{ .reg .u64 t; cvta.to.shared.u64 t, %1; cvt.u32.u64 %0, t; }"
        : "=r"(a) : "l"(p));
    return a;
}

__device__ __forceinline__ void mma_f16(float* c, const unsigned* a, const unsigned* b) {
    asm volatile(
        "mma.sync.aligned.m16n8k16.row.col.f32.f16.f16.f32 "
        "{%0,%1,%2,%3}, {%4,%5,%6,%7}, {%8,%9}, {%0,%1,%2,%3};"
        : "+f"(c[0]), "+f"(c[1]), "+f"(c[2]), "+f"(c[3])
        : "r"(a[0]), "r"(a[1]), "r"(a[2]), "r"(a[3]), "r"(b[0]), "r"(b[1]));
}

__device__ __forceinline__ void ldm_x4(unsigned* r, uint32_t addr) {
    asm volatile("ldmatrix.sync.aligned.m8n8.x4.shared.b16 {%0,%1,%2,%3}, [%4];"
        : "=r"(r[0]), "=r"(r[1]), "=r"(r[2]), "=r"(r[3]) : "r"(addr));
}
__device__ __forceinline__ void ldm_x4t(unsigned* r, uint32_t addr) {
    asm volatile("ldmatrix.sync.aligned.m8n8.x4.trans.shared.b16 {%0,%1,%2,%3}, [%4];"
        : "=r"(r[0]), "=r"(r[1]), "=r"(r[2]), "=r"(r[3]) : "r"(addr));
}

// cp.async 16B global -> shared
__device__ __forceinline__ void cp16(uint32_t dst, const void* src) {
    asm volatile("cp.async.cg.shared.global [%0], [%1], 16;"
        :: "r"(dst), "l"(__cvta_generic_to_global(src)) : "memory");
}
#define CP_COMMIT() asm volatile("cp.async.commit_group;" ::: "memory")
#define CP_WAIT1()  asm volatile("cp.async.wait_group 1;" ::: "memory")
#define CP_WAIT0()  asm volatile("cp.async.wait_group 0;" ::: "memory")

// pack two f32 -> f16x2 register (lo = first arg)
__device__ __forceinline__ unsigned pack_f162(float lo, float hi) {
    unsigned r;
    asm("cvt.rn.f16x2.f32 %0, %1, %2;" : "=r"(r) : "f"(hi), "f"(lo));
    return r;
}
__device__ __forceinline__ unsigned hsub2(unsigned a, unsigned b) {
    unsigned r;
    asm("sub.f16x2 %0, %1, %2;" : "=r"(r) : "r"(a), "r"(b));
    return r;
}
__device__ __forceinline__ unsigned ex2_f16x2(unsigned a) {
    unsigned r;
    asm("ex2.approx.f16x2 %0, %1;" : "=r"(r) : "r"(a));
    return r;
}

// ---------------------------------------------------------------------------
// LayerNorm -> fp16: warp-per-row, pure shuffle reduce
// ---------------------------------------------------------------------------
__global__ void ln_f16_kernel(const float* __restrict__ x,
                              const float* __restrict__ g,
                              const float* __restrict__ b,
                              f16* __restrict__ o) {
    int warp = threadIdx.x >> 5, lane = threadIdx.x & 31;
    int row = blockIdx.x * 4 + warp;
    const float4* xr = reinterpret_cast<const float4*>(x + (size_t)row * CC);

    float4 v[8];
    float s = 0.0f, ss = 0.0f;
    #pragma unroll
    for (int j = 0; j < 8; j++) {
        v[j] = xr[lane + j * 32];
        s  += v[j].x + v[j].y + v[j].z + v[j].w;
        ss += v[j].x * v[j].x + v[j].y * v[j].y + v[j].z * v[j].z + v[j].w * v[j].w;
    }
    #pragma unroll
    for (int of = 16; of > 0; of >>= 1) {
        s  += __shfl_xor_sync(0xFFFFFFFFu, s,  of);
        ss += __shfl_xor_sync(0xFFFFFFFFu, ss, of);
    }

    float mu  = s * (1.0f / CC);
    float var = ss * (1.0f / CC) - mu * mu;
    float inv = rsqrtf(var + 1e-5f);

    const float4* gr = reinterpret_cast<const float4*>(g);
    const float4* br = reinterpret_cast<const float4*>(b);
    uint2* op = reinterpret_cast<uint2*>(o + (size_t)row * CC);
    #pragma unroll
    for (int j = 0; j < 8; j++) {
        float4 gv = gr[lane + j * 32];
        float4 bv = br[lane + j * 32];
        float o0 = (v[j].x - mu) * inv * gv.x + bv.x;
        float o1 = (v[j].y - mu) * inv * gv.y + bv.y;
        float o2 = (v[j].z - mu) * inv * gv.z + bv.z;
        float o3 = (v[j].w - mu) * inv * gv.w + bv.w;
        op[lane + j * 32] = make_uint2(pack_f162(o0, o1), pack_f162(o2, o3));
    }
}

// ---------------------------------------------------------------------------
// Transpose: w[K][N] fp32 -> wT[N][K] fp16
// ---------------------------------------------------------------------------
__global__ void wsplit_f16(const float* __restrict__ w,
                           f16* __restrict__ tOut,
                           int K, int N) {
    __shared__ float t[32][33];
    int bx = blockIdx.x, by = blockIdx.y;
    int x = bx * 32 + threadIdx.x;
    #pragma unroll
    for (int j = 0; j < 32; j += 8)
        t[threadIdx.y + j][threadIdx.x] = w[(size_t)(by * 32 + threadIdx.y + j) * N + x];
    __syncthreads();
    int n = bx * 32 + threadIdx.y;
    int k = by * 32 + threadIdx.x;
    #pragma unroll
    for (int j = 0; j < 32; j += 8)
        tOut[(size_t)(n + j) * K + k] = __float2half(t[threadIdx.x][threadIdx.y + j]);
}

// ---------------------------------------------------------------------------
// 1-pass fp16 GEMM (fp32 accumulate): C[M,N] = A[M,K] @ B[N,K]^T.
// MODE 0: fp32 out (+bias). MODE 2: fused qkv epilogue — cols [0,2C) -> Cq
// (xQSCALE for cols < C), cols [2C,3C) -> Cv at col-2C.
// CTA 128x128 tile, 8 warps (2x4), warp 64x32. K chunk 64 (4 k16 blocks,
// 64 MMAs/warp between syncs), cp.async double buffer, dynamic smem 73.7KB,
// PAD 72 (144B rows: 8-row ldmatrix phases hit 8 distinct banks).
// Same ascending k16 accumulation order as before -> bit-identical results.
// ---------------------------------------------------------------------------
#define KCG 64
#define PADG 72
#define SBUF (128 * PADG)          // f16 elems per tensor-buffer
#define GSMEM (4 * SBUF * 2)       // bytes (73728)

template <int MODE>
__global__ void __launch_bounds__(256, 2)
gemm_f16(const f16* __restrict__ A, const f16* __restrict__ B,
         const float* __restrict__ bias, float* __restrict__ C,
         f16* __restrict__ Cq, f16* __restrict__ Cv,
         int M, int N, int K) {
    extern __shared__ f16 gsm[];
    const uint32_t sbase = smem_u32(gsm);

    int tid = threadIdx.x;
    int warp = tid >> 5, lane = tid & 31;
    int wm = warp >> 2, wn = warp & 3;
    int m0 = blockIdx.y * 128, n0 = blockIdx.x * 128;

    // cp.async mapping: 4 rows per thread per tensor (row = (tid>>3)+p*32)
    int lr = tid >> 3, lc = (tid & 7) * 8;

    float acc[4][4][4];
    #pragma unroll
    for (int i = 0; i < 4; i++)
        #pragma unroll
        for (int j = 0; j < 4; j++)
            #pragma unroll
            for (int q = 0; q < 4; q++) acc[i][j][q] = 0.0f;

    int a_row = wm * 64 + (lane & 15);
    int a_cb  = ((lane >> 4) & 1) * 16;
    int b_row = wn * 32 + ((lane >> 4) & 1) * 8 + (lane & 7);
    int b_cb  = ((lane >> 3) & 1) * 16;

    auto issue = [&](int c, int buf) {
        uint32_t bA = sbase + (uint32_t)buf * (SBUF * 2);
        uint32_t bB = sbase + (uint32_t)(2 + buf) * (SBUF * 2);
        #pragma unroll
        for (int p = 0; p < 4; p++) {
            int r = lr + p * 32;
            uint32_t so = (uint32_t)(r * PADG + lc) * 2;
            cp16(bA + so, A + (size_t)(m0 + r) * K + c * KCG + lc);
            cp16(bB + so, B + (size_t)(n0 + r) * K + c * KCG + lc);
        }
        CP_COMMIT();
    };

    issue(0, 0);

    int nch = K / KCG;
    #pragma unroll 1
    for (int c = 0; c < nch; c++) {
        int cur = c & 1;
        if (c + 1 < nch) {
            issue(c + 1, cur ^ 1);
            CP_WAIT1();
        } else {
            CP_WAIT0();
        }
        __syncthreads();

        uint32_t baseA = sbase + (uint32_t)cur * (SBUF * 2);
        uint32_t baseB = sbase + (uint32_t)(2 + cur) * (SBUF * 2);

        #pragma unroll
        for (int kk = 0; kk < 4; kk++) {
            unsigned fA[4][4], fB[4][2];
            #pragma unroll
            for (int np = 0; np < 2; np++) {
                unsigned r4[4];
                uint32_t ab = baseB + (uint32_t)(b_row + np * 16) * (PADG * 2)
                              + kk * 32 + b_cb;
                ldm_x4(r4, ab);
                fB[np * 2 + 0][0] = r4[0]; fB[np * 2 + 0][1] = r4[1];
                fB[np * 2 + 1][0] = r4[2]; fB[np * 2 + 1][1] = r4[3];
            }
            #pragma unroll
            for (int mt = 0; mt < 4; mt++)
                ldm_x4(fA[mt], baseA + (uint32_t)(a_row + mt * 16) * (PADG * 2)
                                + kk * 32 + a_cb);
            #pragma unroll
            for (int mt = 0; mt < 4; mt++)
                #pragma unroll
                for (int nt = 0; nt < 4; nt++)
                    mma_f16(acc[mt][nt], fA[mt], fB[nt]);
        }
        __syncthreads();
    }

    // epilogue
    #pragma unroll
    for (int mt = 0; mt < 4; mt++) {
        int row = m0 + wm * 64 + mt * 16 + (lane >> 2);
        #pragma unroll
        for (int nt = 0; nt < 4; nt++) {
            int col = n0 + wn * 32 + nt * 8 + (lane & 3) * 2;
            if (MODE == 2) {
                // fused qkv routing: [0,C)=q (xQSCALE), [C,2C)=k, [2C,3C)=v
                float sc = (col < CC) ? QSCALE : 1.0f;
                f16* dst;
                if (col < 2 * CC) dst = Cq + (size_t)row * (2 * CC) + col;
                else              dst = Cv + (size_t)row * CC + (col - 2 * CC);
                #pragma unroll
                for (int half = 0; half < 2; half++) {
                    float v0 = acc[mt][nt][half * 2 + 0] * sc;
                    float v1 = acc[mt][nt][half * 2 + 1] * sc;
                    *reinterpret_cast<unsigned*>(
                        dst + (size_t)(half * 8) * ((col < 2 * CC) ? 2 * CC : CC)) =
                        pack_f162(v0, v1);
                }
            } else {
                float bx = bias[col], by = bias[col + 1];
                float2 r0 = make_float2(acc[mt][nt][0] + bx, acc[mt][nt][1] + by);
                float2 r1 = make_float2(acc[mt][nt][2] + bx, acc[mt][nt][3] + by);
                *reinterpret_cast<float2*>(C + (size_t)row * N + col) = r0;
                *reinterpret_cast<float2*>(C + (size_t)(row + 8) * N + col) = r1;
            }
        }
    }
}

// ---------------------------------------------------------------------------
// Flash attention on tensor cores — fp16 operands, fp32 accumulate.
// log2-domain softmax (q pre-scaled 0.125*log2e), p = ex2.approx.f16x2,
// l via ones-column MMA. BQ=128, 4 warps. cp.async double buffer.
// (unchanged from R14 — at its mma.sync MMA floor)
// ---------------------------------------------------------------------------
#define APAD 72
#define KVB (2 * 64 * APAD)        // elems per K/V buffer (K | V)
#define ASMEM (2 * KVB * 2 + 16)   // bytes (+16: boundary ldmatrix guard)

__global__ void __launch_bounds__(128)
attn_mma(const f16* __restrict__ qkh, const f16* __restrict__ vp,
         float* __restrict__ out) {
    extern __shared__ f16 sm[];
    const uint32_t sb = smem_u32(sm);

    int qt = blockIdx.x, h = blockIdx.y, b = blockIdx.z;
    int tid = threadIdx.x, warp = tid >> 5, lane = tid & 31;
    int quad = lane >> 2;

    // --- stage Q (fp16, 128 rows) in smem; build persistent frags ---
    for (int i = tid; i < 128 * 8; i += 128) {
        int r = i >> 3, c8 = (i & 7) * 8;
        size_t grow = (size_t)(b * NN + qt * 128 + r) * (2 * CC) + h * HD + c8;
        *reinterpret_cast<uint4*>(&sm[r * APAD + c8]) =
            *reinterpret_cast<const uint4*>(qkh + grow);
    }
    __syncthreads();
    unsigned fQ[2][4][4];
    {
        int cb = ((lane >> 4) & 1) * 16;
        #pragma unroll
        for (int mt = 0; mt < 2; mt++) {
            int ar = warp * 32 + mt * 16 + (lane & 15);
            #pragma unroll
            for (int kk = 0; kk < 4; kk++)
                ldm_x4(fQ[mt][kk], sb + (uint32_t)(ar * APAD) * 2 + kk * 32 + cb);
        }
    }
    __syncthreads();

    // --- ones-column init: V rows col64=1.0, cols65-71=0, both buffers ---
    {
        int buf = tid >> 6, r = tid & 63;
        uint32_t addr = sb + (uint32_t)buf * (KVB * 2)
                        + (uint32_t)(64 * APAD + r * APAD + 64) * 2;
        asm volatile("st.shared.v4.b32 [%0], {%1,%2,%3,%4};"
            :: "r"(addr), "r"(0x00003C00u), "r"(0u), "r"(0u), "r"(0u) : "memory");
    }

    float O[2][8][4];
    #pragma unroll
    for (int mt = 0; mt < 2; mt++)
        #pragma unroll
        for (int nt = 0; nt < 8; nt++)
            #pragma unroll
            for (int q = 0; q < 4; q++) O[mt][nt][q] = 0.0f;
    float lacc[2][4];
    #pragma unroll
    for (int mt = 0; mt < 2; mt++)
        #pragma unroll
        for (int q = 0; q < 4; q++) lacc[mt][q] = 0.0f;
    float mS[2][2];
    #pragma unroll
    for (int mt = 0; mt < 2; mt++) { mS[mt][0] = -1e30f; mS[mt][1] = -1e30f; }

    int krow = tid >> 3, kcol = (tid & 7) * 8;

    int kb_row = ((lane >> 4) & 1) * 8 + (lane & 7);
    int kb_cb  = ((lane >> 3) & 1) * 16;
    int vb_row = ((lane >> 3) & 1) * 8 + (lane & 7);
    int vb_cb  = ((lane >> 4) & 1) * 16;

    auto kv_issue = [&](int it, int buf) {
        uint32_t base = sb + (uint32_t)buf * (KVB * 2);
        #pragma unroll
        for (int rr = 0; rr < 64; rr += 16) {
            int r = krow + rr;
            size_t gk = (size_t)(b * NN + it * 64 + r) * (2 * CC) + CC + h * HD + kcol;
            size_t gv = (size_t)(b * NN + it * 64 + r) * CC + h * HD + kcol;
            cp16(base + (uint32_t)(0 * 64 * APAD + r * APAD + kcol) * 2, qkh + gk);
            cp16(base + (uint32_t)(1 * 64 * APAD + r * APAD + kcol) * 2, vp + gv);
        }
        CP_COMMIT();
    };

    kv_issue(0, 0);

    const int NIT = NN / 64;
    #pragma unroll 1
    for (int it = 0; it < NIT; it++) {
        int cur = it & 1;
        if (it + 1 < NIT) {
            kv_issue(it + 1, cur ^ 1);
            CP_WAIT1();
        } else {
            CP_WAIT0();
        }
        __syncthreads();

        uint32_t base = sb + (uint32_t)cur * (KVB * 2);
        uint32_t sKh = base;
        uint32_t sVh = base + 1 * 64 * APAD * 2;

        // ---- S = Q @ K^T (1 pass, fp16; K frags shared across 2 m-tiles) ----
        float S[2][8][4];
        #pragma unroll
        for (int mt = 0; mt < 2; mt++)
            #pragma unroll
            for (int nt = 0; nt < 8; nt++)
                #pragma unroll
                for (int q = 0; q < 4; q++) S[mt][nt][q] = 0.0f;

        #pragma unroll
        for (int kk = 0; kk < 4; kk++) {
            unsigned fKh[8][2];
            #pragma unroll
            for (int np = 0; np < 4; np++) {
                unsigned r4[4];
                uint32_t off = (uint32_t)(kb_row + np * 16) * (APAD * 2) + kb_cb + kk * 32;
                ldm_x4(r4, sKh + off);
                fKh[np * 2 + 0][0] = r4[0]; fKh[np * 2 + 0][1] = r4[1];
                fKh[np * 2 + 1][0] = r4[2]; fKh[np * 2 + 1][1] = r4[3];
            }
            #pragma unroll
            for (int mt = 0; mt < 2; mt++)
                #pragma unroll
                for (int nt = 0; nt < 8; nt++)
                    mma_f16(S[mt][nt], fQ[mt][kk], fKh[nt]);
        }

        // ---- log2-domain softmax + fp16x2 exp + pack P ----
        unsigned Phi[2][8][2];
        #pragma unroll
        for (int mt = 0; mt < 2; mt++) {
            float mx0 = -1e30f, mx1 = -1e30f;
            #pragma unroll
            for (int nt = 0; nt < 8; nt++) {
                mx0 = fmaxf(mx0, fmaxf(S[mt][nt][0], S[mt][nt][1]));
                mx1 = fmaxf(mx1, fmaxf(S[mt][nt][2], S[mt][nt][3]));
            }
            mx0 = fmaxf(mx0, __shfl_xor_sync(0xFFFFFFFFu, mx0, 1));
            mx0 = fmaxf(mx0, __shfl_xor_sync(0xFFFFFFFFu, mx0, 2));
            mx1 = fmaxf(mx1, __shfl_xor_sync(0xFFFFFFFFu, mx1, 1));
            mx1 = fmaxf(mx1, __shfl_xor_sync(0xFFFFFFFFu, mx1, 2));
            float mn0 = fmaxf(mS[mt][0], mx0), mn1 = fmaxf(mS[mt][1], mx1);
            float al0 = exp2f(mS[mt][0] - mn0), al1 = exp2f(mS[mt][1] - mn1);
            mS[mt][0] = mn0; mS[mt][1] = mn1;

            unsigned m00 = pack_f162(mn0, mn0);
            unsigned m11 = pack_f162(mn1, mn1);

            #pragma unroll
            for (int nt = 0; nt < 8; nt++) {
                O[mt][nt][0] *= al0; O[mt][nt][1] *= al0;
                O[mt][nt][2] *= al1; O[mt][nt][3] *= al1;
            }
            lacc[mt][0] *= al0; lacc[mt][1] *= al0;
            lacc[mt][2] *= al1; lacc[mt][3] *= al1;

            #pragma unroll
            for (int nt = 0; nt < 8; nt++) {
                unsigned s01 = pack_f162(S[mt][nt][0], S[mt][nt][1]);
                unsigned s23 = pack_f162(S[mt][nt][2], S[mt][nt][3]);
                Phi[mt][nt][0] = ex2_f16x2(hsub2(s01, m00));
                Phi[mt][nt][1] = ex2_f16x2(hsub2(s23, m11));
            }
        }

        // ---- O += P @ V; l += P @ ones (fp16 MMA; V frags shared) ----
        #pragma unroll
        for (int kk = 0; kk < 4; kk++) {
            unsigned fVh[8][2], fL[2];
            #pragma unroll
            for (int nt2 = 0; nt2 < 4; nt2++) {
                unsigned r4[4];
                uint32_t off = (uint32_t)(vb_row + kk * 16) * (APAD * 2) + vb_cb + nt2 * 32;
                ldm_x4t(r4, sVh + off);
                fVh[nt2 * 2 + 0][0] = r4[0]; fVh[nt2 * 2 + 0][1] = r4[1];
                fVh[nt2 * 2 + 1][0] = r4[2]; fVh[nt2 * 2 + 1][1] = r4[3];
            }
            {
                unsigned r4[4];
                uint32_t off = (uint32_t)(vb_row + kk * 16) * (APAD * 2) + vb_cb + 4 * 32;
                ldm_x4t(r4, sVh + off);
                fL[0] = r4[0]; fL[1] = r4[1];   // cols 64-71 (ones | zeros)
            }
            #pragma unroll
            for (int mt = 0; mt < 2; mt++) {
                unsigned aPh[4] = {Phi[mt][2 * kk][0], Phi[mt][2 * kk][1],
                                   Phi[mt][2 * kk + 1][0], Phi[mt][2 * kk + 1][1]};
                #pragma unroll
                for (int nt = 0; nt < 8; nt++)
                    mma_f16(O[mt][nt], aPh, fVh[nt]);
                mma_f16(lacc[mt], aPh, fL);
            }
        }
        __syncthreads();
    }

    // ---- finalize & store (l lives in tq=0 lanes' c0/c2) ----
    #pragma unroll
    for (int mt = 0; mt < 2; mt++) {
        float l0 = __shfl_sync(0xFFFFFFFFu, lacc[mt][0], lane & 28);
        float l1 = __shfl_sync(0xFFFFFFFFu, lacc[mt][2], lane & 28);
        float inv0 = 1.0f / l0, inv1 = 1.0f / l1;
        int row0 = b * NN + qt * 128 + warp * 32 + mt * 16 + quad;
        #pragma unroll
        for (int nt = 0; nt < 8; nt++) {
            int col = h * HD + nt * 8 + (lane & 3) * 2;
            *reinterpret_cast<float2*>(out + (size_t)row0 * CC + col) =
                make_float2(O[mt][nt][0] * inv0, O[mt][nt][1] * inv0);
            *reinterpret_cast<float2*>(out + (size_t)(row0 + 8) * CC + col) =
                make_float2(O[mt][nt][2] * inv1, O[mt][nt][3] * inv1);
        }
    }
}

// ---------------------------------------------------------------------------
extern "C" void kernel_launch(void* const* d_in, const int* in_sizes, int n_in,
                              void* d_out, int out_size) {
    const float* x      = (const float*)d_in[0];
    const float* ln1_g  = (const float*)d_in[1];
    const float* ln1_b  = (const float*)d_in[2];
    const float* w_qk   = (const float*)d_in[3];
    const float* w_v    = (const float*)d_in[4];
    const float* ln2_g  = (const float*)d_in[5];
    const float* ln2_b  = (const float*)d_in[6];
    const float* w_proj = (const float*)d_in[7];
    const float* b_proj = (const float*)d_in[8];
    float* out = (float*)d_out;

    float* ao;
    f16 *xf, *qkh, *vp, *wT, *wpT;
    cudaGetSymbolAddress((void**)&ao,   g_ao);
    cudaGetSymbolAddress((void**)&xf,   g_xf);
    cudaGetSymbolAddress((void**)&qkh,  g_qkh);
    cudaGetSymbolAddress((void**)&vp,   g_v);
    cudaGetSymbolAddress((void**)&wT,   g_wT);
    cudaGetSymbolAddress((void**)&wpT,  g_wpT);

    cudaFuncSetAttribute(attn_mma, cudaFuncAttributeMaxDynamicSharedMemorySize, ASMEM);
    cudaFuncSetAttribute(gemm_f16<2>, cudaFuncAttributeMaxDynamicSharedMemorySize, GSMEM);
    cudaFuncSetAttribute(gemm_f16<0>, cudaFuncAttributeMaxDynamicSharedMemorySize, GSMEM);

    // weight transpose -> fp16 (fused buffer: qk rows [0,2C), v rows [2C,3C))
    wsplit_f16<<<dim3(2 * CC / 32, CC / 32), dim3(32, 8)>>>(w_qk, wT, CC, 2 * CC);
    wsplit_f16<<<dim3(CC / 32, CC / 32), dim3(32, 8)>>>(
        w_v, wT + (size_t)2 * CC * CC, CC, CC);
    wsplit_f16<<<dim3(CC / 32, CC / 32), dim3(32, 8)>>>(w_proj, wpT, CC, CC);

    // 1. LN1 -> fp16 (warp-per-row)
    ln_f16_kernel<<<MM / 4, 128>>>(x, ln1_g, ln1_b, xf);

    // 2. fused qkv projection (1-pass fp16; q pre-scaled by 0.125*log2e)
    gemm_f16<2><<<dim3(3 * CC / 128, MM / 128), 256, GSMEM>>>(
        xf, wT, nullptr, nullptr, qkh, vp, MM, 3 * CC, CC);

    // 3. tensor-core flash attention (log2-softmax, f16x2 exp, MMA-computed l)
    attn_mma<<<dim3(NN / 128, HH, BB), 128, ASMEM>>>(qkh, vp, ao);

    // 4. LN2 -> fp16
    ln_f16_kernel<<<MM / 4, 128>>>(ao, ln2_g, ln2_b, xf);

    // 5. output projection + bias (1-pass fp16, fp32 out)
    gemm_f16<0><<<dim3(CC / 128, MM / 128), 256, GSMEM>>>(
        xf, wpT, b_proj, out, nullptr, nullptr, MM, CC, CC);
}